// round 1
// baseline (speedup 1.0000x reference)
#include <cuda_runtime.h>
#include <math.h>

#define BB  2
#define SS  2048
#define DD  1024
#define HH  16
#define HDD 64
#define MM  (BB*SS)      // 4096 rows for the GEMMs
#define CL  64           // scan chunk length
#define NC  (SS/CL)      // 32 scan chunks
#define RL  64           // retention chunk length
#define RNC (SS/RL)      // 32 retention chunks

// ---------------- scratch (static device globals; no allocs allowed) -------
__device__ float g_u [BB*SS*DD];
__device__ float g_a [BB*SS*DD];
__device__ float g_h [BB*SS*DD];
__device__ float g_qp[BB*SS*DD];
__device__ float g_Ac[BB*NC*DD];
__device__ float g_Uc[BB*NC*DD];
__device__ float g_P [BB*NC*DD];
__device__ float g_M [BB*HH*RNC*HDD*HDD];   // per-chunk KV outer products
__device__ float g_Sp[BB*HH*RNC*HDD*HDD];   // per-chunk state prefixes

// ---------------- GEMM: C = X*W + b (optionally dual-B, sigmoid on 2nd) ----
// X: [M=4096, K=1024] row-major, W: [K=1024, N=1024] row-major.
// 64x64 block tile, 16 K-tile, 256 threads, 4x4 microtile per thread.
template<int DUAL>
__global__ __launch_bounds__(256)
void gemm_k(const float* __restrict__ X, const float* __restrict__ W1,
            const float* __restrict__ W2, const float* __restrict__ b1,
            const float* __restrict__ b2, float* __restrict__ O1,
            float* __restrict__ O2)
{
    const int N = DD, K = DD;
    __shared__ float As[16][64];                 // transposed: As[k][m]
    __shared__ float B1s[16][64];
    __shared__ float B2s[DUAL ? 16 : 1][64];

    int tid = threadIdx.x;
    int tx = tid & 15, ty = tid >> 4;
    int bm = blockIdx.y * 64, bn = blockIdx.x * 64;
    int arow = tid >> 2, acg = (tid & 3) << 2;   // A tile 64x16
    int brow = tid >> 4, bcg = (tid & 15) << 2;  // B tile 16x64

    float acc1[4][4], acc2[4][4];
#pragma unroll
    for (int r = 0; r < 4; r++)
#pragma unroll
        for (int c = 0; c < 4; c++) { acc1[r][c] = 0.f; acc2[r][c] = 0.f; }

    for (int k0 = 0; k0 < K; k0 += 16) {
        float4 av = *(const float4*)&X[(size_t)(bm + arow) * K + k0 + acg];
        As[acg + 0][arow] = av.x;
        As[acg + 1][arow] = av.y;
        As[acg + 2][arow] = av.z;
        As[acg + 3][arow] = av.w;
        *(float4*)&B1s[brow][bcg] = *(const float4*)&W1[(size_t)(k0 + brow) * N + bn + bcg];
        if (DUAL)
            *(float4*)&B2s[brow][bcg] = *(const float4*)&W2[(size_t)(k0 + brow) * N + bn + bcg];
        __syncthreads();
#pragma unroll
        for (int k = 0; k < 16; k++) {
            float4 af = *(const float4*)&As[k][ty << 2];
            float4 bf = *(const float4*)&B1s[k][tx << 2];
            float a[4]  = { af.x, af.y, af.z, af.w };
            float bbv[4] = { bf.x, bf.y, bf.z, bf.w };
#pragma unroll
            for (int r = 0; r < 4; r++)
#pragma unroll
                for (int c = 0; c < 4; c++) acc1[r][c] += a[r] * bbv[c];
            if (DUAL) {
                float4 bf2 = *(const float4*)&B2s[k][tx << 2];
                float b2v[4] = { bf2.x, bf2.y, bf2.z, bf2.w };
#pragma unroll
                for (int r = 0; r < 4; r++)
#pragma unroll
                    for (int c = 0; c < 4; c++) acc2[r][c] += a[r] * b2v[c];
            }
        }
        __syncthreads();
    }
#pragma unroll
    for (int r = 0; r < 4; r++) {
        int m = bm + (ty << 2) + r;
#pragma unroll
        for (int c = 0; c < 4; c++) {
            int n = bn + (tx << 2) + c;
            O1[(size_t)m * N + n] = acc1[r][c] + b1[n];
            if (DUAL) {
                float g = acc2[r][c] + b2[n];
                O2[(size_t)m * N + n] = 1.f / (1.f + expf(-g));
            }
        }
    }
}

// ---------------- gated scan: h_t = a_t*h_{t-1} + u_t (3-phase chunked) ----
__global__ void scan_chunk_k()
{
    int d = blockIdx.x * 256 + threadIdx.x;
    int c = blockIdx.y, b = blockIdx.z;
    size_t p = ((size_t)b * SS + (size_t)c * CL) * DD + d;
    float A = 1.f, U = 0.f;
#pragma unroll 8
    for (int j = 0; j < CL; j++) {
        float av = g_a[p], uv = g_u[p];
        U = av * U + uv;
        A *= av;
        p += DD;
    }
    size_t o = ((size_t)b * NC + c) * DD + d;
    g_Ac[o] = A;
    g_Uc[o] = U;
}

__global__ void scan_prefix_k()
{
    int d = blockIdx.x * 256 + threadIdx.x;
    int b = blockIdx.y;
    float hv = 0.f;
#pragma unroll
    for (int c = 0; c < NC; c++) {
        size_t o = ((size_t)b * NC + c) * DD + d;
        g_P[o] = hv;
        hv = g_Ac[o] * hv + g_Uc[o];
    }
}

__global__ void scan_apply_k()
{
    int d = blockIdx.x * 256 + threadIdx.x;
    int c = blockIdx.y, b = blockIdx.z;
    float hv = g_P[((size_t)b * NC + c) * DD + d];
    size_t p = ((size_t)b * SS + (size_t)c * CL) * DD + d;
#pragma unroll 8
    for (int j = 0; j < CL; j++) {
        hv = g_a[p] * hv + g_u[p];
        g_h[p] = hv;
        p += DD;
    }
}

// ---------------- retention phase 1: intra-chunk attention + chunk KV ------
// One block per (chunk c, head h, batch b). 64x64 tiles.
//   scores[i][j] = (q_i . k_j)/8 * gamma^(i-j)  for i>=j (local, same chunk)
//   out_intra    = scores @ V
//   M_c[d1][d2]  = sum_j gamma^(63-j) k_j[d1] v_j[d2]
__global__ __launch_bounds__(256)
void ret_p1(const float* __restrict__ kin, const float* __restrict__ vin,
            const float* __restrict__ gammas, float* __restrict__ out)
{
    extern __shared__ float sm[];
    float* Qs = sm;                  // [64][64], reused for P after scores
    float* Ks = sm + 4096;           // [64][65] padded
    float* Vs = Ks + 64 * 65;        // [64][64]
    float* gp = Vs + 4096;           // gamma^t, t=0..64

    int c = blockIdx.x, h = blockIdx.y, b = blockIdx.z;
    int tid = threadIdx.x, tx = tid & 15, ty = tid >> 4;
    if (tid < 65) gp[tid] = powf(gammas[h], (float)tid);

    size_t base = ((size_t)b * SS + (size_t)c * RL) * DD + (size_t)h * HDD;
#pragma unroll
    for (int rep = 0; rep < 4; rep++) {
        int e = rep * 1024 + tid * 4;
        int row = e >> 6, col = e & 63;
        size_t ga = base + (size_t)row * DD + col;
        float4 qv = *(const float4*)&g_qp[ga];
        *(float4*)&Qs[row * 64 + col] = qv;
        float4 kv = *(const float4*)&kin[ga];
        Ks[row * 65 + col + 0] = kv.x;
        Ks[row * 65 + col + 1] = kv.y;
        Ks[row * 65 + col + 2] = kv.z;
        Ks[row * 65 + col + 3] = kv.w;
        float4 vv = *(const float4*)&vin[ga];
        *(float4*)&Vs[row * 64 + col] = vv;
    }
    __syncthreads();

    int i0 = ty << 2, j0 = tx << 2;
    float sc[4][4];
#pragma unroll
    for (int r = 0; r < 4; r++)
#pragma unroll
        for (int cc = 0; cc < 4; cc++) sc[r][cc] = 0.f;

#pragma unroll 4
    for (int d = 0; d < 64; d++) {
        float qf[4], kf[4];
#pragma unroll
        for (int r = 0; r < 4; r++) qf[r] = Qs[(i0 + r) * 64 + d];
#pragma unroll
        for (int r = 0; r < 4; r++) kf[r] = Ks[(j0 + r) * 65 + d];
#pragma unroll
        for (int r = 0; r < 4; r++)
#pragma unroll
            for (int cc = 0; cc < 4; cc++) sc[r][cc] += qf[r] * kf[cc];
    }
    // decay mask
    float pr[4][4];
#pragma unroll
    for (int r = 0; r < 4; r++)
#pragma unroll
        for (int cc = 0; cc < 4; cc++) {
            int di = (i0 + r) - (j0 + cc);
            pr[r][cc] = (di >= 0) ? sc[r][cc] * gp[di] * 0.125f : 0.f;
        }
    __syncthreads();                 // all Qs reads done
#pragma unroll
    for (int r = 0; r < 4; r++)
#pragma unroll
        for (int cc = 0; cc < 4; cc++)
            Qs[(i0 + r) * 64 + j0 + cc] = pr[r][cc];   // P tile into Qs
    __syncthreads();

    float ov[4][4], mv[4][4];
#pragma unroll
    for (int r = 0; r < 4; r++)
#pragma unroll
        for (int cc = 0; cc < 4; cc++) { ov[r][cc] = 0.f; mv[r][cc] = 0.f; }

#pragma unroll 4
    for (int j = 0; j < 64; j++) {
        float w = gp[63 - j];
        float pf[4], kf[4], vf[4];
#pragma unroll
        for (int r = 0; r < 4; r++) pf[r] = Qs[(i0 + r) * 64 + j];
#pragma unroll
        for (int r = 0; r < 4; r++) kf[r] = Ks[j * 65 + i0 + r] * w;
#pragma unroll
        for (int cc = 0; cc < 4; cc++) vf[cc] = Vs[j * 64 + j0 + cc];
#pragma unroll
        for (int r = 0; r < 4; r++)
#pragma unroll
            for (int cc = 0; cc < 4; cc++) {
                ov[r][cc] += pf[r] * vf[cc];
                mv[r][cc] += kf[r] * vf[cc];
            }
    }
    // write intra output (full overwrite) and M
    size_t mb = (((size_t)(b * HH + h)) * RNC + c) * 4096;
#pragma unroll
    for (int r = 0; r < 4; r++)
#pragma unroll
        for (int cc = 0; cc < 4; cc++) {
            out[base + (size_t)(i0 + r) * DD + j0 + cc] = ov[r][cc];
            g_M[mb + (size_t)(i0 + r) * 64 + j0 + cc]   = mv[r][cc];
        }
}

// ---------------- retention phase 2: scalar state scan over chunks --------
// S_{c+1} = gamma^RL * S_c + M_c ; store S_c (prefix) per chunk.
__global__ void ret_scan_k(const float* __restrict__ gammas)
{
    int idx = blockIdx.x * 256 + threadIdx.x;   // over B*H*64*64 = 131072
    int e  = idx & 4095;
    int bh = idx >> 12;
    int h  = bh & (HH - 1);
    float gL = powf(gammas[h], (float)RL);
    float s = 0.f;
#pragma unroll
    for (int c = 0; c < RNC; c++) {
        size_t o = ((size_t)bh * RNC + c) * 4096 + e;
        g_Sp[o] = s;
        s = gL * s + g_M[o];
    }
}

// ---------------- retention phase 3: out += (gamma^{i+1} q_i / 8) @ S_c ---
__global__ __launch_bounds__(256)
void ret_p3(const float* __restrict__ gammas, float* __restrict__ out)
{
    __shared__ float Qs[64 * 64];
    __shared__ float Ss[64 * 64];
    __shared__ float gp[65];
    int c = blockIdx.x, h = blockIdx.y, b = blockIdx.z;
    int tid = threadIdx.x, tx = tid & 15, ty = tid >> 4;
    if (tid < 65) gp[tid] = powf(gammas[h], (float)tid);
    __syncthreads();

    size_t base = ((size_t)b * SS + (size_t)c * RL) * DD + (size_t)h * HDD;
    size_t sb   = (((size_t)(b * HH + h)) * RNC + c) * 4096;
#pragma unroll
    for (int rep = 0; rep < 4; rep++) {
        int e = rep * 1024 + tid * 4;
        int row = e >> 6, col = e & 63;
        float4 qv = *(const float4*)&g_qp[base + (size_t)row * DD + col];
        float s0 = gp[row + 1] * 0.125f;
        *(float4*)&Qs[e] = make_float4(qv.x * s0, qv.y * s0, qv.z * s0, qv.w * s0);
        *(float4*)&Ss[e] = *(const float4*)&g_Sp[sb + e];
    }
    __syncthreads();

    int i0 = ty << 2, d0 = tx << 2;
    float o[4][4];
#pragma unroll
    for (int r = 0; r < 4; r++)
#pragma unroll
        for (int cc = 0; cc < 4; cc++) o[r][cc] = 0.f;

#pragma unroll 4
    for (int r1 = 0; r1 < 64; r1++) {
        float qf[4], sf[4];
#pragma unroll
        for (int r = 0; r < 4; r++) qf[r] = Qs[(i0 + r) * 64 + r1];
#pragma unroll
        for (int cc = 0; cc < 4; cc++) sf[cc] = Ss[r1 * 64 + d0 + cc];
#pragma unroll
        for (int r = 0; r < 4; r++)
#pragma unroll
            for (int cc = 0; cc < 4; cc++) o[r][cc] += qf[r] * sf[cc];
    }
#pragma unroll
    for (int r = 0; r < 4; r++)
#pragma unroll
        for (int cc = 0; cc < 4; cc++) {
            size_t oo = base + (size_t)(i0 + r) * DD + d0 + cc;
            out[oo] += o[r][cc];
        }
}

// ---------------- launch --------------------------------------------------
extern "C" void kernel_launch(void* const* d_in, const int* in_sizes, int n_in,
                              void* d_out, int out_size)
{
    const float* q      = (const float*)d_in[0];
    const float* k      = (const float*)d_in[1];
    const float* v      = (const float*)d_in[2];
    const float* W_in   = (const float*)d_in[3];
    const float* b_in   = (const float*)d_in[4];
    const float* W_gate = (const float*)d_in[5];
    const float* b_gate = (const float*)d_in[6];
    const float* W_out  = (const float*)d_in[7];
    const float* b_out  = (const float*)d_in[8];
    const float* gammas = (const float*)d_in[9];
    float* out = (float*)d_out;

    void *pu, *pa, *ph, *pqp;
    cudaGetSymbolAddress(&pu,  g_u);
    cudaGetSymbolAddress(&pa,  g_a);
    cudaGetSymbolAddress(&ph,  g_h);
    cudaGetSymbolAddress(&pqp, g_qp);

    dim3 gg(DD / 64, MM / 64);   // (16, 64)

    // u = q@W_in + b_in ; a = sigmoid(q@W_gate + b_gate)
    gemm_k<1><<<gg, 256>>>(q, W_in, W_gate, b_in, b_gate, (float*)pu, (float*)pa);

    // gated scan h_t = a_t h_{t-1} + u_t
    scan_chunk_k <<<dim3(DD / 256, NC, BB), 256>>>();
    scan_prefix_k<<<dim3(DD / 256, BB),     256>>>();
    scan_apply_k <<<dim3(DD / 256, NC, BB), 256>>>();

    // q_proj = h@W_out + b_out
    gemm_k<0><<<gg, 256>>>((const float*)ph, W_out, nullptr, b_out, nullptr,
                           (float*)pqp, nullptr);

    // retention (chunked linear attention form)
    const int P1_SMEM = (4096 + 64 * 65 + 4096 + 65) * 4;   // 49668 bytes
    cudaFuncSetAttribute(ret_p1, cudaFuncAttributeMaxDynamicSharedMemorySize, P1_SMEM);
    ret_p1<<<dim3(RNC, HH, BB), 256, P1_SMEM>>>(k, v, gammas, out);
    ret_scan_k<<<(BB * HH * HDD * HDD) / 256, 256>>>(gammas);
    ret_p3<<<dim3(RNC, HH, BB), 256>>>(gammas, out);
}

// round 3
// speedup vs baseline: 1.2951x; 1.2951x over previous
#include <cuda_runtime.h>
#include <cuda_bf16.h>
#include <math.h>
#include <stdint.h>

#define BB  2
#define SS  2048
#define DD  1024
#define HH  16
#define HDD 64
#define MM  (BB*SS)
#define SCL 32            // scan chunk length
#define SNC (SS/SCL)      // 64 scan chunks
#define RL  64            // retention chunk length
#define RNC (SS/RL)       // 32 retention chunks

// ---------------- scratch ---------------------------------------------------
__device__ float g_u [BB*SS*DD];
__device__ float g_a [BB*SS*DD];
__device__ float g_h [BB*SS*DD];
__device__ float g_qp[BB*SS*DD];
__device__ float g_Ac[BB*SNC*DD];
__device__ float g_Uc[BB*SNC*DD];
__device__ float g_P [BB*SNC*DD];
__device__ float g_M [BB*HH*RNC*HDD*HDD];
__device__ float g_Sp[BB*HH*RNC*HDD*HDD];

// ---------------- helpers ---------------------------------------------------
__device__ __forceinline__ uint32_t smem_u32(const void* p) {
    uint32_t a;
    asm("{ .reg .u64 t; cvta.to.shared.u64 t, %1; cvt.u32.u64 %0, t; }"
        : "=r"(a) : "l"(p));
    return a;
}
#define SW(o) ((o) ^ ((((uint32_t)(o)) >> 3) & 0x70))

__device__ __forceinline__ void ldsm_x4(uint32_t addr, uint32_t* r) {
    asm volatile("ldmatrix.sync.aligned.m8n8.x4.shared.b16 {%0,%1,%2,%3}, [%4];"
                 : "=r"(r[0]), "=r"(r[1]), "=r"(r[2]), "=r"(r[3]) : "r"(addr));
}
__device__ __forceinline__ void ldsm_x2(uint32_t addr, uint32_t* r) {
    asm volatile("ldmatrix.sync.aligned.m8n8.x2.shared.b16 {%0,%1}, [%2];"
                 : "=r"(r[0]), "=r"(r[1]) : "r"(addr));
}
__device__ __forceinline__ void mma_bf16(float* d, const uint32_t* a, const uint32_t* b) {
    asm volatile("mma.sync.aligned.m16n8k16.row.col.f32.bf16.bf16.f32 "
                 "{%0,%1,%2,%3}, {%4,%5,%6,%7}, {%8,%9}, {%0,%1,%2,%3};"
                 : "+f"(d[0]), "+f"(d[1]), "+f"(d[2]), "+f"(d[3])
                 : "r"(a[0]), "r"(a[1]), "r"(a[2]), "r"(a[3]), "r"(b[0]), "r"(b[1]));
}
__device__ __forceinline__ void split2(float x, float y, uint32_t& hi, uint32_t& lo) {
    __nv_bfloat16 hx = __float2bfloat16(x), hy = __float2bfloat16(y);
    float rx = x - __bfloat162float(hx);
    float ry = y - __bfloat162float(hy);
    __nv_bfloat16 lx = __float2bfloat16(rx), ly = __float2bfloat16(ry);
    hi = ((uint32_t)__bfloat16_as_ushort(hy) << 16) | (uint32_t)__bfloat16_as_ushort(hx);
    lo = ((uint32_t)__bfloat16_as_ushort(ly) << 16) | (uint32_t)__bfloat16_as_ushort(lx);
}

// ---------------- mma.sync GEMM: C = X*W + b (DUAL: +sigmoid second) -------
// X [4096,1024] rm, W [1024,1024] rm. 128x128 CTA tile, 512 thr, K-chunk 64.
// Split precision: X = Ahi+Alo, W = Bhi+Blo; C ~= Ahi*Bhi + Ahi*Blo + Alo*Bhi.
#define OF_AHI 0u
#define OF_ALO 16384u
#define OF_B1H 32768u
#define OF_B1L 49152u
#define OF_B2H 65536u
#define OF_B2L 81920u
#define SMEM_DUAL   98304u
#define SMEM_SINGLE 65536u

template<int DUAL>
__global__ __launch_bounds__(512)
void gemm_mma(const float* __restrict__ X,
              const float* __restrict__ W1, const float* __restrict__ W2,
              const float* __restrict__ b1, const float* __restrict__ b2,
              float* __restrict__ O1, float* __restrict__ O2)
{
    extern __shared__ char sm[];
    const uint32_t sb = smem_u32(sm);
    const int tid = threadIdx.x, wid = tid >> 5, lane = tid & 31;
    const int m0 = blockIdx.y * 128, n0 = blockIdx.x * 128;
    const int wrow = (wid >> 2) * 32, wcol = (wid & 3) * 32;

    float acc1[2][4][4];
    float acc2[2][4][4];
#pragma unroll
    for (int mt = 0; mt < 2; mt++)
#pragma unroll
        for (int nt = 0; nt < 4; nt++)
#pragma unroll
            for (int c = 0; c < 4; c++) { acc1[mt][nt][c] = 0.f; acc2[mt][nt][c] = 0.f; }

    // precompute ldmatrix lane row indices
    const int aq = lane >> 3, ar = lane & 7;           // A: quad, row-in-quad
    const int br = lane & 7, bh = (lane >> 3) & 1;     // B: row, k-half

    for (int kc = 0; kc < 16; kc++) {
        // ---- A tile: 128 rows x 64 floats -> bf16 hi/lo, SW128 ----
        const float* Xp = X + (size_t)m0 * 1024 + kc * 64;
#pragma unroll
        for (int it = 0; it < 4; it++) {
            int i = it * 512 + tid;                    // 0..2047 float4s
            int row = i >> 4, c4 = (i & 15) << 2;
            float4 xv = *(const float4*)&Xp[(size_t)row * 1024 + c4];
            uint32_t h01, l01, h23, l23;
            split2(xv.x, xv.y, h01, l01);
            split2(xv.z, xv.w, h23, l23);
            uint32_t off = SW(row * 128 + c4 * 2);
            *(uint2*)(sm + OF_AHI + off) = make_uint2(h01, h23);
            *(uint2*)(sm + OF_ALO + off) = make_uint2(l01, l23);
        }
        // ---- B tiles: W[kc*64+k][n0+n] -> Bs[n][k-pairs] hi/lo, SW128 ----
#pragma unroll
        for (int mat = 0; mat < (DUAL ? 2 : 1); mat++) {
            const float* Wp = (mat ? W2 : W1) + (size_t)(kc * 64) * 1024 + n0;
            uint32_t ofh = mat ? OF_B2H : OF_B1H;
            uint32_t ofl = mat ? OF_B2L : OF_B1L;
#pragma unroll
            for (int it = 0; it < 2; it++) {
                int i = it * 512 + tid;                // 0..1023
                int kp = i >> 5, n4 = (i & 31) << 2;
                const float* w0 = Wp + (size_t)(kp * 2) * 1024 + n4;
                float4 a = *(const float4*)w0;
                float4 b = *(const float4*)(w0 + 1024);
                uint32_t hi, lo, off;
                split2(a.x, b.x, hi, lo);
                off = SW((n4 + 0) * 128 + kp * 4);
                *(uint32_t*)(sm + ofh + off) = hi; *(uint32_t*)(sm + ofl + off) = lo;
                split2(a.y, b.y, hi, lo);
                off = SW((n4 + 1) * 128 + kp * 4);
                *(uint32_t*)(sm + ofh + off) = hi; *(uint32_t*)(sm + ofl + off) = lo;
                split2(a.z, b.z, hi, lo);
                off = SW((n4 + 2) * 128 + kp * 4);
                *(uint32_t*)(sm + ofh + off) = hi; *(uint32_t*)(sm + ofl + off) = lo;
                split2(a.w, b.w, hi, lo);
                off = SW((n4 + 3) * 128 + kp * 4);
                *(uint32_t*)(sm + ofh + off) = hi; *(uint32_t*)(sm + ofl + off) = lo;
            }
        }
        __syncthreads();

        // ---- fragments + mma over 4 k16 steps ----
#pragma unroll
        for (int ks = 0; ks < 4; ks++) {
            int k0 = ks * 16;
            uint32_t aHI[2][4], aLO[2][4];
#pragma unroll
            for (int mt = 0; mt < 2; mt++) {
                int m = wrow + mt * 16 + (aq & 1) * 8 + ar;
                int k = k0 + (aq >> 1) * 8;
                uint32_t off = SW(m * 128 + k * 2);
                ldsm_x4(sb + OF_AHI + off, aHI[mt]);
                ldsm_x4(sb + OF_ALO + off, aLO[mt]);
            }
            uint32_t bH[4][2], bL[4][2];
#pragma unroll
            for (int nt = 0; nt < 4; nt++) {
                int n = wcol + nt * 8 + br;
                int k = k0 + bh * 8;
                uint32_t off = SW(n * 128 + k * 2);
                ldsm_x2(sb + OF_B1H + off, bH[nt]);
                ldsm_x2(sb + OF_B1L + off, bL[nt]);
            }
#pragma unroll
            for (int mt = 0; mt < 2; mt++)
#pragma unroll
                for (int nt = 0; nt < 4; nt++) {
                    mma_bf16(acc1[mt][nt], aHI[mt], bH[nt]);
                    mma_bf16(acc1[mt][nt], aHI[mt], bL[nt]);
                    mma_bf16(acc1[mt][nt], aLO[mt], bH[nt]);
                }
            if (DUAL) {
#pragma unroll
                for (int nt = 0; nt < 4; nt++) {
                    int n = wcol + nt * 8 + br;
                    int k = k0 + bh * 8;
                    uint32_t off = SW(n * 128 + k * 2);
                    ldsm_x2(sb + OF_B2H + off, bH[nt]);
                    ldsm_x2(sb + OF_B2L + off, bL[nt]);
                }
#pragma unroll
                for (int mt = 0; mt < 2; mt++)
#pragma unroll
                    for (int nt = 0; nt < 4; nt++) {
                        mma_bf16(acc2[mt][nt], aHI[mt], bH[nt]);
                        mma_bf16(acc2[mt][nt], aHI[mt], bL[nt]);
                        mma_bf16(acc2[mt][nt], aLO[mt], bH[nt]);
                    }
            }
        }
        __syncthreads();
    }

    // ---- epilogue: direct register -> global ----
#pragma unroll
    for (int nt = 0; nt < 4; nt++) {
        int n = n0 + wcol + nt * 8 + (lane & 3) * 2;
        float bv0 = __ldg(&b1[n]), bv1 = __ldg(&b1[n + 1]);
        float gv0 = 0.f, gv1 = 0.f;
        if (DUAL) { gv0 = __ldg(&b2[n]); gv1 = __ldg(&b2[n + 1]); }
#pragma unroll
        for (int mt = 0; mt < 2; mt++) {
            int m = m0 + wrow + mt * 16 + (lane >> 2);
            float2 v0 = make_float2(acc1[mt][nt][0] + bv0, acc1[mt][nt][1] + bv1);
            float2 v1 = make_float2(acc1[mt][nt][2] + bv0, acc1[mt][nt][3] + bv1);
            *(float2*)&O1[(size_t)m * 1024 + n]       = v0;
            *(float2*)&O1[(size_t)(m + 8) * 1024 + n] = v1;
            if (DUAL) {
                float2 s0, s1;
                s0.x = 1.f / (1.f + expf(-(acc2[mt][nt][0] + gv0)));
                s0.y = 1.f / (1.f + expf(-(acc2[mt][nt][1] + gv1)));
                s1.x = 1.f / (1.f + expf(-(acc2[mt][nt][2] + gv0)));
                s1.y = 1.f / (1.f + expf(-(acc2[mt][nt][3] + gv1)));
                *(float2*)&O2[(size_t)m * 1024 + n]       = s0;
                *(float2*)&O2[(size_t)(m + 8) * 1024 + n] = s1;
            }
        }
    }
}

// ---------------- gated scan (float4, 3-phase, chunk=32) -------------------
__global__ void scan_chunk_k()
{
    int d4 = threadIdx.x;
    int c = blockIdx.x, b = blockIdx.y;
    const float4* af = (const float4*)g_a;
    const float4* uf = (const float4*)g_u;
    size_t base = ((size_t)b * SS + (size_t)c * SCL) * 256 + d4;
    float4 A = make_float4(1.f, 1.f, 1.f, 1.f);
    float4 U = make_float4(0.f, 0.f, 0.f, 0.f);
#pragma unroll 8
    for (int j = 0; j < SCL; j++) {
        float4 av = af[base + (size_t)j * 256];
        float4 uv = uf[base + (size_t)j * 256];
        U.x = av.x * U.x + uv.x; U.y = av.y * U.y + uv.y;
        U.z = av.z * U.z + uv.z; U.w = av.w * U.w + uv.w;
        A.x *= av.x; A.y *= av.y; A.z *= av.z; A.w *= av.w;
    }
    size_t o = ((size_t)b * SNC + c) * 256 + d4;
    ((float4*)g_Ac)[o] = A;
    ((float4*)g_Uc)[o] = U;
}

__global__ void scan_prefix_k()
{
    int d4 = threadIdx.x;
    int b = blockIdx.x;
    float4 h = make_float4(0.f, 0.f, 0.f, 0.f);
#pragma unroll
    for (int c = 0; c < SNC; c++) {
        size_t o = ((size_t)b * SNC + c) * 256 + d4;
        ((float4*)g_P)[o] = h;
        float4 A = ((const float4*)g_Ac)[o];
        float4 U = ((const float4*)g_Uc)[o];
        h.x = A.x * h.x + U.x; h.y = A.y * h.y + U.y;
        h.z = A.z * h.z + U.z; h.w = A.w * h.w + U.w;
    }
}

__global__ void scan_apply_k()
{
    int d4 = threadIdx.x;
    int c = blockIdx.x, b = blockIdx.y;
    float4 h = ((const float4*)g_P)[((size_t)b * SNC + c) * 256 + d4];
    const float4* af = (const float4*)g_a;
    const float4* uf = (const float4*)g_u;
    float4* hf = (float4*)g_h;
    size_t base = ((size_t)b * SS + (size_t)c * SCL) * 256 + d4;
#pragma unroll 8
    for (int j = 0; j < SCL; j++) {
        float4 av = af[base + (size_t)j * 256];
        float4 uv = uf[base + (size_t)j * 256];
        h.x = av.x * h.x + uv.x; h.y = av.y * h.y + uv.y;
        h.z = av.z * h.z + uv.z; h.w = av.w * h.w + uv.w;
        hf[base + (size_t)j * 256] = h;
    }
}

// ---------------- retention phase 1 ----------------------------------------
__global__ __launch_bounds__(256)
void ret_p1(const float* __restrict__ kin, const float* __restrict__ vin,
            const float* __restrict__ gammas, float* __restrict__ out)
{
    extern __shared__ float smf[];
    float* Qs = smf;
    float* Ks = smf + 4096;
    float* Vs = Ks + 64 * 65;
    float* gp = Vs + 4096;

    int c = blockIdx.x, h = blockIdx.y, b = blockIdx.z;
    int tid = threadIdx.x, tx = tid & 15, ty = tid >> 4;
    if (tid < 65) gp[tid] = powf(gammas[h], (float)tid);

    size_t base = ((size_t)b * SS + (size_t)c * RL) * DD + (size_t)h * HDD;
#pragma unroll
    for (int rep = 0; rep < 4; rep++) {
        int e = rep * 1024 + tid * 4;
        int row = e >> 6, col = e & 63;
        size_t ga = base + (size_t)row * DD + col;
        float4 qv = *(const float4*)&g_qp[ga];
        *(float4*)&Qs[row * 64 + col] = qv;
        float4 kv = *(const float4*)&kin[ga];
        Ks[row * 65 + col + 0] = kv.x;
        Ks[row * 65 + col + 1] = kv.y;
        Ks[row * 65 + col + 2] = kv.z;
        Ks[row * 65 + col + 3] = kv.w;
        float4 vv = *(const float4*)&vin[ga];
        *(float4*)&Vs[row * 64 + col] = vv;
    }
    __syncthreads();

    int i0 = ty << 2, j0 = tx << 2;
    float sc[4][4];
#pragma unroll
    for (int r = 0; r < 4; r++)
#pragma unroll
        for (int cc = 0; cc < 4; cc++) sc[r][cc] = 0.f;

#pragma unroll 4
    for (int d = 0; d < 64; d++) {
        float qf[4], kf[4];
#pragma unroll
        for (int r = 0; r < 4; r++) qf[r] = Qs[(i0 + r) * 64 + d];
#pragma unroll
        for (int r = 0; r < 4; r++) kf[r] = Ks[(j0 + r) * 65 + d];
#pragma unroll
        for (int r = 0; r < 4; r++)
#pragma unroll
            for (int cc = 0; cc < 4; cc++) sc[r][cc] += qf[r] * kf[cc];
    }
    float pr[4][4];
#pragma unroll
    for (int r = 0; r < 4; r++)
#pragma unroll
        for (int cc = 0; cc < 4; cc++) {
            int di = (i0 + r) - (j0 + cc);
            pr[r][cc] = (di >= 0) ? sc[r][cc] * gp[di] * 0.125f : 0.f;
        }
    __syncthreads();
#pragma unroll
    for (int r = 0; r < 4; r++)
#pragma unroll
        for (int cc = 0; cc < 4; cc++)
            Qs[(i0 + r) * 64 + j0 + cc] = pr[r][cc];
    __syncthreads();

    float ov[4][4], mv[4][4];
#pragma unroll
    for (int r = 0; r < 4; r++)
#pragma unroll
        for (int cc = 0; cc < 4; cc++) { ov[r][cc] = 0.f; mv[r][cc] = 0.f; }

#pragma unroll 4
    for (int j = 0; j < 64; j++) {
        float w = gp[63 - j];
        float pf[4], kf[4], vf[4];
#pragma unroll
        for (int r = 0; r < 4; r++) pf[r] = Qs[(i0 + r) * 64 + j];
#pragma unroll
        for (int r = 0; r < 4; r++) kf[r] = Ks[j * 65 + i0 + r] * w;
#pragma unroll
        for (int cc = 0; cc < 4; cc++) vf[cc] = Vs[j * 64 + j0 + cc];
#pragma unroll
        for (int r = 0; r < 4; r++)
#pragma unroll
            for (int cc = 0; cc < 4; cc++) {
                ov[r][cc] += pf[r] * vf[cc];
                mv[r][cc] += kf[r] * vf[cc];
            }
    }
    size_t mb = (((size_t)(b * HH + h)) * RNC + c) * 4096;
#pragma unroll
    for (int r = 0; r < 4; r++)
#pragma unroll
        for (int cc = 0; cc < 4; cc++) {
            out[base + (size_t)(i0 + r) * DD + j0 + cc] = ov[r][cc];
            g_M[mb + (size_t)(i0 + r) * 64 + j0 + cc]   = mv[r][cc];
        }
}

// ---------------- retention phase 2 ----------------------------------------
__global__ void ret_scan_k(const float* __restrict__ gammas)
{
    int idx = blockIdx.x * 256 + threadIdx.x;
    int e  = idx & 4095;
    int bh2 = idx >> 12;
    int h  = bh2 & (HH - 1);
    float gL = powf(gammas[h], (float)RL);
    float s = 0.f;
#pragma unroll
    for (int c = 0; c < RNC; c++) {
        size_t o = ((size_t)bh2 * RNC + c) * 4096 + e;
        g_Sp[o] = s;
        s = gL * s + g_M[o];
    }
}

// ---------------- retention phase 3 ----------------------------------------
__global__ __launch_bounds__(256)
void ret_p3(const float* __restrict__ gammas, float* __restrict__ out)
{
    __shared__ float Qs[64 * 64];
    __shared__ float Ssm[64 * 64];
    __shared__ float gp[65];
    int c = blockIdx.x, h = blockIdx.y, b = blockIdx.z;
    int tid = threadIdx.x, tx = tid & 15, ty = tid >> 4;
    if (tid < 65) gp[tid] = powf(gammas[h], (float)tid);
    __syncthreads();

    size_t base = ((size_t)b * SS + (size_t)c * RL) * DD + (size_t)h * HDD;
    size_t sbo  = (((size_t)(b * HH + h)) * RNC + c) * 4096;
#pragma unroll
    for (int rep = 0; rep < 4; rep++) {
        int e = rep * 1024 + tid * 4;
        int row = e >> 6, col = e & 63;
        float4 qv = *(const float4*)&g_qp[base + (size_t)row * DD + col];
        float s0 = gp[row + 1] * 0.125f;
        *(float4*)&Qs[e] = make_float4(qv.x * s0, qv.y * s0, qv.z * s0, qv.w * s0);
        *(float4*)&Ssm[e] = *(const float4*)&g_Sp[sbo + e];
    }
    __syncthreads();

    int i0 = ty << 2, d0 = tx << 2;
    float o[4][4];
#pragma unroll
    for (int r = 0; r < 4; r++)
#pragma unroll
        for (int cc = 0; cc < 4; cc++) o[r][cc] = 0.f;

#pragma unroll 4
    for (int r1 = 0; r1 < 64; r1++) {
        float qf[4], sf[4];
#pragma unroll
        for (int r = 0; r < 4; r++) qf[r] = Qs[(i0 + r) * 64 + r1];
#pragma unroll
        for (int cc = 0; cc < 4; cc++) sf[cc] = Ssm[r1 * 64 + d0 + cc];
#pragma unroll
        for (int r = 0; r < 4; r++)
#pragma unroll
            for (int cc = 0; cc < 4; cc++) o[r][cc] += qf[r] * sf[cc];
    }
#pragma unroll
    for (int r = 0; r < 4; r++)
#pragma unroll
        for (int cc = 0; cc < 4; cc++) {
            size_t oo = base + (size_t)(i0 + r) * DD + d0 + cc;
            out[oo] += o[r][cc];
        }
}

// ---------------- launch ---------------------------------------------------
extern "C" void kernel_launch(void* const* d_in, const int* in_sizes, int n_in,
                              void* d_out, int out_size)
{
    const float* q      = (const float*)d_in[0];
    const float* k      = (const float*)d_in[1];
    const float* v      = (const float*)d_in[2];
    const float* W_in   = (const float*)d_in[3];
    const float* b_in   = (const float*)d_in[4];
    const float* W_gate = (const float*)d_in[5];
    const float* b_gate = (const float*)d_in[6];
    const float* W_out  = (const float*)d_in[7];
    const float* b_out  = (const float*)d_in[8];
    const float* gammas = (const float*)d_in[9];
    float* out = (float*)d_out;

    void *pu, *pa, *ph, *pqp;
    cudaGetSymbolAddress(&pu,  g_u);
    cudaGetSymbolAddress(&pa,  g_a);
    cudaGetSymbolAddress(&ph,  g_h);
    cudaGetSymbolAddress(&pqp, g_qp);

    cudaFuncSetAttribute(gemm_mma<1>, cudaFuncAttributeMaxDynamicSharedMemorySize, SMEM_DUAL);
    cudaFuncSetAttribute(gemm_mma<0>, cudaFuncAttributeMaxDynamicSharedMemorySize, SMEM_SINGLE);
    const int P1_SMEM = (4096 + 64 * 65 + 4096 + 65) * 4;
    cudaFuncSetAttribute(ret_p1, cudaFuncAttributeMaxDynamicSharedMemorySize, P1_SMEM);

    dim3 gg(8, 32);   // 128x128 tiles over 4096x1024

    // u = q@W_in + b_in ; a = sigmoid(q@W_gate + b_gate)
    gemm_mma<1><<<gg, 512, SMEM_DUAL>>>(q, W_in, W_gate, b_in, b_gate,
                                        (float*)pu, (float*)pa);

    // gated scan h_t = a_t h_{t-1} + u_t
    scan_chunk_k <<<dim3(SNC, BB), 256>>>();
    scan_prefix_k<<<BB, 256>>>();
    scan_apply_k <<<dim3(SNC, BB), 256>>>();

    // q_proj = h@W_out + b_out
    gemm_mma<0><<<gg, 512, SMEM_SINGLE>>>((const float*)ph, W_out, nullptr,
                                          b_out, nullptr, (float*)pqp, nullptr);

    // retention
    ret_p1<<<dim3(RNC, HH, BB), 256, P1_SMEM>>>(k, v, gammas, out);
    ret_scan_k<<<(BB * HH * HDD * HDD) / 256, 256>>>(gammas);
    ret_p3<<<dim3(RNC, HH, BB), 256>>>(gammas, out);
}

// round 4
// speedup vs baseline: 2.1900x; 1.6910x over previous
#include <cuda_runtime.h>
#include <cuda_bf16.h>
#include <math.h>
#include <stdint.h>

#define BB  2
#define SS  2048
#define DD  1024
#define HH  16
#define HDD 64
#define MM  (BB*SS)
#define SCL 16            // scan chunk length
#define SNC (SS/SCL)      // 128 scan chunks
#define RL  64            // retention chunk length
#define RNC (SS/RL)       // 32 retention chunks

// ---------------- scratch ---------------------------------------------------
__device__ float g_u [BB*SS*DD];
__device__ float g_a [BB*SS*DD];
__device__ float g_qp[BB*SS*DD];
__device__ float g_Ac[BB*SNC*DD];
__device__ float g_Uc[BB*SNC*DD];
__device__ float g_P [BB*SNC*DD];
__device__ float g_M [BB*HH*RNC*HDD*HDD];
__device__ float g_Sp[BB*HH*RNC*HDD*HDD];

__device__ __nv_bfloat16 g_Xhi[MM*DD], g_Xlo[MM*DD];   // q split
__device__ __nv_bfloat16 g_Hhi[MM*DD], g_Hlo[MM*DD];   // h split (from scan)
__device__ __nv_bfloat16 g_W1h[DD*DD], g_W1l[DD*DD];   // W_in^T split
__device__ __nv_bfloat16 g_W2h[DD*DD], g_W2l[DD*DD];   // W_gate^T split
__device__ __nv_bfloat16 g_W3h[DD*DD], g_W3l[DD*DD];   // W_out^T split

// ---------------- helpers ---------------------------------------------------
__device__ __forceinline__ uint32_t smem_u32(const void* p) {
    uint32_t a;
    asm("{ .reg .u64 t; cvta.to.shared.u64 t, %1; cvt.u32.u64 %0, t; }"
        : "=r"(a) : "l"(p));
    return a;
}
#define SW(o) ((o) ^ ((((uint32_t)(o)) >> 3) & 0x70))

#define CP_ASYNC16(dst, src) \
    asm volatile("cp.async.cg.shared.global [%0], [%1], 16;" :: "r"(dst), "l"(src))
#define CP_COMMIT() asm volatile("cp.async.commit_group;" ::: "memory")
#define CP_WAIT1()  asm volatile("cp.async.wait_group 1;" ::: "memory")
#define CP_WAIT0()  asm volatile("cp.async.wait_group 0;" ::: "memory")

__device__ __forceinline__ void ldsm_x4(uint32_t addr, uint32_t* r) {
    asm volatile("ldmatrix.sync.aligned.m8n8.x4.shared.b16 {%0,%1,%2,%3}, [%4];"
                 : "=r"(r[0]), "=r"(r[1]), "=r"(r[2]), "=r"(r[3]) : "r"(addr));
}
__device__ __forceinline__ void ldsm_x2(uint32_t addr, uint32_t* r) {
    asm volatile("ldmatrix.sync.aligned.m8n8.x2.shared.b16 {%0,%1}, [%2];"
                 : "=r"(r[0]), "=r"(r[1]) : "r"(addr));
}
__device__ __forceinline__ void mma_bf16(float* d, const uint32_t* a, const uint32_t* b) {
    asm volatile("mma.sync.aligned.m16n8k16.row.col.f32.bf16.bf16.f32 "
                 "{%0,%1,%2,%3}, {%4,%5,%6,%7}, {%8,%9}, {%0,%1,%2,%3};"
                 : "+f"(d[0]), "+f"(d[1]), "+f"(d[2]), "+f"(d[3])
                 : "r"(a[0]), "r"(a[1]), "r"(a[2]), "r"(a[3]), "r"(b[0]), "r"(b[1]));
}
__device__ __forceinline__ void split2(float x, float y, uint32_t& hi, uint32_t& lo) {
    __nv_bfloat16 hx = __float2bfloat16(x), hy = __float2bfloat16(y);
    float rx = x - __bfloat162float(hx);
    float ry = y - __bfloat162float(hy);
    __nv_bfloat16 lx = __float2bfloat16(rx), ly = __float2bfloat16(ry);
    hi = ((uint32_t)__bfloat16_as_ushort(hy) << 16) | (uint32_t)__bfloat16_as_ushort(hx);
    lo = ((uint32_t)__bfloat16_as_ushort(ly) << 16) | (uint32_t)__bfloat16_as_ushort(lx);
}

// ---------------- conversion kernels ---------------------------------------
__global__ __launch_bounds__(256)
void conv_x_k(const float* __restrict__ X, __nv_bfloat16* __restrict__ hi,
              __nv_bfloat16* __restrict__ lo)
{
    int i = blockIdx.x * 256 + threadIdx.x;          // float4 index
    float4 v = ((const float4*)X)[i];
    uint32_t h01, l01, h23, l23;
    split2(v.x, v.y, h01, l01);
    split2(v.z, v.w, h23, l23);
    ((uint2*)hi)[i] = make_uint2(h01, h23);
    ((uint2*)lo)[i] = make_uint2(l01, l23);
}

// W[k][n] f32 -> Wt[n][k] bf16 hi/lo (transpose + split)
__global__ __launch_bounds__(256)
void conv_w_k(const float* __restrict__ W, __nv_bfloat16* __restrict__ hi,
              __nv_bfloat16* __restrict__ lo)
{
    __shared__ float t[32][33];
    int n0 = blockIdx.x * 32, k0 = blockIdx.y * 32;
    int tx = threadIdx.x & 31, ty = threadIdx.x >> 5;   // (32, 8)
#pragma unroll
    for (int r = 0; r < 4; r++)
        t[ty * 4 + r][tx] = W[(size_t)(k0 + ty * 4 + r) * DD + n0 + tx];
    __syncthreads();
#pragma unroll
    for (int r = 0; r < 4; r++) {
        int n = ty * 4 + r;
        float v = t[tx][n];                 // W[k0+tx][n0+n]
        __nv_bfloat16 hv = __float2bfloat16(v);
        float rv = v - __bfloat162float(hv);
        size_t o = (size_t)(n0 + n) * DD + k0 + tx;
        hi[o] = hv;
        lo[o] = __float2bfloat16(rv);
    }
}

// ---------------- mma.sync GEMM with cp.async pipeline ---------------------
// A tiles (rows m) and B tiles (rows n) both: 128 rows x 64 bf16 (128 B/row).
// Stage layout (offsets within stage): AHI 0, ALO 16K, B1H 32K, B1L 48K, [B2H 64K, B2L 80K]
template<int DUAL>
__global__ __launch_bounds__(512)
void gemm_mma(const __nv_bfloat16* __restrict__ Ahi_g, const __nv_bfloat16* __restrict__ Alo_g,
              const __nv_bfloat16* __restrict__ B1h_g, const __nv_bfloat16* __restrict__ B1l_g,
              const __nv_bfloat16* __restrict__ B2h_g, const __nv_bfloat16* __restrict__ B2l_g,
              const float* __restrict__ b1, const float* __restrict__ b2,
              float* __restrict__ O1, float* __restrict__ O2)
{
    extern __shared__ char sm[];
    const uint32_t sb = smem_u32(sm);
    const int NT = DUAL ? 6 : 4;
    const uint32_t STAGE = NT * 16384u;
    const int tid = threadIdx.x, wid = tid >> 5, lane = tid & 31;
    const int m0 = blockIdx.y * 128, n0 = blockIdx.x * 128;
    const int wrow = (wid >> 2) * 32, wcol = (wid & 3) * 32;

    const char* srcs[6];
    srcs[0] = (const char*)Ahi_g + (size_t)m0 * 2048;
    srcs[1] = (const char*)Alo_g + (size_t)m0 * 2048;
    srcs[2] = (const char*)B1h_g + (size_t)n0 * 2048;
    srcs[3] = (const char*)B1l_g + (size_t)n0 * 2048;
    if (DUAL) {
        srcs[4] = (const char*)B2h_g + (size_t)n0 * 2048;
        srcs[5] = (const char*)B2l_g + (size_t)n0 * 2048;
    }

    const int lrow = tid >> 3, lc16 = (tid & 7) * 16;   // 64 rows per 512-thr pass? no:
    // per tile: 128 rows x 8 x16B = 1024 ops; 512 threads -> 2 reps.
    // rep layout: i = rep*512 + tid; row = i>>3, c16 = (i&7)*16
    (void)lrow; (void)lc16;

    float acc1[2][4][4];
    float acc2[2][4][4];
#pragma unroll
    for (int mt = 0; mt < 2; mt++)
#pragma unroll
        for (int nt = 0; nt < 4; nt++)
#pragma unroll
            for (int c = 0; c < 4; c++) { acc1[mt][nt][c] = 0.f; acc2[mt][nt][c] = 0.f; }

    const int aq = lane >> 3, ar = lane & 7;
    const int br = lane & 7, bhh = (lane >> 3) & 1;

    // ---- stage loader ----
    auto load_stage = [&](int s, int kc) {
        uint32_t sbase = sb + (uint32_t)s * STAGE;
#pragma unroll
        for (int t = 0; t < NT; t++) {
            const char* gp = srcs[t] + (size_t)kc * 128;
#pragma unroll
            for (int rep = 0; rep < 2; rep++) {
                int i = rep * 512 + tid;
                int row = i >> 3, c16 = (i & 7) * 16;
                uint32_t so = sbase + t * 16384u + SW(row * 128 + c16);
                CP_ASYNC16(so, gp + (size_t)row * 2048 + c16);
            }
        }
        CP_COMMIT();
    };

    load_stage(0, 0);

    for (int kc = 0; kc < 16; kc++) {
        if (kc + 1 < 16) load_stage((kc + 1) & 1, kc + 1);
        else CP_COMMIT();          // keep group accounting uniform
        CP_WAIT1();
        __syncthreads();

        uint32_t stb = sb + (uint32_t)(kc & 1) * STAGE;
#pragma unroll
        for (int ks = 0; ks < 4; ks++) {
            int k0 = ks * 16;
            uint32_t aHI[2][4], aLO[2][4];
#pragma unroll
            for (int mt = 0; mt < 2; mt++) {
                int m = wrow + mt * 16 + (aq & 1) * 8 + ar;
                int k = k0 + (aq >> 1) * 8;
                uint32_t off = SW(m * 128 + k * 2);
                ldsm_x4(stb + off, aHI[mt]);
                ldsm_x4(stb + 16384u + off, aLO[mt]);
            }
            uint32_t bH[4][2], bL[4][2];
#pragma unroll
            for (int nt = 0; nt < 4; nt++) {
                int n = wcol + nt * 8 + br;
                int k = k0 + bhh * 8;
                uint32_t off = SW(n * 128 + k * 2);
                ldsm_x2(stb + 32768u + off, bH[nt]);
                ldsm_x2(stb + 49152u + off, bL[nt]);
            }
#pragma unroll
            for (int mt = 0; mt < 2; mt++)
#pragma unroll
                for (int nt = 0; nt < 4; nt++) {
                    mma_bf16(acc1[mt][nt], aHI[mt], bH[nt]);
                    mma_bf16(acc1[mt][nt], aHI[mt], bL[nt]);
                    mma_bf16(acc1[mt][nt], aLO[mt], bH[nt]);
                }
            if (DUAL) {
#pragma unroll
                for (int nt = 0; nt < 4; nt++) {
                    int n = wcol + nt * 8 + br;
                    int k = k0 + bhh * 8;
                    uint32_t off = SW(n * 128 + k * 2);
                    ldsm_x2(stb + 65536u + off, bH[nt]);
                    ldsm_x2(stb + 81920u + off, bL[nt]);
                }
#pragma unroll
                for (int mt = 0; mt < 2; mt++)
#pragma unroll
                    for (int nt = 0; nt < 4; nt++) {
                        mma_bf16(acc2[mt][nt], aHI[mt], bH[nt]);
                        mma_bf16(acc2[mt][nt], aHI[mt], bL[nt]);
                        mma_bf16(acc2[mt][nt], aLO[mt], bH[nt]);
                    }
            }
        }
        __syncthreads();
    }
    CP_WAIT0();

    // ---- epilogue ----
#pragma unroll
    for (int nt = 0; nt < 4; nt++) {
        int n = n0 + wcol + nt * 8 + (lane & 3) * 2;
        float bv0 = __ldg(&b1[n]), bv1 = __ldg(&b1[n + 1]);
        float gv0 = 0.f, gv1 = 0.f;
        if (DUAL) { gv0 = __ldg(&b2[n]); gv1 = __ldg(&b2[n + 1]); }
#pragma unroll
        for (int mt = 0; mt < 2; mt++) {
            int m = m0 + wrow + mt * 16 + (lane >> 2);
            float2 v0 = make_float2(acc1[mt][nt][0] + bv0, acc1[mt][nt][1] + bv1);
            float2 v1 = make_float2(acc1[mt][nt][2] + bv0, acc1[mt][nt][3] + bv1);
            *(float2*)&O1[(size_t)m * 1024 + n]       = v0;
            *(float2*)&O1[(size_t)(m + 8) * 1024 + n] = v1;
            if (DUAL) {
                float2 s0, s1;
                s0.x = 1.f / (1.f + expf(-(acc2[mt][nt][0] + gv0)));
                s0.y = 1.f / (1.f + expf(-(acc2[mt][nt][1] + gv1)));
                s1.x = 1.f / (1.f + expf(-(acc2[mt][nt][2] + gv0)));
                s1.y = 1.f / (1.f + expf(-(acc2[mt][nt][3] + gv1)));
                *(float2*)&O2[(size_t)m * 1024 + n]       = s0;
                *(float2*)&O2[(size_t)(m + 8) * 1024 + n] = s1;
            }
        }
    }
}
#define SMEM_DUAL   (2u * 6u * 16384u)   // 196608
#define SMEM_SINGLE (2u * 4u * 16384u)   // 131072

// ---------------- gated scan (float4, 3-phase, chunk=16) -------------------
__global__ void scan_chunk_k()
{
    int d4 = threadIdx.x;
    int c = blockIdx.x, b = blockIdx.y;
    const float4* af = (const float4*)g_a;
    const float4* uf = (const float4*)g_u;
    size_t base = ((size_t)b * SS + (size_t)c * SCL) * 256 + d4;
    float4 A = make_float4(1.f, 1.f, 1.f, 1.f);
    float4 U = make_float4(0.f, 0.f, 0.f, 0.f);
#pragma unroll
    for (int j = 0; j < SCL; j++) {
        float4 av = af[base + (size_t)j * 256];
        float4 uv = uf[base + (size_t)j * 256];
        U.x = av.x * U.x + uv.x; U.y = av.y * U.y + uv.y;
        U.z = av.z * U.z + uv.z; U.w = av.w * U.w + uv.w;
        A.x *= av.x; A.y *= av.y; A.z *= av.z; A.w *= av.w;
    }
    size_t o = ((size_t)b * SNC + c) * 256 + d4;
    ((float4*)g_Ac)[o] = A;
    ((float4*)g_Uc)[o] = U;
}

__global__ void scan_prefix_k()
{
    int d4 = threadIdx.x;
    int b = blockIdx.x;
    float4 h = make_float4(0.f, 0.f, 0.f, 0.f);
#pragma unroll 8
    for (int c = 0; c < SNC; c++) {
        size_t o = ((size_t)b * SNC + c) * 256 + d4;
        ((float4*)g_P)[o] = h;
        float4 A = ((const float4*)g_Ac)[o];
        float4 U = ((const float4*)g_Uc)[o];
        h.x = A.x * h.x + U.x; h.y = A.y * h.y + U.y;
        h.z = A.z * h.z + U.z; h.w = A.w * h.w + U.w;
    }
}

// applies the scan and emits h as bf16 hi/lo (ready for the W_out GEMM)
__global__ void scan_apply_k()
{
    int d4 = threadIdx.x;
    int c = blockIdx.x, b = blockIdx.y;
    float4 h = ((const float4*)g_P)[((size_t)b * SNC + c) * 256 + d4];
    const float4* af = (const float4*)g_a;
    const float4* uf = (const float4*)g_u;
    uint2* hh = (uint2*)g_Hhi;
    uint2* hl = (uint2*)g_Hlo;
    size_t base = ((size_t)b * SS + (size_t)c * SCL) * 256 + d4;
#pragma unroll
    for (int j = 0; j < SCL; j++) {
        float4 av = af[base + (size_t)j * 256];
        float4 uv = uf[base + (size_t)j * 256];
        h.x = av.x * h.x + uv.x; h.y = av.y * h.y + uv.y;
        h.z = av.z * h.z + uv.z; h.w = av.w * h.w + uv.w;
        uint32_t h01, l01, h23, l23;
        split2(h.x, h.y, h01, l01);
        split2(h.z, h.w, h23, l23);
        hh[base + (size_t)j * 256] = make_uint2(h01, h23);
        hl[base + (size_t)j * 256] = make_uint2(l01, l23);
    }
}

// ---------------- retention phase 1 ----------------------------------------
__global__ __launch_bounds__(256)
void ret_p1(const float* __restrict__ kin, const float* __restrict__ vin,
            const float* __restrict__ gammas, float* __restrict__ out)
{
    extern __shared__ float smf[];
    float* Qs = smf;
    float* Ks = smf + 4096;
    float* Vs = Ks + 64 * 65;
    float* gp = Vs + 4096;

    int c = blockIdx.x, h = blockIdx.y, b = blockIdx.z;
    int tid = threadIdx.x, tx = tid & 15, ty = tid >> 4;
    if (tid < 65) gp[tid] = powf(gammas[h], (float)tid);

    size_t base = ((size_t)b * SS + (size_t)c * RL) * DD + (size_t)h * HDD;
#pragma unroll
    for (int rep = 0; rep < 4; rep++) {
        int e = rep * 1024 + tid * 4;
        int row = e >> 6, col = e & 63;
        size_t ga = base + (size_t)row * DD + col;
        float4 qv = *(const float4*)&g_qp[ga];
        *(float4*)&Qs[row * 64 + col] = qv;
        float4 kv = *(const float4*)&kin[ga];
        Ks[row * 65 + col + 0] = kv.x;
        Ks[row * 65 + col + 1] = kv.y;
        Ks[row * 65 + col + 2] = kv.z;
        Ks[row * 65 + col + 3] = kv.w;
        float4 vv = *(const float4*)&vin[ga];
        *(float4*)&Vs[row * 64 + col] = vv;
    }
    __syncthreads();

    int i0 = ty << 2, j0 = tx << 2;
    float sc[4][4];
#pragma unroll
    for (int r = 0; r < 4; r++)
#pragma unroll
        for (int cc = 0; cc < 4; cc++) sc[r][cc] = 0.f;

#pragma unroll 4
    for (int d = 0; d < 64; d++) {
        float qf[4], kf[4];
#pragma unroll
        for (int r = 0; r < 4; r++) qf[r] = Qs[(i0 + r) * 64 + d];
#pragma unroll
        for (int r = 0; r < 4; r++) kf[r] = Ks[(j0 + r) * 65 + d];
#pragma unroll
        for (int r = 0; r < 4; r++)
#pragma unroll
            for (int cc = 0; cc < 4; cc++) sc[r][cc] += qf[r] * kf[cc];
    }
    float pr[4][4];
#pragma unroll
    for (int r = 0; r < 4; r++)
#pragma unroll
        for (int cc = 0; cc < 4; cc++) {
            int di = (i0 + r) - (j0 + cc);
            pr[r][cc] = (di >= 0) ? sc[r][cc] * gp[di] * 0.125f : 0.f;
        }
    __syncthreads();
#pragma unroll
    for (int r = 0; r < 4; r++)
#pragma unroll
        for (int cc = 0; cc < 4; cc++)
            Qs[(i0 + r) * 64 + j0 + cc] = pr[r][cc];
    __syncthreads();

    float ov[4][4], mv[4][4];
#pragma unroll
    for (int r = 0; r < 4; r++)
#pragma unroll
        for (int cc = 0; cc < 4; cc++) { ov[r][cc] = 0.f; mv[r][cc] = 0.f; }

#pragma unroll 4
    for (int j = 0; j < 64; j++) {
        float w = gp[63 - j];
        float pf[4], kf[4], vf[4];
#pragma unroll
        for (int r = 0; r < 4; r++) pf[r] = Qs[(i0 + r) * 64 + j];
#pragma unroll
        for (int r = 0; r < 4; r++) kf[r] = Ks[j * 65 + i0 + r] * w;
#pragma unroll
        for (int cc = 0; cc < 4; cc++) vf[cc] = Vs[j * 64 + j0 + cc];
#pragma unroll
        for (int r = 0; r < 4; r++)
#pragma unroll
            for (int cc = 0; cc < 4; cc++) {
                ov[r][cc] += pf[r] * vf[cc];
                mv[r][cc] += kf[r] * vf[cc];
            }
    }
    size_t mb = (((size_t)(b * HH + h)) * RNC + c) * 4096;
#pragma unroll
    for (int r = 0; r < 4; r++)
#pragma unroll
        for (int cc = 0; cc < 4; cc++) {
            out[base + (size_t)(i0 + r) * DD + j0 + cc] = ov[r][cc];
            g_M[mb + (size_t)(i0 + r) * 64 + j0 + cc]   = mv[r][cc];
        }
}

// ---------------- retention phase 2 ----------------------------------------
__global__ void ret_scan_k(const float* __restrict__ gammas)
{
    int idx = blockIdx.x * 256 + threadIdx.x;
    int e  = idx & 4095;
    int bh2 = idx >> 12;
    int h  = bh2 & (HH - 1);
    float gL = powf(gammas[h], (float)RL);
    float s = 0.f;
#pragma unroll
    for (int c = 0; c < RNC; c++) {
        size_t o = ((size_t)bh2 * RNC + c) * 4096 + e;
        g_Sp[o] = s;
        s = gL * s + g_M[o];
    }
}

// ---------------- retention phase 3 ----------------------------------------
__global__ __launch_bounds__(256)
void ret_p3(const float* __restrict__ gammas, float* __restrict__ out)
{
    __shared__ float Qs[64 * 64];
    __shared__ float Ssm[64 * 64];
    __shared__ float gp[65];
    int c = blockIdx.x, h = blockIdx.y, b = blockIdx.z;
    int tid = threadIdx.x, tx = tid & 15, ty = tid >> 4;
    if (tid < 65) gp[tid] = powf(gammas[h], (float)tid);
    __syncthreads();

    size_t base = ((size_t)b * SS + (size_t)c * RL) * DD + (size_t)h * HDD;
    size_t sbo  = (((size_t)(b * HH + h)) * RNC + c) * 4096;
#pragma unroll
    for (int rep = 0; rep < 4; rep++) {
        int e = rep * 1024 + tid * 4;
        int row = e >> 6, col = e & 63;
        float4 qv = *(const float4*)&g_qp[base + (size_t)row * DD + col];
        float s0 = gp[row + 1] * 0.125f;
        *(float4*)&Qs[e] = make_float4(qv.x * s0, qv.y * s0, qv.z * s0, qv.w * s0);
        *(float4*)&Ssm[e] = *(const float4*)&g_Sp[sbo + e];
    }
    __syncthreads();

    int i0 = ty << 2, d0 = tx << 2;
    float o[4][4];
#pragma unroll
    for (int r = 0; r < 4; r++)
#pragma unroll
        for (int cc = 0; cc < 4; cc++) o[r][cc] = 0.f;

#pragma unroll 4
    for (int r1 = 0; r1 < 64; r1++) {
        float qf[4], sf[4];
#pragma unroll
        for (int r = 0; r < 4; r++) qf[r] = Qs[(i0 + r) * 64 + r1];
#pragma unroll
        for (int cc = 0; cc < 4; cc++) sf[cc] = Ssm[r1 * 64 + d0 + cc];
#pragma unroll
        for (int r = 0; r < 4; r++)
#pragma unroll
            for (int cc = 0; cc < 4; cc++) o[r][cc] += qf[r] * sf[cc];
    }
#pragma unroll
    for (int r = 0; r < 4; r++)
#pragma unroll
        for (int cc = 0; cc < 4; cc++) {
            size_t oo = base + (size_t)(i0 + r) * DD + d0 + cc;
            out[oo] += o[r][cc];
        }
}

// ---------------- launch ---------------------------------------------------
extern "C" void kernel_launch(void* const* d_in, const int* in_sizes, int n_in,
                              void* d_out, int out_size)
{
    const float* q      = (const float*)d_in[0];
    const float* k      = (const float*)d_in[1];
    const float* v      = (const float*)d_in[2];
    const float* W_in   = (const float*)d_in[3];
    const float* b_in   = (const float*)d_in[4];
    const float* W_gate = (const float*)d_in[5];
    const float* b_gate = (const float*)d_in[6];
    const float* W_out  = (const float*)d_in[7];
    const float* b_out  = (const float*)d_in[8];
    const float* gammas = (const float*)d_in[9];
    float* out = (float*)d_out;

    void *pu, *pa, *pqp;
    void *pxh, *pxl, *phh, *phl;
    void *pw1h, *pw1l, *pw2h, *pw2l, *pw3h, *pw3l;
    cudaGetSymbolAddress(&pu,  g_u);
    cudaGetSymbolAddress(&pa,  g_a);
    cudaGetSymbolAddress(&pqp, g_qp);
    cudaGetSymbolAddress(&pxh, g_Xhi);  cudaGetSymbolAddress(&pxl, g_Xlo);
    cudaGetSymbolAddress(&phh, g_Hhi);  cudaGetSymbolAddress(&phl, g_Hlo);
    cudaGetSymbolAddress(&pw1h, g_W1h); cudaGetSymbolAddress(&pw1l, g_W1l);
    cudaGetSymbolAddress(&pw2h, g_W2h); cudaGetSymbolAddress(&pw2l, g_W2l);
    cudaGetSymbolAddress(&pw3h, g_W3h); cudaGetSymbolAddress(&pw3l, g_W3l);

    cudaFuncSetAttribute(gemm_mma<1>, cudaFuncAttributeMaxDynamicSharedMemorySize, SMEM_DUAL);
    cudaFuncSetAttribute(gemm_mma<0>, cudaFuncAttributeMaxDynamicSharedMemorySize, SMEM_SINGLE);
    const int P1_SMEM = (4096 + 64 * 65 + 4096 + 65) * 4;
    cudaFuncSetAttribute(ret_p1, cudaFuncAttributeMaxDynamicSharedMemorySize, P1_SMEM);

    // one-time splits: q -> Xhi/Xlo ; W -> Wt hi/lo
    conv_x_k<<<(MM * DD / 4) / 256, 256>>>(q, (__nv_bfloat16*)pxh, (__nv_bfloat16*)pxl);
    conv_w_k<<<dim3(32, 32), 256>>>(W_in,   (__nv_bfloat16*)pw1h, (__nv_bfloat16*)pw1l);
    conv_w_k<<<dim3(32, 32), 256>>>(W_gate, (__nv_bfloat16*)pw2h, (__nv_bfloat16*)pw2l);
    conv_w_k<<<dim3(32, 32), 256>>>(W_out,  (__nv_bfloat16*)pw3h, (__nv_bfloat16*)pw3l);

    dim3 gg(8, 32);

    // u = q@W_in + b_in ; a = sigmoid(q@W_gate + b_gate)
    gemm_mma<1><<<gg, 512, SMEM_DUAL>>>(
        (const __nv_bfloat16*)pxh, (const __nv_bfloat16*)pxl,
        (const __nv_bfloat16*)pw1h, (const __nv_bfloat16*)pw1l,
        (const __nv_bfloat16*)pw2h, (const __nv_bfloat16*)pw2l,
        b_in, b_gate, (float*)pu, (float*)pa);

    // gated scan h_t = a_t h_{t-1} + u_t  (emits bf16 hi/lo h)
    scan_chunk_k <<<dim3(SNC, BB), 256>>>();
    scan_prefix_k<<<BB, 256>>>();
    scan_apply_k <<<dim3(SNC, BB), 256>>>();

    // q_proj = h@W_out + b_out
    gemm_mma<0><<<gg, 512, SMEM_SINGLE>>>(
        (const __nv_bfloat16*)phh, (const __nv_bfloat16*)phl,
        (const __nv_bfloat16*)pw3h, (const __nv_bfloat16*)pw3l,
        nullptr, nullptr, b_out, nullptr, (float*)pqp, nullptr);

    // retention
    ret_p1<<<dim3(RNC, HH, BB), 256, P1_SMEM>>>(k, v, gammas, out);
    ret_scan_k<<<(BB * HH * HDD * HDD) / 256, 256>>>(gammas);
    ret_p3<<<dim3(RNC, HH, BB), 256>>>(gammas, out);
}

// round 5
// speedup vs baseline: 2.4129x; 1.1018x over previous
#include <cuda_runtime.h>
#include <cuda_bf16.h>
#include <math.h>
#include <stdint.h>

#define BB  2
#define SS  2048
#define DD  1024
#define HH  16
#define HDD 64
#define MM  (BB*SS)
#define SCL 16            // scan chunk length
#define SNC (SS/SCL)      // 128 scan chunks
#define RL  64            // retention chunk length
#define RNC (SS/RL)       // 32 retention chunks

// ---------------- scratch ---------------------------------------------------
__device__ float g_u [BB*SS*DD];
__device__ float g_a [BB*SS*DD];
__device__ float g_qp[BB*SS*DD];
__device__ float g_Ac[BB*SNC*DD];
__device__ float g_Uc[BB*SNC*DD];
__device__ float g_P [BB*SNC*DD];
__device__ float g_M [BB*HH*RNC*HDD*HDD];
__device__ float g_Sp[BB*HH*RNC*HDD*HDD];

__device__ __nv_bfloat16 g_Xhi[MM*DD], g_Xlo[MM*DD];
__device__ __nv_bfloat16 g_Hhi[MM*DD], g_Hlo[MM*DD];
__device__ __nv_bfloat16 g_W1h[DD*DD], g_W1l[DD*DD];
__device__ __nv_bfloat16 g_W2h[DD*DD], g_W2l[DD*DD];
__device__ __nv_bfloat16 g_W3h[DD*DD], g_W3l[DD*DD];

// ---------------- helpers ---------------------------------------------------
__device__ __forceinline__ uint32_t smem_u32(const void* p) {
    uint32_t a;
    asm("{ .reg .u64 t; cvta.to.shared.u64 t, %1; cvt.u32.u64 %0, t; }"
        : "=r"(a) : "l"(p));
    return a;
}
#define SW(o) ((o) ^ ((((uint32_t)(o)) >> 3) & 0x70))

#define CP_ASYNC16(dst, src) \
    asm volatile("cp.async.cg.shared.global [%0], [%1], 16;" :: "r"(dst), "l"(src))
#define CP_COMMIT() asm volatile("cp.async.commit_group;" ::: "memory")
#define CP_WAIT1()  asm volatile("cp.async.wait_group 1;" ::: "memory")
#define CP_WAIT0()  asm volatile("cp.async.wait_group 0;" ::: "memory")

__device__ __forceinline__ void ldsm_x4(uint32_t addr, uint32_t* r) {
    asm volatile("ldmatrix.sync.aligned.m8n8.x4.shared.b16 {%0,%1,%2,%3}, [%4];"
                 : "=r"(r[0]), "=r"(r[1]), "=r"(r[2]), "=r"(r[3]) : "r"(addr));
}
__device__ __forceinline__ void ldsm_x2(uint32_t addr, uint32_t* r) {
    asm volatile("ldmatrix.sync.aligned.m8n8.x2.shared.b16 {%0,%1}, [%2];"
                 : "=r"(r[0]), "=r"(r[1]) : "r"(addr));
}
__device__ __forceinline__ void ldsm_x4_t(uint32_t addr, uint32_t* r) {
    asm volatile("ldmatrix.sync.aligned.m8n8.x4.trans.shared.b16 {%0,%1,%2,%3}, [%4];"
                 : "=r"(r[0]), "=r"(r[1]), "=r"(r[2]), "=r"(r[3]) : "r"(addr));
}
__device__ __forceinline__ void ldsm_x2_t(uint32_t addr, uint32_t* r) {
    asm volatile("ldmatrix.sync.aligned.m8n8.x2.trans.shared.b16 {%0,%1}, [%2];"
                 : "=r"(r[0]), "=r"(r[1]) : "r"(addr));
}
__device__ __forceinline__ void mma_bf16(float* d, const uint32_t* a, const uint32_t* b) {
    asm volatile("mma.sync.aligned.m16n8k16.row.col.f32.bf16.bf16.f32 "
                 "{%0,%1,%2,%3}, {%4,%5,%6,%7}, {%8,%9}, {%0,%1,%2,%3};"
                 : "+f"(d[0]), "+f"(d[1]), "+f"(d[2]), "+f"(d[3])
                 : "r"(a[0]), "r"(a[1]), "r"(a[2]), "r"(a[3]), "r"(b[0]), "r"(b[1]));
}
__device__ __forceinline__ void split2(float x, float y, uint32_t& hi, uint32_t& lo) {
    __nv_bfloat16 hx = __float2bfloat16(x), hy = __float2bfloat16(y);
    float rx = x - __bfloat162float(hx);
    float ry = y - __bfloat162float(hy);
    __nv_bfloat16 lx = __float2bfloat16(rx), ly = __float2bfloat16(ry);
    hi = ((uint32_t)__bfloat16_as_ushort(hy) << 16) | (uint32_t)__bfloat16_as_ushort(hx);
    lo = ((uint32_t)__bfloat16_as_ushort(ly) << 16) | (uint32_t)__bfloat16_as_ushort(lx);
}

// ---------------- conversion kernels ---------------------------------------
__global__ __launch_bounds__(256)
void conv_x_k(const float* __restrict__ X, __nv_bfloat16* __restrict__ hi,
              __nv_bfloat16* __restrict__ lo)
{
    int i = blockIdx.x * 256 + threadIdx.x;
    float4 v = ((const float4*)X)[i];
    uint32_t h01, l01, h23, l23;
    split2(v.x, v.y, h01, l01);
    split2(v.z, v.w, h23, l23);
    ((uint2*)hi)[i] = make_uint2(h01, h23);
    ((uint2*)lo)[i] = make_uint2(l01, l23);
}

// W[k][n] f32 -> Wt[n][k] bf16 hi/lo (transpose + split), 3 matrices in one grid
__global__ __launch_bounds__(256)
void conv_w3_k(const float* __restrict__ Wa, const float* __restrict__ Wb,
               const float* __restrict__ Wc,
               __nv_bfloat16* __restrict__ ha, __nv_bfloat16* __restrict__ la,
               __nv_bfloat16* __restrict__ hb, __nv_bfloat16* __restrict__ lb,
               __nv_bfloat16* __restrict__ hc, __nv_bfloat16* __restrict__ lc)
{
    __shared__ float t[32][33];
    int z = blockIdx.z;
    const float* W = (z == 0) ? Wa : (z == 1) ? Wb : Wc;
    __nv_bfloat16* hi = (z == 0) ? ha : (z == 1) ? hb : hc;
    __nv_bfloat16* lo = (z == 0) ? la : (z == 1) ? lb : lc;
    int n0 = blockIdx.x * 32, k0 = blockIdx.y * 32;
    int tx = threadIdx.x & 31, ty = threadIdx.x >> 5;
#pragma unroll
    for (int r = 0; r < 4; r++)
        t[ty * 4 + r][tx] = W[(size_t)(k0 + ty * 4 + r) * DD + n0 + tx];
    __syncthreads();
#pragma unroll
    for (int r = 0; r < 4; r++) {
        int n = ty * 4 + r;
        float v = t[tx][n];
        __nv_bfloat16 hv = __float2bfloat16(v);
        float rv = v - __bfloat162float(hv);
        size_t o = (size_t)(n0 + n) * DD + k0 + tx;
        hi[o] = hv;
        lo[o] = __float2bfloat16(rv);
    }
}

// ---------------- mma.sync GEMM with cp.async pipeline ---------------------
template<int DUAL>
__global__ __launch_bounds__(512)
void gemm_mma(const __nv_bfloat16* __restrict__ Ahi_g, const __nv_bfloat16* __restrict__ Alo_g,
              const __nv_bfloat16* __restrict__ B1h_g, const __nv_bfloat16* __restrict__ B1l_g,
              const __nv_bfloat16* __restrict__ B2h_g, const __nv_bfloat16* __restrict__ B2l_g,
              const float* __restrict__ b1, const float* __restrict__ b2,
              float* __restrict__ O1, float* __restrict__ O2)
{
    extern __shared__ char sm[];
    const uint32_t sb = smem_u32(sm);
    const int NT = DUAL ? 6 : 4;
    const uint32_t STAGE = NT * 16384u;
    const int tid = threadIdx.x, wid = tid >> 5, lane = tid & 31;
    const int m0 = blockIdx.y * 128, n0 = blockIdx.x * 128;
    const int wrow = (wid >> 2) * 32, wcol = (wid & 3) * 32;

    const char* srcs[6];
    srcs[0] = (const char*)Ahi_g + (size_t)m0 * 2048;
    srcs[1] = (const char*)Alo_g + (size_t)m0 * 2048;
    srcs[2] = (const char*)B1h_g + (size_t)n0 * 2048;
    srcs[3] = (const char*)B1l_g + (size_t)n0 * 2048;
    if (DUAL) {
        srcs[4] = (const char*)B2h_g + (size_t)n0 * 2048;
        srcs[5] = (const char*)B2l_g + (size_t)n0 * 2048;
    }

    float acc1[2][4][4];
    float acc2[2][4][4];
#pragma unroll
    for (int mt = 0; mt < 2; mt++)
#pragma unroll
        for (int nt = 0; nt < 4; nt++)
#pragma unroll
            for (int c = 0; c < 4; c++) { acc1[mt][nt][c] = 0.f; acc2[mt][nt][c] = 0.f; }

    const int aq = lane >> 3, ar = lane & 7;
    const int br = lane & 7, bhh = (lane >> 3) & 1;

    auto load_stage = [&](int s, int kc) {
        uint32_t sbase = sb + (uint32_t)s * STAGE;
#pragma unroll
        for (int t = 0; t < NT; t++) {
            const char* gp = srcs[t] + (size_t)kc * 128;
#pragma unroll
            for (int rep = 0; rep < 2; rep++) {
                int i = rep * 512 + tid;
                int row = i >> 3, c16 = (i & 7) * 16;
                uint32_t so = sbase + t * 16384u + SW(row * 128 + c16);
                CP_ASYNC16(so, gp + (size_t)row * 2048 + c16);
            }
        }
        CP_COMMIT();
    };

    load_stage(0, 0);

    for (int kc = 0; kc < 16; kc++) {
        if (kc + 1 < 16) load_stage((kc + 1) & 1, kc + 1);
        else CP_COMMIT();
        CP_WAIT1();
        __syncthreads();

        uint32_t stb = sb + (uint32_t)(kc & 1) * STAGE;
#pragma unroll
        for (int ks = 0; ks < 4; ks++) {
            int k0 = ks * 16;
            uint32_t aHI[2][4], aLO[2][4];
#pragma unroll
            for (int mt = 0; mt < 2; mt++) {
                int m = wrow + mt * 16 + (aq & 1) * 8 + ar;
                int k = k0 + (aq >> 1) * 8;
                uint32_t off = SW(m * 128 + k * 2);
                ldsm_x4(stb + off, aHI[mt]);
                ldsm_x4(stb + 16384u + off, aLO[mt]);
            }
            uint32_t bH[4][2], bL[4][2];
#pragma unroll
            for (int nt = 0; nt < 4; nt++) {
                int n = wcol + nt * 8 + br;
                int k = k0 + bhh * 8;
                uint32_t off = SW(n * 128 + k * 2);
                ldsm_x2(stb + 32768u + off, bH[nt]);
                ldsm_x2(stb + 49152u + off, bL[nt]);
            }
#pragma unroll
            for (int mt = 0; mt < 2; mt++)
#pragma unroll
                for (int nt = 0; nt < 4; nt++) {
                    mma_bf16(acc1[mt][nt], aHI[mt], bH[nt]);
                    mma_bf16(acc1[mt][nt], aHI[mt], bL[nt]);
                    mma_bf16(acc1[mt][nt], aLO[mt], bH[nt]);
                }
            if (DUAL) {
#pragma unroll
                for (int nt = 0; nt < 4; nt++) {
                    int n = wcol + nt * 8 + br;
                    int k = k0 + bhh * 8;
                    uint32_t off = SW(n * 128 + k * 2);
                    ldsm_x2(stb + 65536u + off, bH[nt]);
                    ldsm_x2(stb + 81920u + off, bL[nt]);
                }
#pragma unroll
                for (int mt = 0; mt < 2; mt++)
#pragma unroll
                    for (int nt = 0; nt < 4; nt++) {
                        mma_bf16(acc2[mt][nt], aHI[mt], bH[nt]);
                        mma_bf16(acc2[mt][nt], aHI[mt], bL[nt]);
                        mma_bf16(acc2[mt][nt], aLO[mt], bH[nt]);
                    }
            }
        }
        __syncthreads();
    }
    CP_WAIT0();

#pragma unroll
    for (int nt = 0; nt < 4; nt++) {
        int n = n0 + wcol + nt * 8 + (lane & 3) * 2;
        float bv0 = __ldg(&b1[n]), bv1 = __ldg(&b1[n + 1]);
        float gv0 = 0.f, gv1 = 0.f;
        if (DUAL) { gv0 = __ldg(&b2[n]); gv1 = __ldg(&b2[n + 1]); }
#pragma unroll
        for (int mt = 0; mt < 2; mt++) {
            int m = m0 + wrow + mt * 16 + (lane >> 2);
            float2 v0 = make_float2(acc1[mt][nt][0] + bv0, acc1[mt][nt][1] + bv1);
            float2 v1 = make_float2(acc1[mt][nt][2] + bv0, acc1[mt][nt][3] + bv1);
            *(float2*)&O1[(size_t)m * 1024 + n]       = v0;
            *(float2*)&O1[(size_t)(m + 8) * 1024 + n] = v1;
            if (DUAL) {
                float2 s0, s1;
                s0.x = 1.f / (1.f + expf(-(acc2[mt][nt][0] + gv0)));
                s0.y = 1.f / (1.f + expf(-(acc2[mt][nt][1] + gv1)));
                s1.x = 1.f / (1.f + expf(-(acc2[mt][nt][2] + gv0)));
                s1.y = 1.f / (1.f + expf(-(acc2[mt][nt][3] + gv1)));
                *(float2*)&O2[(size_t)m * 1024 + n]       = s0;
                *(float2*)&O2[(size_t)(m + 8) * 1024 + n] = s1;
            }
        }
    }
}
#define SMEM_DUAL   (2u * 6u * 16384u)
#define SMEM_SINGLE (2u * 4u * 16384u)

// ---------------- gated scan (float4, 3-phase, chunk=16) -------------------
__global__ void scan_chunk_k()
{
    int d4 = threadIdx.x;
    int c = blockIdx.x, b = blockIdx.y;
    const float4* af = (const float4*)g_a;
    const float4* uf = (const float4*)g_u;
    size_t base = ((size_t)b * SS + (size_t)c * SCL) * 256 + d4;
    float4 A = make_float4(1.f, 1.f, 1.f, 1.f);
    float4 U = make_float4(0.f, 0.f, 0.f, 0.f);
#pragma unroll
    for (int j = 0; j < SCL; j++) {
        float4 av = af[base + (size_t)j * 256];
        float4 uv = uf[base + (size_t)j * 256];
        U.x = av.x * U.x + uv.x; U.y = av.y * U.y + uv.y;
        U.z = av.z * U.z + uv.z; U.w = av.w * U.w + uv.w;
        A.x *= av.x; A.y *= av.y; A.z *= av.z; A.w *= av.w;
    }
    size_t o = ((size_t)b * SNC + c) * 256 + d4;
    ((float4*)g_Ac)[o] = A;
    ((float4*)g_Uc)[o] = U;
}

__global__ void scan_prefix_k()
{
    int d4 = threadIdx.x;
    int b = blockIdx.x;
    float4 h = make_float4(0.f, 0.f, 0.f, 0.f);
#pragma unroll 8
    for (int c = 0; c < SNC; c++) {
        size_t o = ((size_t)b * SNC + c) * 256 + d4;
        ((float4*)g_P)[o] = h;
        float4 A = ((const float4*)g_Ac)[o];
        float4 U = ((const float4*)g_Uc)[o];
        h.x = A.x * h.x + U.x; h.y = A.y * h.y + U.y;
        h.z = A.z * h.z + U.z; h.w = A.w * h.w + U.w;
    }
}

__global__ void scan_apply_k()
{
    int d4 = threadIdx.x;
    int c = blockIdx.x, b = blockIdx.y;
    float4 h = ((const float4*)g_P)[((size_t)b * SNC + c) * 256 + d4];
    const float4* af = (const float4*)g_a;
    const float4* uf = (const float4*)g_u;
    uint2* hh = (uint2*)g_Hhi;
    uint2* hl = (uint2*)g_Hlo;
    size_t base = ((size_t)b * SS + (size_t)c * SCL) * 256 + d4;
#pragma unroll
    for (int j = 0; j < SCL; j++) {
        float4 av = af[base + (size_t)j * 256];
        float4 uv = uf[base + (size_t)j * 256];
        h.x = av.x * h.x + uv.x; h.y = av.y * h.y + uv.y;
        h.z = av.z * h.z + uv.z; h.w = av.w * h.w + uv.w;
        uint32_t h01, l01, h23, l23;
        split2(h.x, h.y, h01, l01);
        split2(h.z, h.w, h23, l23);
        hh[base + (size_t)j * 256] = make_uint2(h01, h23);
        hl[base + (size_t)j * 256] = make_uint2(l01, l23);
    }
}

// ---------------- retention phase 1 (tensor cores) --------------------------
// 128 threads = 4 warps; warp w owns output rows 16w..16w+15.
// smem: QH 0, QL 8K, KH 16K, KL 24K, WH 32K, WL 40K, VH 48K, VL 56K, gp 64K
#define P1_QH 0u
#define P1_QL 8192u
#define P1_KH 16384u
#define P1_KL 24576u
#define P1_WH 32768u
#define P1_WL 40960u
#define P1_VH 49152u
#define P1_VL 57344u
#define P1_GP 65536u
#define P1_SMEM (P1_GP + 272u)

__global__ __launch_bounds__(128)
void ret_p1(const float* __restrict__ kin, const float* __restrict__ vin,
            const float* __restrict__ gammas, float* __restrict__ out)
{
    extern __shared__ char sm[];
    const uint32_t sb = smem_u32(sm);
    float* gps = (float*)(sm + P1_GP);

    int c = blockIdx.x, h = blockIdx.y, b = blockIdx.z;
    int tid = threadIdx.x, wid = tid >> 5, lane = tid & 31;

    if (tid < 65) gps[tid] = powf(gammas[h], (float)tid);
    __syncthreads();

    size_t base = ((size_t)b * SS + (size_t)c * RL) * DD + (size_t)h * HDD;
    // load + split: Q (x0.125), K, Kw = K*gp[63-j], V
#pragma unroll
    for (int it = 0; it < 8; it++) {
        int i = it * 128 + tid;
        int row = i >> 4, c4 = (i & 15) << 2;
        size_t ga = base + (size_t)row * DD + c4;
        uint32_t off = SW(row * 128 + c4 * 2);
        uint32_t h01, l01, h23, l23;

        float4 qv = *(const float4*)&g_qp[ga];
        split2(qv.x * 0.125f, qv.y * 0.125f, h01, l01);
        split2(qv.z * 0.125f, qv.w * 0.125f, h23, l23);
        *(uint2*)(sm + P1_QH + off) = make_uint2(h01, h23);
        *(uint2*)(sm + P1_QL + off) = make_uint2(l01, l23);

        float4 kv = *(const float4*)&kin[ga];
        split2(kv.x, kv.y, h01, l01);
        split2(kv.z, kv.w, h23, l23);
        *(uint2*)(sm + P1_KH + off) = make_uint2(h01, h23);
        *(uint2*)(sm + P1_KL + off) = make_uint2(l01, l23);

        float w = gps[63 - row];
        split2(kv.x * w, kv.y * w, h01, l01);
        split2(kv.z * w, kv.w * w, h23, l23);
        *(uint2*)(sm + P1_WH + off) = make_uint2(h01, h23);
        *(uint2*)(sm + P1_WL + off) = make_uint2(l01, l23);

        float4 vv = *(const float4*)&vin[ga];
        split2(vv.x, vv.y, h01, l01);
        split2(vv.z, vv.w, h23, l23);
        *(uint2*)(sm + P1_VH + off) = make_uint2(h01, h23);
        *(uint2*)(sm + P1_VL + off) = make_uint2(l01, l23);
    }
    __syncthreads();

    const int R = wid * 16;
    const int aq = lane >> 3, ar = lane & 7;
    const int br = lane & 7, bhh = (lane >> 3) & 1;
    const int l2 = lane & 15;
    const int lg = lane >> 3, lr = lane & 7;   // for x4 trans groups

    // ---- S = (Q/8) Kt : c[nb][4] ----
    float c_[8][4];
#pragma unroll
    for (int nb = 0; nb < 8; nb++)
#pragma unroll
        for (int r = 0; r < 4; r++) c_[nb][r] = 0.f;

#pragma unroll
    for (int ks = 0; ks < 4; ks++) {
        int k0 = ks * 16;
        uint32_t aH[4], aL[4];
        {
            int m = R + (aq & 1) * 8 + ar;
            int k = k0 + (aq >> 1) * 8;
            uint32_t off = SW(m * 128 + k * 2);
            ldsm_x4(sb + P1_QH + off, aH);
            ldsm_x4(sb + P1_QL + off, aL);
        }
#pragma unroll
        for (int nb = 0; nb < 8; nb++) {
            int n = nb * 8 + br;
            int k = k0 + bhh * 8;
            uint32_t off = SW(n * 128 + k * 2);
            uint32_t bH[2], bL[2];
            ldsm_x2(sb + P1_KH + off, bH);
            ldsm_x2(sb + P1_KL + off, bL);
            mma_bf16(c_[nb], aH, bH);
            mma_bf16(c_[nb], aH, bL);
            mma_bf16(c_[nb], aL, bH);
        }
    }

    // ---- decay mask: P = S * gamma^(i-j), i>=j ----
    const int rb = R + (lane >> 2);
    const int cb = (lane & 3) * 2;
#pragma unroll
    for (int nb = 0; nb < 8; nb++) {
        int col0 = nb * 8 + cb;
        c_[nb][0] *= (rb >= col0)         ? gps[rb - col0]         : 0.f;
        c_[nb][1] *= (rb >= col0 + 1)     ? gps[rb - col0 - 1]     : 0.f;
        c_[nb][2] *= (rb + 8 >= col0)     ? gps[rb + 8 - col0]     : 0.f;
        c_[nb][3] *= (rb + 8 >= col0 + 1) ? gps[rb + 8 - col0 - 1] : 0.f;
    }

    // ---- O = P V  and  M = Kw^T V ----
    float oc[8][4], mc[8][4];
#pragma unroll
    for (int nb = 0; nb < 8; nb++)
#pragma unroll
        for (int r = 0; r < 4; r++) { oc[nb][r] = 0.f; mc[nb][r] = 0.f; }

#pragma unroll
    for (int kk = 0; kk < 4; kk++) {
        int k0 = kk * 16;
        // A from P (register reuse identity)
        uint32_t aPh[4], aPl[4];
        split2(c_[2 * kk][0],     c_[2 * kk][1],     aPh[0], aPl[0]);
        split2(c_[2 * kk][2],     c_[2 * kk][3],     aPh[1], aPl[1]);
        split2(c_[2 * kk + 1][0], c_[2 * kk + 1][1], aPh[2], aPl[2]);
        split2(c_[2 * kk + 1][2], c_[2 * kk + 1][3], aPh[3], aPl[3]);
        // A from Kw^T via ldsm.x4.trans: group g: row = k0 + (g&2)*4 + lr, col = R + (g&1)*8
        uint32_t aKh[4], aKl[4];
        {
            int jrow = k0 + ((lg & 2) ? 8 : 0) + lr;
            int mcol = R + ((lg & 1) ? 8 : 0);
            uint32_t off = SW(jrow * 128 + mcol * 2);
            ldsm_x4_t(sb + P1_WH + off, aKh);
            ldsm_x4_t(sb + P1_WL + off, aKl);
        }
#pragma unroll
        for (int nb = 0; nb < 8; nb++) {
            int n = nb * 8;
            int jrow = k0 + l2;
            uint32_t off = SW(jrow * 128 + n * 2);
            uint32_t bH[2], bL[2];
            ldsm_x2_t(sb + P1_VH + off, bH);
            ldsm_x2_t(sb + P1_VL + off, bL);
            mma_bf16(oc[nb], aPh, bH);
            mma_bf16(oc[nb], aPh, bL);
            mma_bf16(oc[nb], aPl, bH);
            mma_bf16(mc[nb], aKh, bH);
            mma_bf16(mc[nb], aKh, bL);
            mma_bf16(mc[nb], aKl, bH);
        }
    }

    // ---- write O (overwrite out) and M ----
    size_t mb = (((size_t)(b * HH + h)) * RNC + c) * 4096;
#pragma unroll
    for (int nb = 0; nb < 8; nb++) {
        int col = nb * 8 + cb;
        *(float2*)&out[base + (size_t)rb * DD + col]       = make_float2(oc[nb][0], oc[nb][1]);
        *(float2*)&out[base + (size_t)(rb + 8) * DD + col] = make_float2(oc[nb][2], oc[nb][3]);
        *(float2*)&g_M[mb + (size_t)rb * 64 + col]         = make_float2(mc[nb][0], mc[nb][1]);
        *(float2*)&g_M[mb + (size_t)(rb + 8) * 64 + col]   = make_float2(mc[nb][2], mc[nb][3]);
    }
}

// ---------------- retention phase 2 ----------------------------------------
__global__ void ret_scan_k(const float* __restrict__ gammas)
{
    int idx = blockIdx.x * 256 + threadIdx.x;
    int e  = idx & 4095;
    int bh2 = idx >> 12;
    int h  = bh2 & (HH - 1);
    float gL = powf(gammas[h], (float)RL);
    float s = 0.f;
#pragma unroll
    for (int c = 0; c < RNC; c++) {
        size_t o = ((size_t)bh2 * RNC + c) * 4096 + e;
        g_Sp[o] = s;
        s = gL * s + g_M[o];
    }
}

// ---------------- retention phase 3 (tensor cores) --------------------------
// out += (gamma^{i+1} q_i / 8) @ Sp_c ; 128 threads, 4 warps.
__global__ __launch_bounds__(128)
void ret_p3(const float* __restrict__ gammas, float* __restrict__ out)
{
    __shared__ char sm[33536];
    const uint32_t sb = smem_u32(sm);
    const uint32_t QH = 0, QL = 8192, SH = 16384, SL = 24576;
    float* gps = (float*)(sm + 32768);

    int c = blockIdx.x, h = blockIdx.y, b = blockIdx.z;
    int tid = threadIdx.x, wid = tid >> 5, lane = tid & 31;

    if (tid < 65) gps[tid] = powf(gammas[h], (float)tid);
    __syncthreads();

    size_t base = ((size_t)b * SS + (size_t)c * RL) * DD + (size_t)h * HDD;
    size_t sbo  = (((size_t)(b * HH + h)) * RNC + c) * 4096;
#pragma unroll
    for (int it = 0; it < 8; it++) {
        int i = it * 128 + tid;
        int row = i >> 4, c4 = (i & 15) << 2;
        uint32_t off = SW(row * 128 + c4 * 2);
        uint32_t h01, l01, h23, l23;

        float4 qv = *(const float4*)&g_qp[base + (size_t)row * DD + c4];
        float s0 = gps[row + 1] * 0.125f;
        split2(qv.x * s0, qv.y * s0, h01, l01);
        split2(qv.z * s0, qv.w * s0, h23, l23);
        *(uint2*)(sm + QH + off) = make_uint2(h01, h23);
        *(uint2*)(sm + QL + off) = make_uint2(l01, l23);

        float4 sv = *(const float4*)&g_Sp[sbo + (size_t)row * 64 + c4];
        split2(sv.x, sv.y, h01, l01);
        split2(sv.z, sv.w, h23, l23);
        *(uint2*)(sm + SH + off) = make_uint2(h01, h23);
        *(uint2*)(sm + SL + off) = make_uint2(l01, l23);
    }
    __syncthreads();

    const int R = wid * 16;
    const int aq = lane >> 3, ar = lane & 7;
    const int l2 = lane & 15;

    float oc[8][4];
#pragma unroll
    for (int nb = 0; nb < 8; nb++)
#pragma unroll
        for (int r = 0; r < 4; r++) oc[nb][r] = 0.f;

#pragma unroll
    for (int ks = 0; ks < 4; ks++) {
        int k0 = ks * 16;
        uint32_t aH[4], aL[4];
        {
            int m = R + (aq & 1) * 8 + ar;
            int k = k0 + (aq >> 1) * 8;
            uint32_t off = SW(m * 128 + k * 2);
            ldsm_x4(sb + QH + off, aH);
            ldsm_x4(sb + QL + off, aL);
        }
#pragma unroll
        for (int nb = 0; nb < 8; nb++) {
            int n = nb * 8;
            int krow = k0 + l2;                 // Sp storage row = d1 = k
            uint32_t off = SW(krow * 128 + n * 2);
            uint32_t bH[2], bL[2];
            ldsm_x2_t(sb + SH + off, bH);
            ldsm_x2_t(sb + SL + off, bL);
            mma_bf16(oc[nb], aH, bH);
            mma_bf16(oc[nb], aH, bL);
            mma_bf16(oc[nb], aL, bH);
        }
    }

    const int rb = R + (lane >> 2);
    const int cb = (lane & 3) * 2;
#pragma unroll
    for (int nb = 0; nb < 8; nb++) {
        int col = nb * 8 + cb;
        size_t o0 = base + (size_t)rb * DD + col;
        size_t o1 = base + (size_t)(rb + 8) * DD + col;
        float2 v0 = *(float2*)&out[o0];
        float2 v1 = *(float2*)&out[o1];
        v0.x += oc[nb][0]; v0.y += oc[nb][1];
        v1.x += oc[nb][2]; v1.y += oc[nb][3];
        *(float2*)&out[o0] = v0;
        *(float2*)&out[o1] = v1;
    }
}

// ---------------- launch ---------------------------------------------------
extern "C" void kernel_launch(void* const* d_in, const int* in_sizes, int n_in,
                              void* d_out, int out_size)
{
    const float* q      = (const float*)d_in[0];
    const float* k      = (const float*)d_in[1];
    const float* v      = (const float*)d_in[2];
    const float* W_in   = (const float*)d_in[3];
    const float* b_in   = (const float*)d_in[4];
    const float* W_gate = (const float*)d_in[5];
    const float* b_gate = (const float*)d_in[6];
    const float* W_out  = (const float*)d_in[7];
    const float* b_out  = (const float*)d_in[8];
    const float* gammas = (const float*)d_in[9];
    float* out = (float*)d_out;

    void *pu, *pa, *pqp;
    void *pxh, *pxl, *phh, *phl;
    void *pw1h, *pw1l, *pw2h, *pw2l, *pw3h, *pw3l;
    cudaGetSymbolAddress(&pu,  g_u);
    cudaGetSymbolAddress(&pa,  g_a);
    cudaGetSymbolAddress(&pqp, g_qp);
    cudaGetSymbolAddress(&pxh, g_Xhi);  cudaGetSymbolAddress(&pxl, g_Xlo);
    cudaGetSymbolAddress(&phh, g_Hhi);  cudaGetSymbolAddress(&phl, g_Hlo);
    cudaGetSymbolAddress(&pw1h, g_W1h); cudaGetSymbolAddress(&pw1l, g_W1l);
    cudaGetSymbolAddress(&pw2h, g_W2h); cudaGetSymbolAddress(&pw2l, g_W2l);
    cudaGetSymbolAddress(&pw3h, g_W3h); cudaGetSymbolAddress(&pw3l, g_W3l);

    cudaFuncSetAttribute(gemm_mma<1>, cudaFuncAttributeMaxDynamicSharedMemorySize, SMEM_DUAL);
    cudaFuncSetAttribute(gemm_mma<0>, cudaFuncAttributeMaxDynamicSharedMemorySize, SMEM_SINGLE);
    cudaFuncSetAttribute(ret_p1, cudaFuncAttributeMaxDynamicSharedMemorySize, P1_SMEM);

    conv_x_k<<<(MM * DD / 4) / 256, 256>>>(q, (__nv_bfloat16*)pxh, (__nv_bfloat16*)pxl);
    conv_w3_k<<<dim3(32, 32, 3), 256>>>(W_in, W_gate, W_out,
        (__nv_bfloat16*)pw1h, (__nv_bfloat16*)pw1l,
        (__nv_bfloat16*)pw2h, (__nv_bfloat16*)pw2l,
        (__nv_bfloat16*)pw3h, (__nv_bfloat16*)pw3l);

    dim3 gg(8, 32);

    gemm_mma<1><<<gg, 512, SMEM_DUAL>>>(
        (const __nv_bfloat16*)pxh, (const __nv_bfloat16*)pxl,
        (const __nv_bfloat16*)pw1h, (const __nv_bfloat16*)pw1l,
        (const __nv_bfloat16*)pw2h, (const __nv_bfloat16*)pw2l,
        b_in, b_gate, (float*)pu, (float*)pa);

    scan_chunk_k <<<dim3(SNC, BB), 256>>>();
    scan_prefix_k<<<BB, 256>>>();
    scan_apply_k <<<dim3(SNC, BB), 256>>>();

    gemm_mma<0><<<gg, 512, SMEM_SINGLE>>>(
        (const __nv_bfloat16*)phh, (const __nv_bfloat16*)phl,
        (const __nv_bfloat16*)pw3h, (const __nv_bfloat16*)pw3l,
        nullptr, nullptr, b_out, nullptr, (float*)pqp, nullptr);

    ret_p1<<<dim3(RNC, HH, BB), 128, P1_SMEM>>>(k, v, gammas, out);
    ret_scan_k<<<(BB * HH * HDD * HDD) / 256, 256>>>(gammas);
    ret_p3<<<dim3(RNC, HH, BB), 128>>>(gammas, out);
}

// round 6
// speedup vs baseline: 2.7186x; 1.1267x over previous
#include <cuda_runtime.h>
#include <cuda_fp16.h>
#include <math.h>
#include <stdint.h>

#define BB  2
#define SS  2048
#define DD  1024
#define HH  16
#define HDD 64
#define MM  (BB*SS)
#define SCL 8             // scan chunk length
#define SNC (SS/SCL)      // 256 scan chunks
#define RL  64            // retention chunk length
#define RNC (SS/RL)       // 32 retention chunks

// ---------------- scratch ---------------------------------------------------
__device__ float g_u [BB*SS*DD];
__device__ float g_a [BB*SS*DD];
__device__ float g_qp[BB*SS*DD];
__device__ float g_Ac[BB*SNC*DD];
__device__ float g_Uc[BB*SNC*DD];
__device__ float g_P [BB*SNC*DD];
__device__ float g_M [BB*HH*RNC*HDD*HDD];
__device__ float g_Sp[BB*HH*RNC*HDD*HDD];

__device__ __half g_Xhi[MM*DD], g_Xlo[MM*DD];   // q split (fp16)
__device__ __half g_Hhi[MM*DD], g_Hlo[MM*DD];   // h split (fp16)
__device__ __half g_W1[DD*DD];                  // W_in^T fp16
__device__ __half g_W2[DD*DD];                  // W_gate^T fp16
__device__ __half g_W3[DD*DD];                  // W_out^T fp16

// ---------------- helpers ---------------------------------------------------
__device__ __forceinline__ uint32_t smem_u32(const void* p) {
    uint32_t a;
    asm("{ .reg .u64 t; cvta.to.shared.u64 t, %1; cvt.u32.u64 %0, t; }"
        : "=r"(a) : "l"(p));
    return a;
}
#define SW(o) ((o) ^ ((((uint32_t)(o)) >> 3) & 0x70))

#define CP_ASYNC16(dst, src) \
    asm volatile("cp.async.cg.shared.global [%0], [%1], 16;" :: "r"(dst), "l"(src))
#define CP_COMMIT() asm volatile("cp.async.commit_group;" ::: "memory")
#define CP_WAIT1()  asm volatile("cp.async.wait_group 1;" ::: "memory")
#define CP_WAIT0()  asm volatile("cp.async.wait_group 0;" ::: "memory")

__device__ __forceinline__ void ldsm_x4(uint32_t addr, uint32_t* r) {
    asm volatile("ldmatrix.sync.aligned.m8n8.x4.shared.b16 {%0,%1,%2,%3}, [%4];"
                 : "=r"(r[0]), "=r"(r[1]), "=r"(r[2]), "=r"(r[3]) : "r"(addr));
}
__device__ __forceinline__ void ldsm_x2(uint32_t addr, uint32_t* r) {
    asm volatile("ldmatrix.sync.aligned.m8n8.x2.shared.b16 {%0,%1}, [%2];"
                 : "=r"(r[0]), "=r"(r[1]) : "r"(addr));
}
__device__ __forceinline__ void ldsm_x4_t(uint32_t addr, uint32_t* r) {
    asm volatile("ldmatrix.sync.aligned.m8n8.x4.trans.shared.b16 {%0,%1,%2,%3}, [%4];"
                 : "=r"(r[0]), "=r"(r[1]), "=r"(r[2]), "=r"(r[3]) : "r"(addr));
}
__device__ __forceinline__ void ldsm_x2_t(uint32_t addr, uint32_t* r) {
    asm volatile("ldmatrix.sync.aligned.m8n8.x2.trans.shared.b16 {%0,%1}, [%2];"
                 : "=r"(r[0]), "=r"(r[1]) : "r"(addr));
}
__device__ __forceinline__ void mma_f16(float* d, const uint32_t* a, const uint32_t* b) {
    asm volatile("mma.sync.aligned.m16n8k16.row.col.f32.f16.f16.f32 "
                 "{%0,%1,%2,%3}, {%4,%5,%6,%7}, {%8,%9}, {%0,%1,%2,%3};"
                 : "+f"(d[0]), "+f"(d[1]), "+f"(d[2]), "+f"(d[3])
                 : "r"(a[0]), "r"(a[1]), "r"(a[2]), "r"(a[3]), "r"(b[0]), "r"(b[1]));
}
__device__ __forceinline__ uint32_t pack2h(float x, float y) {
    uint32_t r;
    asm("cvt.rn.f16x2.f32 %0, %1, %2;" : "=r"(r) : "f"(y), "f"(x));
    return r;
}
__device__ __forceinline__ void split2h(float x, float y, uint32_t& hi, uint32_t& lo) {
    hi = pack2h(x, y);
    __half2 hv = *(__half2*)&hi;
    float rx = x - __low2float(hv);
    float ry = y - __high2float(hv);
    lo = pack2h(rx, ry);
}

// ---------------- conversion kernels ---------------------------------------
__global__ __launch_bounds__(256)
void conv_x_k(const float* __restrict__ X, __half* __restrict__ hi,
              __half* __restrict__ lo)
{
    int i = blockIdx.x * 256 + threadIdx.x;
    float4 v = ((const float4*)X)[i];
    uint32_t h01, l01, h23, l23;
    split2h(v.x, v.y, h01, l01);
    split2h(v.z, v.w, h23, l23);
    ((uint2*)hi)[i] = make_uint2(h01, h23);
    ((uint2*)lo)[i] = make_uint2(l01, l23);
}

// W[k][n] f32 -> Wt[n][k] fp16, 3 matrices in one grid
__global__ __launch_bounds__(256)
void conv_w3_k(const float* __restrict__ Wa, const float* __restrict__ Wb,
               const float* __restrict__ Wc,
               __half* __restrict__ oa, __half* __restrict__ ob,
               __half* __restrict__ oc)
{
    __shared__ float t[32][33];
    int z = blockIdx.z;
    const float* W = (z == 0) ? Wa : (z == 1) ? Wb : Wc;
    __half* o = (z == 0) ? oa : (z == 1) ? ob : oc;
    int n0 = blockIdx.x * 32, k0 = blockIdx.y * 32;
    int tx = threadIdx.x & 31, ty = threadIdx.x >> 5;
#pragma unroll
    for (int r = 0; r < 4; r++)
        t[ty * 4 + r][tx] = W[(size_t)(k0 + ty * 4 + r) * DD + n0 + tx];
    __syncthreads();
#pragma unroll
    for (int r = 0; r < 4; r++) {
        int n = ty * 4 + r;
        o[(size_t)(n0 + n) * DD + k0 + tx] = __float2half_rn(t[tx][n]);
    }
}

// ---------------- mma.sync GEMM with cp.async pipeline ---------------------
// tiles per K-chunk: AHI, ALO, B1[, B2]; each 128 rows x 64 fp16 (128 B/row)
template<int DUAL>
__global__ __launch_bounds__(512)
void gemm_mma(const __half* __restrict__ Ahi_g, const __half* __restrict__ Alo_g,
              const __half* __restrict__ B1_g, const __half* __restrict__ B2_g,
              const float* __restrict__ b1, const float* __restrict__ b2,
              float* __restrict__ O1, float* __restrict__ O2)
{
    extern __shared__ char sm[];
    const uint32_t sb = smem_u32(sm);
    const int NT = DUAL ? 4 : 3;
    const uint32_t STAGE = NT * 16384u;
    const int tid = threadIdx.x, wid = tid >> 5, lane = tid & 31;
    const int m0 = blockIdx.y * 128, n0 = blockIdx.x * 128;
    const int wrow = (wid >> 2) * 32, wcol = (wid & 3) * 32;

    const char* srcs[4];
    srcs[0] = (const char*)Ahi_g + (size_t)m0 * 2048;
    srcs[1] = (const char*)Alo_g + (size_t)m0 * 2048;
    srcs[2] = (const char*)B1_g + (size_t)n0 * 2048;
    if (DUAL) srcs[3] = (const char*)B2_g + (size_t)n0 * 2048;

    float acc1[2][4][4];
    float acc2[2][4][4];
#pragma unroll
    for (int mt = 0; mt < 2; mt++)
#pragma unroll
        for (int nt = 0; nt < 4; nt++)
#pragma unroll
            for (int c = 0; c < 4; c++) { acc1[mt][nt][c] = 0.f; acc2[mt][nt][c] = 0.f; }

    const int aq = lane >> 3, ar = lane & 7;
    const int br = lane & 7, bhh = (lane >> 3) & 1;

    auto load_stage = [&](int s, int kc) {
        uint32_t sbase = sb + (uint32_t)s * STAGE;
#pragma unroll
        for (int t = 0; t < NT; t++) {
            const char* gp = srcs[t] + (size_t)kc * 128;
#pragma unroll
            for (int rep = 0; rep < 2; rep++) {
                int i = rep * 512 + tid;
                int row = i >> 3, c16 = (i & 7) * 16;
                uint32_t so = sbase + t * 16384u + SW(row * 128 + c16);
                CP_ASYNC16(so, gp + (size_t)row * 2048 + c16);
            }
        }
        CP_COMMIT();
    };

    load_stage(0, 0);

    for (int kc = 0; kc < 16; kc++) {
        if (kc + 1 < 16) load_stage((kc + 1) & 1, kc + 1);
        else CP_COMMIT();
        CP_WAIT1();
        __syncthreads();

        uint32_t stb = sb + (uint32_t)(kc & 1) * STAGE;
#pragma unroll
        for (int ks = 0; ks < 4; ks++) {
            int k0 = ks * 16;
            uint32_t aHI[2][4], aLO[2][4];
#pragma unroll
            for (int mt = 0; mt < 2; mt++) {
                int m = wrow + mt * 16 + (aq & 1) * 8 + ar;
                int k = k0 + (aq >> 1) * 8;
                uint32_t off = SW(m * 128 + k * 2);
                ldsm_x4(stb + off, aHI[mt]);
                ldsm_x4(stb + 16384u + off, aLO[mt]);
            }
            uint32_t bF[4][2];
#pragma unroll
            for (int nt = 0; nt < 4; nt++) {
                int n = wcol + nt * 8 + br;
                int k = k0 + bhh * 8;
                uint32_t off = SW(n * 128 + k * 2);
                ldsm_x2(stb + 32768u + off, bF[nt]);
            }
#pragma unroll
            for (int mt = 0; mt < 2; mt++)
#pragma unroll
                for (int nt = 0; nt < 4; nt++) {
                    mma_f16(acc1[mt][nt], aHI[mt], bF[nt]);
                    mma_f16(acc1[mt][nt], aLO[mt], bF[nt]);
                }
            if (DUAL) {
#pragma unroll
                for (int nt = 0; nt < 4; nt++) {
                    int n = wcol + nt * 8 + br;
                    int k = k0 + bhh * 8;
                    uint32_t off = SW(n * 128 + k * 2);
                    ldsm_x2(stb + 49152u + off, bF[nt]);
                }
#pragma unroll
                for (int mt = 0; mt < 2; mt++)
#pragma unroll
                    for (int nt = 0; nt < 4; nt++) {
                        mma_f16(acc2[mt][nt], aHI[mt], bF[nt]);
                        mma_f16(acc2[mt][nt], aLO[mt], bF[nt]);
                    }
            }
        }
        __syncthreads();
    }
    CP_WAIT0();

#pragma unroll
    for (int nt = 0; nt < 4; nt++) {
        int n = n0 + wcol + nt * 8 + (lane & 3) * 2;
        float bv0 = __ldg(&b1[n]), bv1 = __ldg(&b1[n + 1]);
        float gv0 = 0.f, gv1 = 0.f;
        if (DUAL) { gv0 = __ldg(&b2[n]); gv1 = __ldg(&b2[n + 1]); }
#pragma unroll
        for (int mt = 0; mt < 2; mt++) {
            int m = m0 + wrow + mt * 16 + (lane >> 2);
            float2 v0 = make_float2(acc1[mt][nt][0] + bv0, acc1[mt][nt][1] + bv1);
            float2 v1 = make_float2(acc1[mt][nt][2] + bv0, acc1[mt][nt][3] + bv1);
            *(float2*)&O1[(size_t)m * 1024 + n]       = v0;
            *(float2*)&O1[(size_t)(m + 8) * 1024 + n] = v1;
            if (DUAL) {
                float2 s0, s1;
                s0.x = 1.f / (1.f + expf(-(acc2[mt][nt][0] + gv0)));
                s0.y = 1.f / (1.f + expf(-(acc2[mt][nt][1] + gv1)));
                s1.x = 1.f / (1.f + expf(-(acc2[mt][nt][2] + gv0)));
                s1.y = 1.f / (1.f + expf(-(acc2[mt][nt][3] + gv1)));
                *(float2*)&O2[(size_t)m * 1024 + n]       = s0;
                *(float2*)&O2[(size_t)(m + 8) * 1024 + n] = s1;
            }
        }
    }
}
#define SMEM_DUAL   (2u * 4u * 16384u)   // 131072
#define SMEM_SINGLE (2u * 3u * 16384u)   // 98304

// ---------------- gated scan (float4, 3-phase, chunk=8) --------------------
__global__ void scan_chunk_k()
{
    int d4 = threadIdx.x;
    int c = blockIdx.x, b = blockIdx.y;
    const float4* af = (const float4*)g_a;
    const float4* uf = (const float4*)g_u;
    size_t base = ((size_t)b * SS + (size_t)c * SCL) * 256 + d4;
    float4 A = make_float4(1.f, 1.f, 1.f, 1.f);
    float4 U = make_float4(0.f, 0.f, 0.f, 0.f);
#pragma unroll
    for (int j = 0; j < SCL; j++) {
        float4 av = af[base + (size_t)j * 256];
        float4 uv = uf[base + (size_t)j * 256];
        U.x = av.x * U.x + uv.x; U.y = av.y * U.y + uv.y;
        U.z = av.z * U.z + uv.z; U.w = av.w * U.w + uv.w;
        A.x *= av.x; A.y *= av.y; A.z *= av.z; A.w *= av.w;
    }
    size_t o = ((size_t)b * SNC + c) * 256 + d4;
    ((float4*)g_Ac)[o] = A;
    ((float4*)g_Uc)[o] = U;
}

__global__ void scan_prefix_k()
{
    int d4 = threadIdx.x;
    int b = blockIdx.x;
    float4 h = make_float4(0.f, 0.f, 0.f, 0.f);
#pragma unroll 8
    for (int c = 0; c < SNC; c++) {
        size_t o = ((size_t)b * SNC + c) * 256 + d4;
        ((float4*)g_P)[o] = h;
        float4 A = ((const float4*)g_Ac)[o];
        float4 U = ((const float4*)g_Uc)[o];
        h.x = A.x * h.x + U.x; h.y = A.y * h.y + U.y;
        h.z = A.z * h.z + U.z; h.w = A.w * h.w + U.w;
    }
}

__global__ void scan_apply_k()
{
    int d4 = threadIdx.x;
    int c = blockIdx.x, b = blockIdx.y;
    float4 h = ((const float4*)g_P)[((size_t)b * SNC + c) * 256 + d4];
    const float4* af = (const float4*)g_a;
    const float4* uf = (const float4*)g_u;
    uint2* hh = (uint2*)g_Hhi;
    uint2* hl = (uint2*)g_Hlo;
    size_t base = ((size_t)b * SS + (size_t)c * SCL) * 256 + d4;
#pragma unroll
    for (int j = 0; j < SCL; j++) {
        float4 av = af[base + (size_t)j * 256];
        float4 uv = uf[base + (size_t)j * 256];
        h.x = av.x * h.x + uv.x; h.y = av.y * h.y + uv.y;
        h.z = av.z * h.z + uv.z; h.w = av.w * h.w + uv.w;
        uint32_t h01, l01, h23, l23;
        split2h(h.x, h.y, h01, l01);
        split2h(h.z, h.w, h23, l23);
        hh[base + (size_t)j * 256] = make_uint2(h01, h23);
        hl[base + (size_t)j * 256] = make_uint2(l01, l23);
    }
}

// ---------------- retention phase 1 (tensor cores, fp16) --------------------
// smem: QH 0, QL 8K, KS 16K, WS 24K, VS 32K, gp 40K
#define P1_QH 0u
#define P1_QL 8192u
#define P1_KS 16384u
#define P1_WS 24576u
#define P1_VS 32768u
#define P1_GP 40960u

__global__ __launch_bounds__(128)
void ret_p1(const float* __restrict__ kin, const float* __restrict__ vin,
            const float* __restrict__ gammas, float* __restrict__ out)
{
    __shared__ __align__(128) char sm[41232];
    const uint32_t sb = smem_u32(sm);
    float* gps = (float*)(sm + P1_GP);

    int c = blockIdx.x, h = blockIdx.y, b = blockIdx.z;
    int tid = threadIdx.x, wid = tid >> 5, lane = tid & 31;

    if (tid < 65) gps[tid] = powf(gammas[h], (float)tid);
    __syncthreads();

    size_t base = ((size_t)b * SS + (size_t)c * RL) * DD + (size_t)h * HDD;
#pragma unroll
    for (int it = 0; it < 8; it++) {
        int i = it * 128 + tid;
        int row = i >> 4, c4 = (i & 15) << 2;
        size_t ga = base + (size_t)row * DD + c4;
        uint32_t off = SW(row * 128 + c4 * 2);
        uint32_t h01, l01, h23, l23;

        float4 qv = *(const float4*)&g_qp[ga];
        split2h(qv.x * 0.125f, qv.y * 0.125f, h01, l01);
        split2h(qv.z * 0.125f, qv.w * 0.125f, h23, l23);
        *(uint2*)(sm + P1_QH + off) = make_uint2(h01, h23);
        *(uint2*)(sm + P1_QL + off) = make_uint2(l01, l23);

        float4 kv = *(const float4*)&kin[ga];
        *(uint2*)(sm + P1_KS + off) = make_uint2(pack2h(kv.x, kv.y), pack2h(kv.z, kv.w));
        float w = gps[63 - row];
        *(uint2*)(sm + P1_WS + off) =
            make_uint2(pack2h(kv.x * w, kv.y * w), pack2h(kv.z * w, kv.w * w));

        float4 vv = *(const float4*)&vin[ga];
        *(uint2*)(sm + P1_VS + off) = make_uint2(pack2h(vv.x, vv.y), pack2h(vv.z, vv.w));
    }
    __syncthreads();

    const int R = wid * 16;
    const int aq = lane >> 3, ar = lane & 7;
    const int br = lane & 7, bhh = (lane >> 3) & 1;
    const int l2 = lane & 15;
    const int lg = lane >> 3, lr = lane & 7;

    // ---- S = (Q/8) K^T ----
    float c_[8][4];
#pragma unroll
    for (int nb = 0; nb < 8; nb++)
#pragma unroll
        for (int r = 0; r < 4; r++) c_[nb][r] = 0.f;

#pragma unroll
    for (int ks = 0; ks < 4; ks++) {
        int k0 = ks * 16;
        uint32_t aH[4], aL[4];
        {
            int m = R + (aq & 1) * 8 + ar;
            int k = k0 + (aq >> 1) * 8;
            uint32_t off = SW(m * 128 + k * 2);
            ldsm_x4(sb + P1_QH + off, aH);
            ldsm_x4(sb + P1_QL + off, aL);
        }
#pragma unroll
        for (int nb = 0; nb < 8; nb++) {
            int n = nb * 8 + br;
            int k = k0 + bhh * 8;
            uint32_t off = SW(n * 128 + k * 2);
            uint32_t bK[2];
            ldsm_x2(sb + P1_KS + off, bK);
            mma_f16(c_[nb], aH, bK);
            mma_f16(c_[nb], aL, bK);
        }
    }

    // ---- decay mask ----
    const int rb = R + (lane >> 2);
    const int cb = (lane & 3) * 2;
#pragma unroll
    for (int nb = 0; nb < 8; nb++) {
        int col0 = nb * 8 + cb;
        c_[nb][0] *= (rb >= col0)         ? gps[rb - col0]         : 0.f;
        c_[nb][1] *= (rb >= col0 + 1)     ? gps[rb - col0 - 1]     : 0.f;
        c_[nb][2] *= (rb + 8 >= col0)     ? gps[rb + 8 - col0]     : 0.f;
        c_[nb][3] *= (rb + 8 >= col0 + 1) ? gps[rb + 8 - col0 - 1] : 0.f;
    }

    // ---- O = P V  and  M = Kw^T V ----
    float oc[8][4], mc[8][4];
#pragma unroll
    for (int nb = 0; nb < 8; nb++)
#pragma unroll
        for (int r = 0; r < 4; r++) { oc[nb][r] = 0.f; mc[nb][r] = 0.f; }

#pragma unroll
    for (int kk = 0; kk < 4; kk++) {
        int k0 = kk * 16;
        uint32_t aPh[4], aPl[4];
        split2h(c_[2 * kk][0],     c_[2 * kk][1],     aPh[0], aPl[0]);
        split2h(c_[2 * kk][2],     c_[2 * kk][3],     aPh[1], aPl[1]);
        split2h(c_[2 * kk + 1][0], c_[2 * kk + 1][1], aPh[2], aPl[2]);
        split2h(c_[2 * kk + 1][2], c_[2 * kk + 1][3], aPh[3], aPl[3]);
        uint32_t aK[4];
        {
            int jrow = k0 + ((lg & 2) ? 8 : 0) + lr;
            int mcol = R + ((lg & 1) ? 8 : 0);
            uint32_t off = SW(jrow * 128 + mcol * 2);
            ldsm_x4_t(sb + P1_WS + off, aK);
        }
#pragma unroll
        for (int nb = 0; nb < 8; nb++) {
            int n = nb * 8;
            int jrow = k0 + l2;
            uint32_t off = SW(jrow * 128 + n * 2);
            uint32_t bV[2];
            ldsm_x2_t(sb + P1_VS + off, bV);
            mma_f16(oc[nb], aPh, bV);
            mma_f16(oc[nb], aPl, bV);
            mma_f16(mc[nb], aK, bV);
        }
    }

    size_t mb = (((size_t)(b * HH + h)) * RNC + c) * 4096;
#pragma unroll
    for (int nb = 0; nb < 8; nb++) {
        int col = nb * 8 + cb;
        *(float2*)&out[base + (size_t)rb * DD + col]       = make_float2(oc[nb][0], oc[nb][1]);
        *(float2*)&out[base + (size_t)(rb + 8) * DD + col] = make_float2(oc[nb][2], oc[nb][3]);
        *(float2*)&g_M[mb + (size_t)rb * 64 + col]         = make_float2(mc[nb][0], mc[nb][1]);
        *(float2*)&g_M[mb + (size_t)(rb + 8) * 64 + col]   = make_float2(mc[nb][2], mc[nb][3]);
    }
}

// ---------------- retention phase 2 ----------------------------------------
__global__ void ret_scan_k(const float* __restrict__ gammas)
{
    int idx = blockIdx.x * 256 + threadIdx.x;
    int e  = idx & 4095;
    int bh2 = idx >> 12;
    int h  = bh2 & (HH - 1);
    float gL = powf(gammas[h], (float)RL);
    float s = 0.f;
#pragma unroll
    for (int c = 0; c < RNC; c++) {
        size_t o = ((size_t)bh2 * RNC + c) * 4096 + e;
        g_Sp[o] = s;
        s = gL * s + g_M[o];
    }
}

// ---------------- retention phase 3 (tensor cores, fp16) --------------------
__global__ __launch_bounds__(128)
void ret_p3(const float* __restrict__ gammas, float* __restrict__ out)
{
    __shared__ __align__(128) char sm[24848];
    const uint32_t sb = smem_u32(sm);
    const uint32_t QH = 0, QL = 8192, SH = 16384;
    float* gps = (float*)(sm + 24576);

    int c = blockIdx.x, h = blockIdx.y, b = blockIdx.z;
    int tid = threadIdx.x, wid = tid >> 5, lane = tid & 31;

    if (tid < 65) gps[tid] = powf(gammas[h], (float)tid);
    __syncthreads();

    size_t base = ((size_t)b * SS + (size_t)c * RL) * DD + (size_t)h * HDD;
    size_t sbo  = (((size_t)(b * HH + h)) * RNC + c) * 4096;
#pragma unroll
    for (int it = 0; it < 8; it++) {
        int i = it * 128 + tid;
        int row = i >> 4, c4 = (i & 15) << 2;
        uint32_t off = SW(row * 128 + c4 * 2);
        uint32_t h01, l01, h23, l23;

        float4 qv = *(const float4*)&g_qp[base + (size_t)row * DD + c4];
        float s0 = gps[row + 1] * 0.125f;
        split2h(qv.x * s0, qv.y * s0, h01, l01);
        split2h(qv.z * s0, qv.w * s0, h23, l23);
        *(uint2*)(sm + QH + off) = make_uint2(h01, h23);
        *(uint2*)(sm + QL + off) = make_uint2(l01, l23);

        float4 sv = *(const float4*)&g_Sp[sbo + (size_t)row * 64 + c4];
        *(uint2*)(sm + SH + off) = make_uint2(pack2h(sv.x, sv.y), pack2h(sv.z, sv.w));
    }
    __syncthreads();

    const int R = wid * 16;
    const int aq = lane >> 3, ar = lane & 7;
    const int l2 = lane & 15;

    float oc[8][4];
#pragma unroll
    for (int nb = 0; nb < 8; nb++)
#pragma unroll
        for (int r = 0; r < 4; r++) oc[nb][r] = 0.f;

#pragma unroll
    for (int ks = 0; ks < 4; ks++) {
        int k0 = ks * 16;
        uint32_t aH[4], aL[4];
        {
            int m = R + (aq & 1) * 8 + ar;
            int k = k0 + (aq >> 1) * 8;
            uint32_t off = SW(m * 128 + k * 2);
            ldsm_x4(sb + QH + off, aH);
            ldsm_x4(sb + QL + off, aL);
        }
#pragma unroll
        for (int nb = 0; nb < 8; nb++) {
            int n = nb * 8;
            int krow = k0 + l2;
            uint32_t off = SW(krow * 128 + n * 2);
            uint32_t bS[2];
            ldsm_x2_t(sb + SH + off, bS);
            mma_f16(oc[nb], aH, bS);
            mma_f16(oc[nb], aL, bS);
        }
    }

    const int rb = R + (lane >> 2);
    const int cb = (lane & 3) * 2;
#pragma unroll
    for (int nb = 0; nb < 8; nb++) {
        int col = nb * 8 + cb;
        size_t o0 = base + (size_t)rb * DD + col;
        size_t o1 = base + (size_t)(rb + 8) * DD + col;
        float2 v0 = *(float2*)&out[o0];
        float2 v1 = *(float2*)&out[o1];
        v0.x += oc[nb][0]; v0.y += oc[nb][1];
        v1.x += oc[nb][2]; v1.y += oc[nb][3];
        *(float2*)&out[o0] = v0;
        *(float2*)&out[o1] = v1;
    }
}

// ---------------- launch ---------------------------------------------------
extern "C" void kernel_launch(void* const* d_in, const int* in_sizes, int n_in,
                              void* d_out, int out_size)
{
    const float* q      = (const float*)d_in[0];
    const float* k      = (const float*)d_in[1];
    const float* v      = (const float*)d_in[2];
    const float* W_in   = (const float*)d_in[3];
    const float* b_in   = (const float*)d_in[4];
    const float* W_gate = (const float*)d_in[5];
    const float* b_gate = (const float*)d_in[6];
    const float* W_out  = (const float*)d_in[7];
    const float* b_out  = (const float*)d_in[8];
    const float* gammas = (const float*)d_in[9];
    float* out = (float*)d_out;

    void *pu, *pa, *pqp;
    void *pxh, *pxl, *phh, *phl, *pw1, *pw2, *pw3;
    cudaGetSymbolAddress(&pu,  g_u);
    cudaGetSymbolAddress(&pa,  g_a);
    cudaGetSymbolAddress(&pqp, g_qp);
    cudaGetSymbolAddress(&pxh, g_Xhi);  cudaGetSymbolAddress(&pxl, g_Xlo);
    cudaGetSymbolAddress(&phh, g_Hhi);  cudaGetSymbolAddress(&phl, g_Hlo);
    cudaGetSymbolAddress(&pw1, g_W1);
    cudaGetSymbolAddress(&pw2, g_W2);
    cudaGetSymbolAddress(&pw3, g_W3);

    cudaFuncSetAttribute(gemm_mma<1>, cudaFuncAttributeMaxDynamicSharedMemorySize, SMEM_DUAL);
    cudaFuncSetAttribute(gemm_mma<0>, cudaFuncAttributeMaxDynamicSharedMemorySize, SMEM_SINGLE);

    conv_x_k<<<(MM * DD / 4) / 256, 256>>>(q, (__half*)pxh, (__half*)pxl);
    conv_w3_k<<<dim3(32, 32, 3), 256>>>(W_in, W_gate, W_out,
        (__half*)pw1, (__half*)pw2, (__half*)pw3);

    dim3 gg(8, 32);

    gemm_mma<1><<<gg, 512, SMEM_DUAL>>>(
        (const __half*)pxh, (const __half*)pxl,
        (const __half*)pw1, (const __half*)pw2,
        b_in, b_gate, (float*)pu, (float*)pa);

    scan_chunk_k <<<dim3(SNC, BB), 256>>>();
    scan_prefix_k<<<BB, 256>>>();
    scan_apply_k <<<dim3(SNC, BB), 256>>>();

    gemm_mma<0><<<gg, 512, SMEM_SINGLE>>>(
        (const __half*)phh, (const __half*)phl,
        (const __half*)pw3, nullptr,
        b_out, nullptr, (float*)pqp, nullptr);

    ret_p1<<<dim3(RNC, HH, BB), 128>>>(k, v, gammas, out);
    ret_scan_k<<<(BB * HH * HDD * HDD) / 256, 256>>>(gammas);
    ret_p3<<<dim3(RNC, HH, BB), 128>>>(gammas, out);
}

// round 7
// speedup vs baseline: 3.5844x; 1.3185x over previous
#include <cuda_runtime.h>
#include <cuda_fp16.h>
#include <math.h>
#include <stdint.h>

#define BB  2
#define SS  2048
#define DD  1024
#define HH  16
#define HDD 64
#define MM  (BB*SS)
#define SCL 16            // scan chunk length
#define SNC (SS/SCL)      // 128 scan chunks
#define RL  64            // retention chunk length
#define RNC (SS/RL)       // 32 retention chunks

// ---------------- scratch ---------------------------------------------------
__device__ __half g_uh[MM*DD];                  // u (fp16)
__device__ __half g_ah[MM*DD];                  // a (fp16)
__device__ float g_qp[BB*SS*DD];
__device__ float g_Ac[BB*SNC*DD];
__device__ float g_Uc[BB*SNC*DD];
__device__ float g_P [BB*SNC*DD];
__device__ float g_M [BB*HH*RNC*HDD*HDD];
__device__ float g_Sp[BB*HH*RNC*HDD*HDD];

__device__ __half g_Xhi[MM*DD], g_Xlo[MM*DD];   // q split (fp16)
__device__ __half g_Hhi[MM*DD], g_Hlo[MM*DD];   // h split (fp16)
__device__ __half g_W1[DD*DD];                  // W_in^T fp16
__device__ __half g_W2[DD*DD];                  // W_gate^T fp16
__device__ __half g_W3[DD*DD];                  // W_out^T fp16

// ---------------- helpers ---------------------------------------------------
__device__ __forceinline__ uint32_t smem_u32(const void* p) {
    uint32_t a;
    asm("{ .reg .u64 t; cvta.to.shared.u64 t, %1; cvt.u32.u64 %0, t; }"
        : "=r"(a) : "l"(p));
    return a;
}
#define SW(o) ((o) ^ ((((uint32_t)(o)) >> 3) & 0x70))

#define CP_ASYNC16(dst, src) \
    asm volatile("cp.async.cg.shared.global [%0], [%1], 16;" :: "r"(dst), "l"(src))
#define CP_COMMIT() asm volatile("cp.async.commit_group;" ::: "memory")
#define CP_WAIT2()  asm volatile("cp.async.wait_group 2;" ::: "memory")
#define CP_WAIT0()  asm volatile("cp.async.wait_group 0;" ::: "memory")

__device__ __forceinline__ void ldsm_x4(uint32_t addr, uint32_t* r) {
    asm volatile("ldmatrix.sync.aligned.m8n8.x4.shared.b16 {%0,%1,%2,%3}, [%4];"
                 : "=r"(r[0]), "=r"(r[1]), "=r"(r[2]), "=r"(r[3]) : "r"(addr));
}
__device__ __forceinline__ void ldsm_x2(uint32_t addr, uint32_t* r) {
    asm volatile("ldmatrix.sync.aligned.m8n8.x2.shared.b16 {%0,%1}, [%2];"
                 : "=r"(r[0]), "=r"(r[1]) : "r"(addr));
}
__device__ __forceinline__ void ldsm_x4_t(uint32_t addr, uint32_t* r) {
    asm volatile("ldmatrix.sync.aligned.m8n8.x4.trans.shared.b16 {%0,%1,%2,%3}, [%4];"
                 : "=r"(r[0]), "=r"(r[1]), "=r"(r[2]), "=r"(r[3]) : "r"(addr));
}
__device__ __forceinline__ void ldsm_x2_t(uint32_t addr, uint32_t* r) {
    asm volatile("ldmatrix.sync.aligned.m8n8.x2.trans.shared.b16 {%0,%1}, [%2];"
                 : "=r"(r[0]), "=r"(r[1]) : "r"(addr));
}
__device__ __forceinline__ void mma_f16(float* d, const uint32_t* a, const uint32_t* b) {
    asm volatile("mma.sync.aligned.m16n8k16.row.col.f32.f16.f16.f32 "
                 "{%0,%1,%2,%3}, {%4,%5,%6,%7}, {%8,%9}, {%0,%1,%2,%3};"
                 : "+f"(d[0]), "+f"(d[1]), "+f"(d[2]), "+f"(d[3])
                 : "r"(a[0]), "r"(a[1]), "r"(a[2]), "r"(a[3]), "r"(b[0]), "r"(b[1]));
}
__device__ __forceinline__ uint32_t pack2h(float x, float y) {
    uint32_t r;
    asm("cvt.rn.f16x2.f32 %0, %1, %2;" : "=r"(r) : "f"(y), "f"(x));
    return r;
}
__device__ __forceinline__ void split2h(float x, float y, uint32_t& hi, uint32_t& lo) {
    hi = pack2h(x, y);
    __half2 hv = *(__half2*)&hi;
    float rx = x - __low2float(hv);
    float ry = y - __high2float(hv);
    lo = pack2h(rx, ry);
}
__device__ __forceinline__ float2 h2f(uint32_t p) {
    return __half22float2(*(__half2*)&p);
}

// ---------------- conversion kernels ---------------------------------------
__global__ __launch_bounds__(256)
void conv_x_k(const float* __restrict__ X, __half* __restrict__ hi,
              __half* __restrict__ lo)
{
    int i = blockIdx.x * 256 + threadIdx.x;
    float4 v = ((const float4*)X)[i];
    uint32_t h01, l01, h23, l23;
    split2h(v.x, v.y, h01, l01);
    split2h(v.z, v.w, h23, l23);
    ((uint2*)hi)[i] = make_uint2(h01, h23);
    ((uint2*)lo)[i] = make_uint2(l01, l23);
}

__global__ __launch_bounds__(256)
void conv_w3_k(const float* __restrict__ Wa, const float* __restrict__ Wb,
               const float* __restrict__ Wc,
               __half* __restrict__ oa, __half* __restrict__ ob,
               __half* __restrict__ oc)
{
    __shared__ float t[32][33];
    int z = blockIdx.z;
    const float* W = (z == 0) ? Wa : (z == 1) ? Wb : Wc;
    __half* o = (z == 0) ? oa : (z == 1) ? ob : oc;
    int n0 = blockIdx.x * 32, k0 = blockIdx.y * 32;
    int tx = threadIdx.x & 31, ty = threadIdx.x >> 5;
#pragma unroll
    for (int r = 0; r < 4; r++)
        t[ty * 4 + r][tx] = W[(size_t)(k0 + ty * 4 + r) * DD + n0 + tx];
    __syncthreads();
#pragma unroll
    for (int r = 0; r < 4; r++) {
        int n = ty * 4 + r;
        o[(size_t)(n0 + n) * DD + k0 + tx] = __float2half_rn(t[tx][n]);
    }
}

// ---------------- mma.sync GEMM, 3-stage cp.async pipeline ------------------
// DUAL=1: O1/O2 are __half* (u, sigmoid->a). DUAL=0: O1 is float*.
template<int DUAL>
__global__ __launch_bounds__(512)
void gemm_mma(const __half* __restrict__ Ahi_g, const __half* __restrict__ Alo_g,
              const __half* __restrict__ B1_g, const __half* __restrict__ B2_g,
              const float* __restrict__ b1, const float* __restrict__ b2,
              void* __restrict__ O1v, void* __restrict__ O2v)
{
    extern __shared__ char sm[];
    const uint32_t sb = smem_u32(sm);
    const int NT = DUAL ? 4 : 3;
    const uint32_t STAGE = NT * 16384u;
    const int tid = threadIdx.x, wid = tid >> 5, lane = tid & 31;
    const int m0 = blockIdx.y * 128, n0 = blockIdx.x * 128;
    const int wrow = (wid >> 2) * 32, wcol = (wid & 3) * 32;

    const char* srcs[4];
    srcs[0] = (const char*)Ahi_g + (size_t)m0 * 2048;
    srcs[1] = (const char*)Alo_g + (size_t)m0 * 2048;
    srcs[2] = (const char*)B1_g + (size_t)n0 * 2048;
    if (DUAL) srcs[3] = (const char*)B2_g + (size_t)n0 * 2048;

    float acc1[2][4][4];
    float acc2[2][4][4];
#pragma unroll
    for (int mt = 0; mt < 2; mt++)
#pragma unroll
        for (int nt = 0; nt < 4; nt++)
#pragma unroll
            for (int c = 0; c < 4; c++) { acc1[mt][nt][c] = 0.f; acc2[mt][nt][c] = 0.f; }

    const int aq = lane >> 3, ar = lane & 7;
    const int br = lane & 7, bhh = (lane >> 3) & 1;

    auto load_stage = [&](int s, int kc) {
        uint32_t sbase = sb + (uint32_t)s * STAGE;
#pragma unroll
        for (int t = 0; t < NT; t++) {
            const char* gp = srcs[t] + (size_t)kc * 128;
#pragma unroll
            for (int rep = 0; rep < 2; rep++) {
                int i = rep * 512 + tid;
                int row = i >> 3, c16 = (i & 7) * 16;
                uint32_t so = sbase + t * 16384u + SW(row * 128 + c16);
                CP_ASYNC16(so, gp + (size_t)row * 2048 + c16);
            }
        }
        CP_COMMIT();
    };

    load_stage(0, 0);
    load_stage(1, 1);

    for (int kc = 0; kc < 16; kc++) {
        if (kc + 2 < 16) load_stage((kc + 2) % 3, kc + 2);
        else CP_COMMIT();
        CP_WAIT2();
        __syncthreads();

        uint32_t stb = sb + (uint32_t)(kc % 3) * STAGE;
#pragma unroll
        for (int ks = 0; ks < 4; ks++) {
            int k0 = ks * 16;
            uint32_t aHI[2][4], aLO[2][4];
#pragma unroll
            for (int mt = 0; mt < 2; mt++) {
                int m = wrow + mt * 16 + (aq & 1) * 8 + ar;
                int k = k0 + (aq >> 1) * 8;
                uint32_t off = SW(m * 128 + k * 2);
                ldsm_x4(stb + off, aHI[mt]);
                ldsm_x4(stb + 16384u + off, aLO[mt]);
            }
            uint32_t bF[4][2];
#pragma unroll
            for (int nt = 0; nt < 4; nt++) {
                int n = wcol + nt * 8 + br;
                int k = k0 + bhh * 8;
                uint32_t off = SW(n * 128 + k * 2);
                ldsm_x2(stb + 32768u + off, bF[nt]);
            }
#pragma unroll
            for (int mt = 0; mt < 2; mt++)
#pragma unroll
                for (int nt = 0; nt < 4; nt++) {
                    mma_f16(acc1[mt][nt], aHI[mt], bF[nt]);
                    mma_f16(acc1[mt][nt], aLO[mt], bF[nt]);
                }
            if (DUAL) {
#pragma unroll
                for (int nt = 0; nt < 4; nt++) {
                    int n = wcol + nt * 8 + br;
                    int k = k0 + bhh * 8;
                    uint32_t off = SW(n * 128 + k * 2);
                    ldsm_x2(stb + 49152u + off, bF[nt]);
                }
#pragma unroll
                for (int mt = 0; mt < 2; mt++)
#pragma unroll
                    for (int nt = 0; nt < 4; nt++) {
                        mma_f16(acc2[mt][nt], aHI[mt], bF[nt]);
                        mma_f16(acc2[mt][nt], aLO[mt], bF[nt]);
                    }
            }
        }
        __syncthreads();
    }
    CP_WAIT0();

#pragma unroll
    for (int nt = 0; nt < 4; nt++) {
        int n = n0 + wcol + nt * 8 + (lane & 3) * 2;
        float bv0 = __ldg(&b1[n]), bv1 = __ldg(&b1[n + 1]);
        float gv0 = 0.f, gv1 = 0.f;
        if (DUAL) { gv0 = __ldg(&b2[n]); gv1 = __ldg(&b2[n + 1]); }
#pragma unroll
        for (int mt = 0; mt < 2; mt++) {
            int m = m0 + wrow + mt * 16 + (lane >> 2);
            if (DUAL) {
                __half* U = (__half*)O1v;
                __half* A = (__half*)O2v;
                *(uint32_t*)&U[(size_t)m * 1024 + n] =
                    pack2h(acc1[mt][nt][0] + bv0, acc1[mt][nt][1] + bv1);
                *(uint32_t*)&U[(size_t)(m + 8) * 1024 + n] =
                    pack2h(acc1[mt][nt][2] + bv0, acc1[mt][nt][3] + bv1);
                float s0 = 1.f / (1.f + expf(-(acc2[mt][nt][0] + gv0)));
                float s1 = 1.f / (1.f + expf(-(acc2[mt][nt][1] + gv1)));
                float s2 = 1.f / (1.f + expf(-(acc2[mt][nt][2] + gv0)));
                float s3 = 1.f / (1.f + expf(-(acc2[mt][nt][3] + gv1)));
                *(uint32_t*)&A[(size_t)m * 1024 + n]       = pack2h(s0, s1);
                *(uint32_t*)&A[(size_t)(m + 8) * 1024 + n] = pack2h(s2, s3);
            } else {
                float* O1 = (float*)O1v;
                *(float2*)&O1[(size_t)m * 1024 + n] =
                    make_float2(acc1[mt][nt][0] + bv0, acc1[mt][nt][1] + bv1);
                *(float2*)&O1[(size_t)(m + 8) * 1024 + n] =
                    make_float2(acc1[mt][nt][2] + bv0, acc1[mt][nt][3] + bv1);
            }
        }
    }
}
#define SMEM_DUAL   (3u * 4u * 16384u)   // 196608
#define SMEM_SINGLE (3u * 3u * 16384u)   // 147456

// ---------------- gated scan (fp16 inputs, chunk=16, warp-scan prefix) -----
__global__ void scan_chunk_k()
{
    int d4 = threadIdx.x;
    int c = blockIdx.x, b = blockIdx.y;
    size_t baseh = ((size_t)b * SS + (size_t)c * SCL) * DD + d4 * 4;
    float4 A = make_float4(1.f, 1.f, 1.f, 1.f);
    float4 U = make_float4(0.f, 0.f, 0.f, 0.f);
#pragma unroll
    for (int j = 0; j < SCL; j++) {
        uint2 ar = *(const uint2*)&g_ah[baseh + (size_t)j * DD];
        uint2 ur = *(const uint2*)&g_uh[baseh + (size_t)j * DD];
        float2 a01 = h2f(ar.x), a23 = h2f(ar.y);
        float2 u01 = h2f(ur.x), u23 = h2f(ur.y);
        U.x = a01.x * U.x + u01.x; U.y = a01.y * U.y + u01.y;
        U.z = a23.x * U.z + u23.x; U.w = a23.y * U.w + u23.y;
        A.x *= a01.x; A.y *= a01.y; A.z *= a23.x; A.w *= a23.y;
    }
    size_t o = ((size_t)b * SNC + c) * 256 + d4;
    ((float4*)g_Ac)[o] = A;
    ((float4*)g_Uc)[o] = U;
}

// warp-parallel prefix over SNC=128 chunks: 1 warp per (b, float4-channel)
__global__ __launch_bounds__(256)
void scan_prefix_k()
{
    int wg = blockIdx.x * 8 + (threadIdx.x >> 5);   // 0..511
    int lane = threadIdx.x & 31;
    int b = wg >> 8;
    int d4 = wg & 255;

    size_t o0 = ((size_t)b * SNC + lane * 4) * 256 + d4;
    float4 Ac[4], Uc[4];
#pragma unroll
    for (int r = 0; r < 4; r++) {
        Ac[r] = ((const float4*)g_Ac)[o0 + (size_t)r * 256];
        Uc[r] = ((const float4*)g_Uc)[o0 + (size_t)r * 256];
    }
    // lane-local composition over 4 chunks
    float4 A = make_float4(1.f, 1.f, 1.f, 1.f);
    float4 U = make_float4(0.f, 0.f, 0.f, 0.f);
#pragma unroll
    for (int r = 0; r < 4; r++) {
        U.x = Ac[r].x * U.x + Uc[r].x; U.y = Ac[r].y * U.y + Uc[r].y;
        U.z = Ac[r].z * U.z + Uc[r].z; U.w = Ac[r].w * U.w + Uc[r].w;
        A.x *= Ac[r].x; A.y *= Ac[r].y; A.z *= Ac[r].z; A.w *= Ac[r].w;
    }
    // inclusive warp scan of (A,U) pairs
    float4 sA = A, sU = U;
#pragma unroll
    for (int d = 1; d < 32; d <<= 1) {
        float4 tA, tU;
        tA.x = __shfl_up_sync(0xffffffff, sA.x, d);
        tA.y = __shfl_up_sync(0xffffffff, sA.y, d);
        tA.z = __shfl_up_sync(0xffffffff, sA.z, d);
        tA.w = __shfl_up_sync(0xffffffff, sA.w, d);
        tU.x = __shfl_up_sync(0xffffffff, sU.x, d);
        tU.y = __shfl_up_sync(0xffffffff, sU.y, d);
        tU.z = __shfl_up_sync(0xffffffff, sU.z, d);
        tU.w = __shfl_up_sync(0xffffffff, sU.w, d);
        if (lane >= d) {
            sU.x = sA.x * tU.x + sU.x; sU.y = sA.y * tU.y + sU.y;
            sU.z = sA.z * tU.z + sU.z; sU.w = sA.w * tU.w + sU.w;
            sA.x *= tA.x; sA.y *= tA.y; sA.z *= tA.z; sA.w *= tA.w;
        }
    }
    // exclusive: shift by 1
    float4 eU;
    eU.x = __shfl_up_sync(0xffffffff, sU.x, 1);
    eU.y = __shfl_up_sync(0xffffffff, sU.y, 1);
    eU.z = __shfl_up_sync(0xffffffff, sU.z, 1);
    eU.w = __shfl_up_sync(0xffffffff, sU.w, 1);
    if (lane == 0) eU = make_float4(0.f, 0.f, 0.f, 0.f);

    // h before this lane's first chunk = eU (h0 = 0); walk 4 chunks
    float4 h = eU;
#pragma unroll
    for (int r = 0; r < 4; r++) {
        ((float4*)g_P)[o0 + (size_t)r * 256] = h;
        h.x = Ac[r].x * h.x + Uc[r].x; h.y = Ac[r].y * h.y + Uc[r].y;
        h.z = Ac[r].z * h.z + Uc[r].z; h.w = Ac[r].w * h.w + Uc[r].w;
    }
}

__global__ void scan_apply_k()
{
    int d4 = threadIdx.x;
    int c = blockIdx.x, b = blockIdx.y;
    float4 h = ((const float4*)g_P)[((size_t)b * SNC + c) * 256 + d4];
    size_t baseh = ((size_t)b * SS + (size_t)c * SCL) * DD + d4 * 4;
    uint2* hh = (uint2*)g_Hhi;
    uint2* hl = (uint2*)g_Hlo;
    size_t base4 = (((size_t)b * SS + (size_t)c * SCL) * DD) / 4 + d4;
#pragma unroll
    for (int j = 0; j < SCL; j++) {
        uint2 ar = *(const uint2*)&g_ah[baseh + (size_t)j * DD];
        uint2 ur = *(const uint2*)&g_uh[baseh + (size_t)j * DD];
        float2 a01 = h2f(ar.x), a23 = h2f(ar.y);
        float2 u01 = h2f(ur.x), u23 = h2f(ur.y);
        h.x = a01.x * h.x + u01.x; h.y = a01.y * h.y + u01.y;
        h.z = a23.x * h.z + u23.x; h.w = a23.y * h.w + u23.y;
        uint32_t h01, l01, h23, l23;
        split2h(h.x, h.y, h01, l01);
        split2h(h.z, h.w, h23, l23);
        hh[base4 + (size_t)j * 256] = make_uint2(h01, h23);
        hl[base4 + (size_t)j * 256] = make_uint2(l01, l23);
    }
}

// ---------------- retention phase 1 (tensor cores, fp16) --------------------
#define P1_QH 0u
#define P1_QL 8192u
#define P1_KS 16384u
#define P1_WS 24576u
#define P1_VS 32768u
#define P1_GP 40960u

__global__ __launch_bounds__(128)
void ret_p1(const float* __restrict__ kin, const float* __restrict__ vin,
            const float* __restrict__ gammas, float* __restrict__ out)
{
    __shared__ __align__(128) char sm[41232];
    const uint32_t sb = smem_u32(sm);
    float* gps = (float*)(sm + P1_GP);

    int c = blockIdx.x, h = blockIdx.y, b = blockIdx.z;
    int tid = threadIdx.x, wid = tid >> 5, lane = tid & 31;

    if (tid < 65) gps[tid] = powf(gammas[h], (float)tid);
    __syncthreads();

    size_t base = ((size_t)b * SS + (size_t)c * RL) * DD + (size_t)h * HDD;
#pragma unroll
    for (int it = 0; it < 8; it++) {
        int i = it * 128 + tid;
        int row = i >> 4, c4 = (i & 15) << 2;
        size_t ga = base + (size_t)row * DD + c4;
        uint32_t off = SW(row * 128 + c4 * 2);
        uint32_t h01, l01, h23, l23;

        float4 qv = *(const float4*)&g_qp[ga];
        split2h(qv.x * 0.125f, qv.y * 0.125f, h01, l01);
        split2h(qv.z * 0.125f, qv.w * 0.125f, h23, l23);
        *(uint2*)(sm + P1_QH + off) = make_uint2(h01, h23);
        *(uint2*)(sm + P1_QL + off) = make_uint2(l01, l23);

        float4 kv = *(const float4*)&kin[ga];
        *(uint2*)(sm + P1_KS + off) = make_uint2(pack2h(kv.x, kv.y), pack2h(kv.z, kv.w));
        float w = gps[63 - row];
        *(uint2*)(sm + P1_WS + off) =
            make_uint2(pack2h(kv.x * w, kv.y * w), pack2h(kv.z * w, kv.w * w));

        float4 vv = *(const float4*)&vin[ga];
        *(uint2*)(sm + P1_VS + off) = make_uint2(pack2h(vv.x, vv.y), pack2h(vv.z, vv.w));
    }
    __syncthreads();

    const int R = wid * 16;
    const int aq = lane >> 3, ar = lane & 7;
    const int br = lane & 7, bhh = (lane >> 3) & 1;
    const int l2 = lane & 15;
    const int lg = lane >> 3, lr = lane & 7;

    float c_[8][4];
#pragma unroll
    for (int nb = 0; nb < 8; nb++)
#pragma unroll
        for (int r = 0; r < 4; r++) c_[nb][r] = 0.f;

#pragma unroll
    for (int ks = 0; ks < 4; ks++) {
        int k0 = ks * 16;
        uint32_t aH[4], aL[4];
        {
            int m = R + (aq & 1) * 8 + ar;
            int k = k0 + (aq >> 1) * 8;
            uint32_t off = SW(m * 128 + k * 2);
            ldsm_x4(sb + P1_QH + off, aH);
            ldsm_x4(sb + P1_QL + off, aL);
        }
#pragma unroll
        for (int nb = 0; nb < 8; nb++) {
            int n = nb * 8 + br;
            int k = k0 + bhh * 8;
            uint32_t off = SW(n * 128 + k * 2);
            uint32_t bK[2];
            ldsm_x2(sb + P1_KS + off, bK);
            mma_f16(c_[nb], aH, bK);
            mma_f16(c_[nb], aL, bK);
        }
    }

    const int rb = R + (lane >> 2);
    const int cb = (lane & 3) * 2;
#pragma unroll
    for (int nb = 0; nb < 8; nb++) {
        int col0 = nb * 8 + cb;
        c_[nb][0] *= (rb >= col0)         ? gps[rb - col0]         : 0.f;
        c_[nb][1] *= (rb >= col0 + 1)     ? gps[rb - col0 - 1]     : 0.f;
        c_[nb][2] *= (rb + 8 >= col0)     ? gps[rb + 8 - col0]     : 0.f;
        c_[nb][3] *= (rb + 8 >= col0 + 1) ? gps[rb + 8 - col0 - 1] : 0.f;
    }

    float oc[8][4], mc[8][4];
#pragma unroll
    for (int nb = 0; nb < 8; nb++)
#pragma unroll
        for (int r = 0; r < 4; r++) { oc[nb][r] = 0.f; mc[nb][r] = 0.f; }

#pragma unroll
    for (int kk = 0; kk < 4; kk++) {
        int k0 = kk * 16;
        uint32_t aPh[4], aPl[4];
        split2h(c_[2 * kk][0],     c_[2 * kk][1],     aPh[0], aPl[0]);
        split2h(c_[2 * kk][2],     c_[2 * kk][3],     aPh[1], aPl[1]);
        split2h(c_[2 * kk + 1][0], c_[2 * kk + 1][1], aPh[2], aPl[2]);
        split2h(c_[2 * kk + 1][2], c_[2 * kk + 1][3], aPh[3], aPl[3]);
        uint32_t aK[4];
        {
            int jrow = k0 + ((lg & 2) ? 8 : 0) + lr;
            int mcol = R + ((lg & 1) ? 8 : 0);
            uint32_t off = SW(jrow * 128 + mcol * 2);
            ldsm_x4_t(sb + P1_WS + off, aK);
        }
#pragma unroll
        for (int nb = 0; nb < 8; nb++) {
            int n = nb * 8;
            int jrow = k0 + l2;
            uint32_t off = SW(jrow * 128 + n * 2);
            uint32_t bV[2];
            ldsm_x2_t(sb + P1_VS + off, bV);
            mma_f16(oc[nb], aPh, bV);
            mma_f16(oc[nb], aPl, bV);
            mma_f16(mc[nb], aK, bV);
        }
    }

    size_t mb = (((size_t)(b * HH + h)) * RNC + c) * 4096;
#pragma unroll
    for (int nb = 0; nb < 8; nb++) {
        int col = nb * 8 + cb;
        *(float2*)&out[base + (size_t)rb * DD + col]       = make_float2(oc[nb][0], oc[nb][1]);
        *(float2*)&out[base + (size_t)(rb + 8) * DD + col] = make_float2(oc[nb][2], oc[nb][3]);
        *(float2*)&g_M[mb + (size_t)rb * 64 + col]         = make_float2(mc[nb][0], mc[nb][1]);
        *(float2*)&g_M[mb + (size_t)(rb + 8) * 64 + col]   = make_float2(mc[nb][2], mc[nb][3]);
    }
}

// ---------------- retention phase 2 ----------------------------------------
__global__ void ret_scan_k(const float* __restrict__ gammas)
{
    int idx = blockIdx.x * 256 + threadIdx.x;
    int e  = idx & 4095;
    int bh2 = idx >> 12;
    int h  = bh2 & (HH - 1);
    float gL = powf(gammas[h], (float)RL);
    float s = 0.f;
#pragma unroll
    for (int c = 0; c < RNC; c++) {
        size_t o = ((size_t)bh2 * RNC + c) * 4096 + e;
        g_Sp[o] = s;
        s = gL * s + g_M[o];
    }
}

// ---------------- retention phase 3 (tensor cores, fp16) --------------------
__global__ __launch_bounds__(128)
void ret_p3(const float* __restrict__ gammas, float* __restrict__ out)
{
    __shared__ __align__(128) char sm[24848];
    const uint32_t sb = smem_u32(sm);
    const uint32_t QH = 0, QL = 8192, SH = 16384;
    float* gps = (float*)(sm + 24576);

    int c = blockIdx.x, h = blockIdx.y, b = blockIdx.z;
    int tid = threadIdx.x, wid = tid >> 5, lane = tid & 31;

    if (tid < 65) gps[tid] = powf(gammas[h], (float)tid);
    __syncthreads();

    size_t base = ((size_t)b * SS + (size_t)c * RL) * DD + (size_t)h * HDD;
    size_t sbo  = (((size_t)(b * HH + h)) * RNC + c) * 4096;
#pragma unroll
    for (int it = 0; it < 8; it++) {
        int i = it * 128 + tid;
        int row = i >> 4, c4 = (i & 15) << 2;
        uint32_t off = SW(row * 128 + c4 * 2);
        uint32_t h01, l01, h23, l23;

        float4 qv = *(const float4*)&g_qp[base + (size_t)row * DD + c4];
        float s0 = gps[row + 1] * 0.125f;
        split2h(qv.x * s0, qv.y * s0, h01, l01);
        split2h(qv.z * s0, qv.w * s0, h23, l23);
        *(uint2*)(sm + QH + off) = make_uint2(h01, h23);
        *(uint2*)(sm + QL + off) = make_uint2(l01, l23);

        float4 sv = *(const float4*)&g_Sp[sbo + (size_t)row * 64 + c4];
        *(uint2*)(sm + SH + off) = make_uint2(pack2h(sv.x, sv.y), pack2h(sv.z, sv.w));
    }
    __syncthreads();

    const int R = wid * 16;
    const int aq = lane >> 3, ar = lane & 7;
    const int l2 = lane & 15;

    float oc[8][4];
#pragma unroll
    for (int nb = 0; nb < 8; nb++)
#pragma unroll
        for (int r = 0; r < 4; r++) oc[nb][r] = 0.f;

#pragma unroll
    for (int ks = 0; ks < 4; ks++) {
        int k0 = ks * 16;
        uint32_t aH[4], aL[4];
        {
            int m = R + (aq & 1) * 8 + ar;
            int k = k0 + (aq >> 1) * 8;
            uint32_t off = SW(m * 128 + k * 2);
            ldsm_x4(sb + QH + off, aH);
            ldsm_x4(sb + QL + off, aL);
        }
#pragma unroll
        for (int nb = 0; nb < 8; nb++) {
            int n = nb * 8;
            int krow = k0 + l2;
            uint32_t off = SW(krow * 128 + n * 2);
            uint32_t bS[2];
            ldsm_x2_t(sb + SH + off, bS);
            mma_f16(oc[nb], aH, bS);
            mma_f16(oc[nb], aL, bS);
        }
    }

    const int rb = R + (lane >> 2);
    const int cb = (lane & 3) * 2;
#pragma unroll
    for (int nb = 0; nb < 8; nb++) {
        int col = nb * 8 + cb;
        size_t o0 = base + (size_t)rb * DD + col;
        size_t o1 = base + (size_t)(rb + 8) * DD + col;
        float2 v0 = *(float2*)&out[o0];
        float2 v1 = *(float2*)&out[o1];
        v0.x += oc[nb][0]; v0.y += oc[nb][1];
        v1.x += oc[nb][2]; v1.y += oc[nb][3];
        *(float2*)&out[o0] = v0;
        *(float2*)&out[o1] = v1;
    }
}

// ---------------- launch ---------------------------------------------------
extern "C" void kernel_launch(void* const* d_in, const int* in_sizes, int n_in,
                              void* d_out, int out_size)
{
    const float* q      = (const float*)d_in[0];
    const float* k      = (const float*)d_in[1];
    const float* v      = (const float*)d_in[2];
    const float* W_in   = (const float*)d_in[3];
    const float* b_in   = (const float*)d_in[4];
    const float* W_gate = (const float*)d_in[5];
    const float* b_gate = (const float*)d_in[6];
    const float* W_out  = (const float*)d_in[7];
    const float* b_out  = (const float*)d_in[8];
    const float* gammas = (const float*)d_in[9];
    float* out = (float*)d_out;

    void *puh, *pah, *pqp;
    void *pxh, *pxl, *phh, *phl, *pw1, *pw2, *pw3;
    cudaGetSymbolAddress(&puh, g_uh);
    cudaGetSymbolAddress(&pah, g_ah);
    cudaGetSymbolAddress(&pqp, g_qp);
    cudaGetSymbolAddress(&pxh, g_Xhi);  cudaGetSymbolAddress(&pxl, g_Xlo);
    cudaGetSymbolAddress(&phh, g_Hhi);  cudaGetSymbolAddress(&phl, g_Hlo);
    cudaGetSymbolAddress(&pw1, g_W1);
    cudaGetSymbolAddress(&pw2, g_W2);
    cudaGetSymbolAddress(&pw3, g_W3);

    cudaFuncSetAttribute(gemm_mma<1>, cudaFuncAttributeMaxDynamicSharedMemorySize, SMEM_DUAL);
    cudaFuncSetAttribute(gemm_mma<0>, cudaFuncAttributeMaxDynamicSharedMemorySize, SMEM_SINGLE);

    conv_x_k<<<(MM * DD / 4) / 256, 256>>>(q, (__half*)pxh, (__half*)pxl);
    conv_w3_k<<<dim3(32, 32, 3), 256>>>(W_in, W_gate, W_out,
        (__half*)pw1, (__half*)pw2, (__half*)pw3);

    dim3 gg(8, 32);

    gemm_mma<1><<<gg, 512, SMEM_DUAL>>>(
        (const __half*)pxh, (const __half*)pxl,
        (const __half*)pw1, (const __half*)pw2,
        b_in, b_gate, puh, pah);

    scan_chunk_k <<<dim3(SNC, BB), 256>>>();
    scan_prefix_k<<<(BB * 256) / 8, 256>>>();
    scan_apply_k <<<dim3(SNC, BB), 256>>>();

    gemm_mma<0><<<gg, 512, SMEM_SINGLE>>>(
        (const __half*)phh, (const __half*)phl,
        (const __half*)pw3, nullptr,
        b_out, nullptr, pqp, nullptr);

    ret_p1<<<dim3(RNC, HH, BB), 128>>>(k, v, gammas, out);
    ret_scan_k<<<(BB * HH * HDD * HDD) / 256, 256>>>(gammas);
    ret_p3<<<dim3(RNC, HH, BB), 128>>>(gammas, out);
}

// round 8
// speedup vs baseline: 3.6324x; 1.0134x over previous
#include <cuda_runtime.h>
#include <cuda_fp16.h>
#include <math.h>
#include <stdint.h>

#define BB  2
#define SS  2048
#define DD  1024
#define HH  16
#define HDD 64
#define MM  (BB*SS)
#define SCL 16            // scan chunk length
#define SNC (SS/SCL)      // 128 scan chunks
#define RL  64            // retention chunk length
#define RNC (SS/RL)       // 32 retention chunks

// ---------------- scratch ---------------------------------------------------
__device__ __half g_uh[MM*DD];                  // u (fp16)
__device__ __half g_ah[MM*DD];                  // a (fp16)
__device__ float g_Ac[BB*SNC*DD];
__device__ float g_Uc[BB*SNC*DD];
__device__ float g_P [BB*SNC*DD];
__device__ float g_M [BB*HH*RNC*HDD*HDD];
__device__ float g_Sp[BB*HH*RNC*HDD*HDD];

__device__ __half g_Xhi[MM*DD], g_Xlo[MM*DD];   // q split (fp16)
__device__ __half g_Hhi[MM*DD], g_Hlo[MM*DD];   // h split (fp16)
__device__ __half g_QPh[MM*DD], g_QPl[MM*DD];   // q_proj split (fp16)
__device__ __half g_W1[DD*DD];                  // W_in^T fp16
__device__ __half g_W2[DD*DD];                  // W_gate^T fp16
__device__ __half g_W3[DD*DD];                  // W_out^T fp16

// ---------------- helpers ---------------------------------------------------
__device__ __forceinline__ uint32_t smem_u32(const void* p) {
    uint32_t a;
    asm("{ .reg .u64 t; cvta.to.shared.u64 t, %1; cvt.u32.u64 %0, t; }"
        : "=r"(a) : "l"(p));
    return a;
}
#define SW(o) ((o) ^ ((((uint32_t)(o)) >> 3) & 0x70))

#define CP_ASYNC16(dst, src) \
    asm volatile("cp.async.cg.shared.global [%0], [%1], 16;" :: "r"(dst), "l"(src))
#define CP_COMMIT() asm volatile("cp.async.commit_group;" ::: "memory")
#define CP_WAIT2()  asm volatile("cp.async.wait_group 2;" ::: "memory")
#define CP_WAIT0()  asm volatile("cp.async.wait_group 0;" ::: "memory")

__device__ __forceinline__ void ldsm_x4(uint32_t addr, uint32_t* r) {
    asm volatile("ldmatrix.sync.aligned.m8n8.x4.shared.b16 {%0,%1,%2,%3}, [%4];"
                 : "=r"(r[0]), "=r"(r[1]), "=r"(r[2]), "=r"(r[3]) : "r"(addr));
}
__device__ __forceinline__ void ldsm_x2(uint32_t addr, uint32_t* r) {
    asm volatile("ldmatrix.sync.aligned.m8n8.x2.shared.b16 {%0,%1}, [%2];"
                 : "=r"(r[0]), "=r"(r[1]) : "r"(addr));
}
__device__ __forceinline__ void ldsm_x4_t(uint32_t addr, uint32_t* r) {
    asm volatile("ldmatrix.sync.aligned.m8n8.x4.trans.shared.b16 {%0,%1,%2,%3}, [%4];"
                 : "=r"(r[0]), "=r"(r[1]), "=r"(r[2]), "=r"(r[3]) : "r"(addr));
}
__device__ __forceinline__ void ldsm_x2_t(uint32_t addr, uint32_t* r) {
    asm volatile("ldmatrix.sync.aligned.m8n8.x2.trans.shared.b16 {%0,%1}, [%2];"
                 : "=r"(r[0]), "=r"(r[1]) : "r"(addr));
}
__device__ __forceinline__ void mma_f16(float* d, const uint32_t* a, const uint32_t* b) {
    asm volatile("mma.sync.aligned.m16n8k16.row.col.f32.f16.f16.f32 "
                 "{%0,%1,%2,%3}, {%4,%5,%6,%7}, {%8,%9}, {%0,%1,%2,%3};"
                 : "+f"(d[0]), "+f"(d[1]), "+f"(d[2]), "+f"(d[3])
                 : "r"(a[0]), "r"(a[1]), "r"(a[2]), "r"(a[3]), "r"(b[0]), "r"(b[1]));
}
__device__ __forceinline__ uint32_t pack2h(float x, float y) {
    uint32_t r;
    asm("cvt.rn.f16x2.f32 %0, %1, %2;" : "=r"(r) : "f"(y), "f"(x));
    return r;
}
__device__ __forceinline__ void split2h(float x, float y, uint32_t& hi, uint32_t& lo) {
    hi = pack2h(x, y);
    __half2 hv = *(__half2*)&hi;
    float rx = x - __low2float(hv);
    float ry = y - __high2float(hv);
    lo = pack2h(rx, ry);
}
__device__ __forceinline__ float2 h2f(uint32_t p) {
    return __half22float2(*(__half2*)&p);
}
__device__ __forceinline__ uint32_t hmul2u(uint32_t a, uint32_t s) {
    __half2 r = __hmul2(*(__half2*)&a, *(__half2*)&s);
    return *(uint32_t*)&r;
}

// ---------------- merged conversion kernel ----------------------------------
// blocks [0, 4096): q -> Xhi/Xlo (elementwise split)
// blocks [4096, 7168): W transpose+fp16, z = (bid-4096)>>10
__global__ __launch_bounds__(256)
void conv_all_k(const float* __restrict__ X,
                const float* __restrict__ Wa, const float* __restrict__ Wb,
                const float* __restrict__ Wc,
                __half* __restrict__ xhi, __half* __restrict__ xlo,
                __half* __restrict__ oa, __half* __restrict__ ob,
                __half* __restrict__ oc)
{
    __shared__ float t[32][33];
    int bid = blockIdx.x;
    if (bid < 4096) {
        int i = bid * 256 + threadIdx.x;
        float4 v = ((const float4*)X)[i];
        uint32_t h01, l01, h23, l23;
        split2h(v.x, v.y, h01, l01);
        split2h(v.z, v.w, h23, l23);
        ((uint2*)xhi)[i] = make_uint2(h01, h23);
        ((uint2*)xlo)[i] = make_uint2(l01, l23);
        return;
    }
    int r0 = bid - 4096;
    int z = r0 >> 10;
    int rr = r0 & 1023;
    const float* W = (z == 0) ? Wa : (z == 1) ? Wb : Wc;
    __half* o = (z == 0) ? oa : (z == 1) ? ob : oc;
    int n0 = (rr & 31) * 32, k0 = (rr >> 5) * 32;
    int tx = threadIdx.x & 31, ty = threadIdx.x >> 5;
#pragma unroll
    for (int r = 0; r < 4; r++)
        t[ty * 4 + r][tx] = W[(size_t)(k0 + ty * 4 + r) * DD + n0 + tx];
    __syncthreads();
#pragma unroll
    for (int r = 0; r < 4; r++) {
        int n = ty * 4 + r;
        o[(size_t)(n0 + n) * DD + k0 + tx] = __float2half_rn(t[tx][n]);
    }
}

// ---------------- mma.sync GEMM, 3-stage cp.async pipeline ------------------
// DUAL=1: O1/O2 are __half* (u, sigmoid->a). DUAL=0: O1/O2 are __half* hi/lo of q_proj.
template<int DUAL>
__global__ __launch_bounds__(512)
void gemm_mma(const __half* __restrict__ Ahi_g, const __half* __restrict__ Alo_g,
              const __half* __restrict__ B1_g, const __half* __restrict__ B2_g,
              const float* __restrict__ b1, const float* __restrict__ b2,
              void* __restrict__ O1v, void* __restrict__ O2v)
{
    extern __shared__ char sm[];
    const uint32_t sb = smem_u32(sm);
    const int NT = DUAL ? 4 : 3;
    const uint32_t STAGE = NT * 16384u;
    const int tid = threadIdx.x, wid = tid >> 5, lane = tid & 31;
    const int m0 = blockIdx.y * 128, n0 = blockIdx.x * 128;
    const int wrow = (wid >> 2) * 32, wcol = (wid & 3) * 32;

    const char* srcs[4];
    srcs[0] = (const char*)Ahi_g + (size_t)m0 * 2048;
    srcs[1] = (const char*)Alo_g + (size_t)m0 * 2048;
    srcs[2] = (const char*)B1_g + (size_t)n0 * 2048;
    if (DUAL) srcs[3] = (const char*)B2_g + (size_t)n0 * 2048;

    float acc1[2][4][4];
    float acc2[2][4][4];
#pragma unroll
    for (int mt = 0; mt < 2; mt++)
#pragma unroll
        for (int nt = 0; nt < 4; nt++)
#pragma unroll
            for (int c = 0; c < 4; c++) { acc1[mt][nt][c] = 0.f; acc2[mt][nt][c] = 0.f; }

    const int aq = lane >> 3, ar = lane & 7;
    const int br = lane & 7, bhh = (lane >> 3) & 1;

    auto load_stage = [&](int s, int kc) {
        uint32_t sbase = sb + (uint32_t)s * STAGE;
#pragma unroll
        for (int t = 0; t < NT; t++) {
            const char* gp = srcs[t] + (size_t)kc * 128;
#pragma unroll
            for (int rep = 0; rep < 2; rep++) {
                int i = rep * 512 + tid;
                int row = i >> 3, c16 = (i & 7) * 16;
                uint32_t so = sbase + t * 16384u + SW(row * 128 + c16);
                CP_ASYNC16(so, gp + (size_t)row * 2048 + c16);
            }
        }
        CP_COMMIT();
    };

    load_stage(0, 0);
    load_stage(1, 1);

    for (int kc = 0; kc < 16; kc++) {
        if (kc + 2 < 16) load_stage((kc + 2) % 3, kc + 2);
        else CP_COMMIT();
        CP_WAIT2();
        __syncthreads();

        uint32_t stb = sb + (uint32_t)(kc % 3) * STAGE;
#pragma unroll
        for (int ks = 0; ks < 4; ks++) {
            int k0 = ks * 16;
            uint32_t aHI[2][4], aLO[2][4];
#pragma unroll
            for (int mt = 0; mt < 2; mt++) {
                int m = wrow + mt * 16 + (aq & 1) * 8 + ar;
                int k = k0 + (aq >> 1) * 8;
                uint32_t off = SW(m * 128 + k * 2);
                ldsm_x4(stb + off, aHI[mt]);
                ldsm_x4(stb + 16384u + off, aLO[mt]);
            }
            uint32_t bF1[4][2], bF2[4][2];
#pragma unroll
            for (int nt = 0; nt < 4; nt++) {
                int n = wcol + nt * 8 + br;
                int k = k0 + bhh * 8;
                uint32_t off = SW(n * 128 + k * 2);
                ldsm_x2(stb + 32768u + off, bF1[nt]);
                if (DUAL) ldsm_x2(stb + 49152u + off, bF2[nt]);
            }
#pragma unroll
            for (int mt = 0; mt < 2; mt++)
#pragma unroll
                for (int nt = 0; nt < 4; nt++) {
                    mma_f16(acc1[mt][nt], aHI[mt], bF1[nt]);
                    mma_f16(acc1[mt][nt], aLO[mt], bF1[nt]);
                }
            if (DUAL) {
#pragma unroll
                for (int mt = 0; mt < 2; mt++)
#pragma unroll
                    for (int nt = 0; nt < 4; nt++) {
                        mma_f16(acc2[mt][nt], aHI[mt], bF2[nt]);
                        mma_f16(acc2[mt][nt], aLO[mt], bF2[nt]);
                    }
            }
        }
        __syncthreads();
    }
    CP_WAIT0();

#pragma unroll
    for (int nt = 0; nt < 4; nt++) {
        int n = n0 + wcol + nt * 8 + (lane & 3) * 2;
        float bv0 = __ldg(&b1[n]), bv1 = __ldg(&b1[n + 1]);
        float gv0 = 0.f, gv1 = 0.f;
        if (DUAL) { gv0 = __ldg(&b2[n]); gv1 = __ldg(&b2[n + 1]); }
#pragma unroll
        for (int mt = 0; mt < 2; mt++) {
            int m = m0 + wrow + mt * 16 + (lane >> 2);
            float v00 = acc1[mt][nt][0] + bv0, v01 = acc1[mt][nt][1] + bv1;
            float v10 = acc1[mt][nt][2] + bv0, v11 = acc1[mt][nt][3] + bv1;
            if (DUAL) {
                __half* U = (__half*)O1v;
                __half* A = (__half*)O2v;
                *(uint32_t*)&U[(size_t)m * 1024 + n]       = pack2h(v00, v01);
                *(uint32_t*)&U[(size_t)(m + 8) * 1024 + n] = pack2h(v10, v11);
                float s0 = 1.f / (1.f + expf(-(acc2[mt][nt][0] + gv0)));
                float s1 = 1.f / (1.f + expf(-(acc2[mt][nt][1] + gv1)));
                float s2 = 1.f / (1.f + expf(-(acc2[mt][nt][2] + gv0)));
                float s3 = 1.f / (1.f + expf(-(acc2[mt][nt][3] + gv1)));
                *(uint32_t*)&A[(size_t)m * 1024 + n]       = pack2h(s0, s1);
                *(uint32_t*)&A[(size_t)(m + 8) * 1024 + n] = pack2h(s2, s3);
            } else {
                __half* Ph = (__half*)O1v;
                __half* Pl = (__half*)O2v;
                uint32_t hi, lo;
                split2h(v00, v01, hi, lo);
                *(uint32_t*)&Ph[(size_t)m * 1024 + n] = hi;
                *(uint32_t*)&Pl[(size_t)m * 1024 + n] = lo;
                split2h(v10, v11, hi, lo);
                *(uint32_t*)&Ph[(size_t)(m + 8) * 1024 + n] = hi;
                *(uint32_t*)&Pl[(size_t)(m + 8) * 1024 + n] = lo;
            }
        }
    }
}
#define SMEM_DUAL   (3u * 4u * 16384u)   // 196608
#define SMEM_SINGLE (3u * 3u * 16384u)   // 147456

// ---------------- gated scan (fp16 inputs, chunk=16, warp-scan prefix) -----
__global__ void scan_chunk_k()
{
    int d4 = threadIdx.x;
    int c = blockIdx.x, b = blockIdx.y;
    size_t baseh = ((size_t)b * SS + (size_t)c * SCL) * DD + d4 * 4;
    float4 A = make_float4(1.f, 1.f, 1.f, 1.f);
    float4 U = make_float4(0.f, 0.f, 0.f, 0.f);
#pragma unroll
    for (int j = 0; j < SCL; j++) {
        uint2 ar = *(const uint2*)&g_ah[baseh + (size_t)j * DD];
        uint2 ur = *(const uint2*)&g_uh[baseh + (size_t)j * DD];
        float2 a01 = h2f(ar.x), a23 = h2f(ar.y);
        float2 u01 = h2f(ur.x), u23 = h2f(ur.y);
        U.x = a01.x * U.x + u01.x; U.y = a01.y * U.y + u01.y;
        U.z = a23.x * U.z + u23.x; U.w = a23.y * U.w + u23.y;
        A.x *= a01.x; A.y *= a01.y; A.z *= a23.x; A.w *= a23.y;
    }
    size_t o = ((size_t)b * SNC + c) * 256 + d4;
    ((float4*)g_Ac)[o] = A;
    ((float4*)g_Uc)[o] = U;
}

__global__ __launch_bounds__(256)
void scan_prefix_k()
{
    int wg = blockIdx.x * 8 + (threadIdx.x >> 5);
    int lane = threadIdx.x & 31;
    int b = wg >> 8;
    int d4 = wg & 255;

    size_t o0 = ((size_t)b * SNC + lane * 4) * 256 + d4;
    float4 Ac[4], Uc[4];
#pragma unroll
    for (int r = 0; r < 4; r++) {
        Ac[r] = ((const float4*)g_Ac)[o0 + (size_t)r * 256];
        Uc[r] = ((const float4*)g_Uc)[o0 + (size_t)r * 256];
    }
    float4 A = make_float4(1.f, 1.f, 1.f, 1.f);
    float4 U = make_float4(0.f, 0.f, 0.f, 0.f);
#pragma unroll
    for (int r = 0; r < 4; r++) {
        U.x = Ac[r].x * U.x + Uc[r].x; U.y = Ac[r].y * U.y + Uc[r].y;
        U.z = Ac[r].z * U.z + Uc[r].z; U.w = Ac[r].w * U.w + Uc[r].w;
        A.x *= Ac[r].x; A.y *= Ac[r].y; A.z *= Ac[r].z; A.w *= Ac[r].w;
    }
    float4 sA = A, sU = U;
#pragma unroll
    for (int d = 1; d < 32; d <<= 1) {
        float4 tA, tU;
        tA.x = __shfl_up_sync(0xffffffff, sA.x, d);
        tA.y = __shfl_up_sync(0xffffffff, sA.y, d);
        tA.z = __shfl_up_sync(0xffffffff, sA.z, d);
        tA.w = __shfl_up_sync(0xffffffff, sA.w, d);
        tU.x = __shfl_up_sync(0xffffffff, sU.x, d);
        tU.y = __shfl_up_sync(0xffffffff, sU.y, d);
        tU.z = __shfl_up_sync(0xffffffff, sU.z, d);
        tU.w = __shfl_up_sync(0xffffffff, sU.w, d);
        if (lane >= d) {
            sU.x = sA.x * tU.x + sU.x; sU.y = sA.y * tU.y + sU.y;
            sU.z = sA.z * tU.z + sU.z; sU.w = sA.w * tU.w + sU.w;
            sA.x *= tA.x; sA.y *= tA.y; sA.z *= tA.z; sA.w *= tA.w;
        }
    }
    float4 eU;
    eU.x = __shfl_up_sync(0xffffffff, sU.x, 1);
    eU.y = __shfl_up_sync(0xffffffff, sU.y, 1);
    eU.z = __shfl_up_sync(0xffffffff, sU.z, 1);
    eU.w = __shfl_up_sync(0xffffffff, sU.w, 1);
    if (lane == 0) eU = make_float4(0.f, 0.f, 0.f, 0.f);

    float4 h = eU;
#pragma unroll
    for (int r = 0; r < 4; r++) {
        ((float4*)g_P)[o0 + (size_t)r * 256] = h;
        h.x = Ac[r].x * h.x + Uc[r].x; h.y = Ac[r].y * h.y + Uc[r].y;
        h.z = Ac[r].z * h.z + Uc[r].z; h.w = Ac[r].w * h.w + Uc[r].w;
    }
}

__global__ void scan_apply_k()
{
    int d4 = threadIdx.x;
    int c = blockIdx.x, b = blockIdx.y;
    float4 h = ((const float4*)g_P)[((size_t)b * SNC + c) * 256 + d4];
    size_t baseh = ((size_t)b * SS + (size_t)c * SCL) * DD + d4 * 4;
    uint2* hh = (uint2*)g_Hhi;
    uint2* hl = (uint2*)g_Hlo;
    size_t base4 = (((size_t)b * SS + (size_t)c * SCL) * DD) / 4 + d4;
#pragma unroll
    for (int j = 0; j < SCL; j++) {
        uint2 ar = *(const uint2*)&g_ah[baseh + (size_t)j * DD];
        uint2 ur = *(const uint2*)&g_uh[baseh + (size_t)j * DD];
        float2 a01 = h2f(ar.x), a23 = h2f(ar.y);
        float2 u01 = h2f(ur.x), u23 = h2f(ur.y);
        h.x = a01.x * h.x + u01.x; h.y = a01.y * h.y + u01.y;
        h.z = a23.x * h.z + u23.x; h.w = a23.y * h.w + u23.y;
        uint32_t h01, l01, h23, l23;
        split2h(h.x, h.y, h01, l01);
        split2h(h.z, h.w, h23, l23);
        hh[base4 + (size_t)j * 256] = make_uint2(h01, h23);
        hl[base4 + (size_t)j * 256] = make_uint2(l01, l23);
    }
}

// ---------------- retention phase 1 (tensor cores, fp16) --------------------
#define P1_QH 0u
#define P1_QL 8192u
#define P1_KS 16384u
#define P1_WS 24576u
#define P1_VS 32768u
#define P1_GP 40960u

__global__ __launch_bounds__(128)
void ret_p1(const float* __restrict__ kin, const float* __restrict__ vin,
            const float* __restrict__ gammas, float* __restrict__ out)
{
    __shared__ __align__(128) char sm[41232];
    const uint32_t sb = smem_u32(sm);
    float* gps = (float*)(sm + P1_GP);

    int c = blockIdx.x, h = blockIdx.y, b = blockIdx.z;
    int tid = threadIdx.x, wid = tid >> 5, lane = tid & 31;

    if (tid < 65) gps[tid] = powf(gammas[h], (float)tid);
    __syncthreads();

    const uint32_t eighth = pack2h(0.125f, 0.125f);
    size_t base = ((size_t)b * SS + (size_t)c * RL) * DD + (size_t)h * HDD;
#pragma unroll
    for (int it = 0; it < 8; it++) {
        int i = it * 128 + tid;
        int row = i >> 4, c4 = (i & 15) << 2;
        size_t ga = base + (size_t)row * DD + c4;
        uint32_t off = SW(row * 128 + c4 * 2);

        uint2 qh = *(const uint2*)&g_QPh[ga];
        uint2 ql = *(const uint2*)&g_QPl[ga];
        // x0.125 is a power of two: exact in fp16
        *(uint2*)(sm + P1_QH + off) = make_uint2(hmul2u(qh.x, eighth), hmul2u(qh.y, eighth));
        *(uint2*)(sm + P1_QL + off) = make_uint2(hmul2u(ql.x, eighth), hmul2u(ql.y, eighth));

        float4 kv = *(const float4*)&kin[ga];
        *(uint2*)(sm + P1_KS + off) = make_uint2(pack2h(kv.x, kv.y), pack2h(kv.z, kv.w));
        float w = gps[63 - row];
        *(uint2*)(sm + P1_WS + off) =
            make_uint2(pack2h(kv.x * w, kv.y * w), pack2h(kv.z * w, kv.w * w));

        float4 vv = *(const float4*)&vin[ga];
        *(uint2*)(sm + P1_VS + off) = make_uint2(pack2h(vv.x, vv.y), pack2h(vv.z, vv.w));
    }
    __syncthreads();

    const int R = wid * 16;
    const int aq = lane >> 3, ar = lane & 7;
    const int br = lane & 7, bhh = (lane >> 3) & 1;
    const int l2 = lane & 15;
    const int lg = lane >> 3, lr = lane & 7;

    float c_[8][4];
#pragma unroll
    for (int nb = 0; nb < 8; nb++)
#pragma unroll
        for (int r = 0; r < 4; r++) c_[nb][r] = 0.f;

#pragma unroll
    for (int ks = 0; ks < 4; ks++) {
        int k0 = ks * 16;
        uint32_t aH[4], aL[4];
        {
            int m = R + (aq & 1) * 8 + ar;
            int k = k0 + (aq >> 1) * 8;
            uint32_t off = SW(m * 128 + k * 2);
            ldsm_x4(sb + P1_QH + off, aH);
            ldsm_x4(sb + P1_QL + off, aL);
        }
#pragma unroll
        for (int nb = 0; nb < 8; nb++) {
            int n = nb * 8 + br;
            int k = k0 + bhh * 8;
            uint32_t off = SW(n * 128 + k * 2);
            uint32_t bK[2];
            ldsm_x2(sb + P1_KS + off, bK);
            mma_f16(c_[nb], aH, bK);
            mma_f16(c_[nb], aL, bK);
        }
    }

    const int rb = R + (lane >> 2);
    const int cb = (lane & 3) * 2;
#pragma unroll
    for (int nb = 0; nb < 8; nb++) {
        int col0 = nb * 8 + cb;
        c_[nb][0] *= (rb >= col0)         ? gps[rb - col0]         : 0.f;
        c_[nb][1] *= (rb >= col0 + 1)     ? gps[rb - col0 - 1]     : 0.f;
        c_[nb][2] *= (rb + 8 >= col0)     ? gps[rb + 8 - col0]     : 0.f;
        c_[nb][3] *= (rb + 8 >= col0 + 1) ? gps[rb + 8 - col0 - 1] : 0.f;
    }

    float oc[8][4], mc[8][4];
#pragma unroll
    for (int nb = 0; nb < 8; nb++)
#pragma unroll
        for (int r = 0; r < 4; r++) { oc[nb][r] = 0.f; mc[nb][r] = 0.f; }

#pragma unroll
    for (int kk = 0; kk < 4; kk++) {
        int k0 = kk * 16;
        uint32_t aPh[4], aPl[4];
        split2h(c_[2 * kk][0],     c_[2 * kk][1],     aPh[0], aPl[0]);
        split2h(c_[2 * kk][2],     c_[2 * kk][3],     aPh[1], aPl[1]);
        split2h(c_[2 * kk + 1][0], c_[2 * kk + 1][1], aPh[2], aPl[2]);
        split2h(c_[2 * kk + 1][2], c_[2 * kk + 1][3], aPh[3], aPl[3]);
        uint32_t aK[4];
        {
            int jrow = k0 + ((lg & 2) ? 8 : 0) + lr;
            int mcol = R + ((lg & 1) ? 8 : 0);
            uint32_t off = SW(jrow * 128 + mcol * 2);
            ldsm_x4_t(sb + P1_WS + off, aK);
        }
#pragma unroll
        for (int nb = 0; nb < 8; nb++) {
            int n = nb * 8;
            int jrow = k0 + l2;
            uint32_t off = SW(jrow * 128 + n * 2);
            uint32_t bV[2];
            ldsm_x2_t(sb + P1_VS + off, bV);
            mma_f16(oc[nb], aPh, bV);
            mma_f16(oc[nb], aPl, bV);
            mma_f16(mc[nb], aK, bV);
        }
    }

    size_t mb = (((size_t)(b * HH + h)) * RNC + c) * 4096;
#pragma unroll
    for (int nb = 0; nb < 8; nb++) {
        int col = nb * 8 + cb;
        *(float2*)&out[base + (size_t)rb * DD + col]       = make_float2(oc[nb][0], oc[nb][1]);
        *(float2*)&out[base + (size_t)(rb + 8) * DD + col] = make_float2(oc[nb][2], oc[nb][3]);
        *(float2*)&g_M[mb + (size_t)rb * 64 + col]         = make_float2(mc[nb][0], mc[nb][1]);
        *(float2*)&g_M[mb + (size_t)(rb + 8) * 64 + col]   = make_float2(mc[nb][2], mc[nb][3]);
    }
}

// ---------------- retention phase 2 ----------------------------------------
__global__ void ret_scan_k(const float* __restrict__ gammas)
{
    int idx = blockIdx.x * 256 + threadIdx.x;
    int e  = idx & 4095;
    int bh2 = idx >> 12;
    int h  = bh2 & (HH - 1);
    float gL = powf(gammas[h], (float)RL);
    float s = 0.f;
#pragma unroll
    for (int c = 0; c < RNC; c++) {
        size_t o = ((size_t)bh2 * RNC + c) * 4096 + e;
        g_Sp[o] = s;
        s = gL * s + g_M[o];
    }
}

// ---------------- retention phase 3 (tensor cores, fp16) --------------------
__global__ __launch_bounds__(128)
void ret_p3(const float* __restrict__ gammas, float* __restrict__ out)
{
    __shared__ __align__(128) char sm[24848];
    const uint32_t sb = smem_u32(sm);
    const uint32_t QH = 0, QL = 8192, SH = 16384;
    float* gps = (float*)(sm + 24576);

    int c = blockIdx.x, h = blockIdx.y, b = blockIdx.z;
    int tid = threadIdx.x, wid = tid >> 5, lane = tid & 31;

    if (tid < 65) gps[tid] = powf(gammas[h], (float)tid);
    __syncthreads();

    size_t base = ((size_t)b * SS + (size_t)c * RL) * DD + (size_t)h * HDD;
    size_t sbo  = (((size_t)(b * HH + h)) * RNC + c) * 4096;
#pragma unroll
    for (int it = 0; it < 8; it++) {
        int i = it * 128 + tid;
        int row = i >> 4, c4 = (i & 15) << 2;
        uint32_t off = SW(row * 128 + c4 * 2);

        float s0f = gps[row + 1] * 0.125f;
        uint32_t s0 = pack2h(s0f, s0f);
        uint2 qh = *(const uint2*)&g_QPh[base + (size_t)row * DD + c4];
        uint2 ql = *(const uint2*)&g_QPl[base + (size_t)row * DD + c4];
        *(uint2*)(sm + QH + off) = make_uint2(hmul2u(qh.x, s0), hmul2u(qh.y, s0));
        *(uint2*)(sm + QL + off) = make_uint2(hmul2u(ql.x, s0), hmul2u(ql.y, s0));

        float4 sv = *(const float4*)&g_Sp[sbo + (size_t)row * 64 + c4];
        *(uint2*)(sm + SH + off) = make_uint2(pack2h(sv.x, sv.y), pack2h(sv.z, sv.w));
    }
    __syncthreads();

    const int R = wid * 16;
    const int aq = lane >> 3, ar = lane & 7;
    const int l2 = lane & 15;

    float oc[8][4];
#pragma unroll
    for (int nb = 0; nb < 8; nb++)
#pragma unroll
        for (int r = 0; r < 4; r++) oc[nb][r] = 0.f;

#pragma unroll
    for (int ks = 0; ks < 4; ks++) {
        int k0 = ks * 16;
        uint32_t aH[4], aL[4];
        {
            int m = R + (aq & 1) * 8 + ar;
            int k = k0 + (aq >> 1) * 8;
            uint32_t off = SW(m * 128 + k * 2);
            ldsm_x4(sb + QH + off, aH);
            ldsm_x4(sb + QL + off, aL);
        }
#pragma unroll
        for (int nb = 0; nb < 8; nb++) {
            int n = nb * 8;
            int krow = k0 + l2;
            uint32_t off = SW(krow * 128 + n * 2);
            uint32_t bS[2];
            ldsm_x2_t(sb + SH + off, bS);
            mma_f16(oc[nb], aH, bS);
            mma_f16(oc[nb], aL, bS);
        }
    }

    const int rb = R + (lane >> 2);
    const int cb = (lane & 3) * 2;
#pragma unroll
    for (int nb = 0; nb < 8; nb++) {
        int col = nb * 8 + cb;
        size_t o0 = base + (size_t)rb * DD + col;
        size_t o1 = base + (size_t)(rb + 8) * DD + col;
        float2 v0 = *(float2*)&out[o0];
        float2 v1 = *(float2*)&out[o1];
        v0.x += oc[nb][0]; v0.y += oc[nb][1];
        v1.x += oc[nb][2]; v1.y += oc[nb][3];
        *(float2*)&out[o0] = v0;
        *(float2*)&out[o1] = v1;
    }
}

// ---------------- launch ---------------------------------------------------
extern "C" void kernel_launch(void* const* d_in, const int* in_sizes, int n_in,
                              void* d_out, int out_size)
{
    const float* q      = (const float*)d_in[0];
    const float* k      = (const float*)d_in[1];
    const float* v      = (const float*)d_in[2];
    const float* W_in   = (const float*)d_in[3];
    const float* b_in   = (const float*)d_in[4];
    const float* W_gate = (const float*)d_in[5];
    const float* b_gate = (const float*)d_in[6];
    const float* W_out  = (const float*)d_in[7];
    const float* b_out  = (const float*)d_in[8];
    const float* gammas = (const float*)d_in[9];
    float* out = (float*)d_out;

    void *puh, *pah;
    void *pxh, *pxl, *phh, *phl, *pqh, *pql, *pw1, *pw2, *pw3;
    cudaGetSymbolAddress(&puh, g_uh);
    cudaGetSymbolAddress(&pah, g_ah);
    cudaGetSymbolAddress(&pxh, g_Xhi);  cudaGetSymbolAddress(&pxl, g_Xlo);
    cudaGetSymbolAddress(&phh, g_Hhi);  cudaGetSymbolAddress(&phl, g_Hlo);
    cudaGetSymbolAddress(&pqh, g_QPh);  cudaGetSymbolAddress(&pql, g_QPl);
    cudaGetSymbolAddress(&pw1, g_W1);
    cudaGetSymbolAddress(&pw2, g_W2);
    cudaGetSymbolAddress(&pw3, g_W3);

    cudaFuncSetAttribute(gemm_mma<1>, cudaFuncAttributeMaxDynamicSharedMemorySize, SMEM_DUAL);
    cudaFuncSetAttribute(gemm_mma<0>, cudaFuncAttributeMaxDynamicSharedMemorySize, SMEM_SINGLE);

    conv_all_k<<<4096 + 3072, 256>>>(q, W_in, W_gate, W_out,
        (__half*)pxh, (__half*)pxl,
        (__half*)pw1, (__half*)pw2, (__half*)pw3);

    dim3 gg(8, 32);

    gemm_mma<1><<<gg, 512, SMEM_DUAL>>>(
        (const __half*)pxh, (const __half*)pxl,
        (const __half*)pw1, (const __half*)pw2,
        b_in, b_gate, puh, pah);

    scan_chunk_k <<<dim3(SNC, BB), 256>>>();
    scan_prefix_k<<<(BB * 256) / 8, 256>>>();
    scan_apply_k <<<dim3(SNC, BB), 256>>>();

    gemm_mma<0><<<gg, 512, SMEM_SINGLE>>>(
        (const __half*)phh, (const __half*)phl,
        (const __half*)pw3, nullptr,
        b_out, nullptr, pqh, pql);

    ret_p1<<<dim3(RNC, HH, BB), 128>>>(k, v, gammas, out);
    ret_scan_k<<<(BB * HH * HDD * HDD) / 256, 256>>>(gammas);
    ret_p3<<<dim3(RNC, HH, BB), 128>>>(gammas, out);
}

// round 9
// speedup vs baseline: 3.7382x; 1.0291x over previous
#include <cuda_runtime.h>
#include <cuda_fp16.h>
#include <math.h>
#include <stdint.h>

#define BB  2
#define SS  2048
#define DD  1024
#define HH  16
#define HDD 64
#define MM  (BB*SS)
#define SCL 16            // scan chunk length
#define SNC (SS/SCL)      // 128 scan chunks
#define RL  64            // retention chunk length
#define RNC (SS/RL)       // 32 retention chunks

// ---------------- scratch ---------------------------------------------------
__device__ __half g_uh[MM*DD];                  // u (fp16)
__device__ __half g_ah[MM*DD];                  // a (fp16)
__device__ float g_Ac[BB*SNC*DD];
__device__ float g_Uc[BB*SNC*DD];
__device__ float g_P [BB*SNC*DD];
__device__ float g_M [BB*HH*RNC*HDD*HDD];
__device__ float g_Sp[BB*HH*RNC*HDD*HDD];

__device__ __half g_Xhi[MM*DD], g_Xlo[MM*DD];   // q split (fp16)
__device__ __half g_Hhi[MM*DD], g_Hlo[MM*DD];   // h split (fp16)
__device__ __half g_QPh[MM*DD], g_QPl[MM*DD];   // q_proj split (fp16)
__device__ __half g_W1[DD*DD];                  // W_in^T fp16
__device__ __half g_W2[DD*DD];                  // W_gate^T fp16
__device__ __half g_W3[DD*DD];                  // W_out^T fp16

// ---------------- helpers ---------------------------------------------------
__device__ __forceinline__ uint32_t smem_u32(const void* p) {
    uint32_t a;
    asm("{ .reg .u64 t; cvta.to.shared.u64 t, %1; cvt.u32.u64 %0, t; }"
        : "=r"(a) : "l"(p));
    return a;
}
#define SW(o) ((o) ^ ((((uint32_t)(o)) >> 3) & 0x70))

#define CP_ASYNC16(dst, src) \
    asm volatile("cp.async.cg.shared.global [%0], [%1], 16;" :: "r"(dst), "l"(src))
#define CP_COMMIT() asm volatile("cp.async.commit_group;" ::: "memory")
#define CP_WAIT2()  asm volatile("cp.async.wait_group 2;" ::: "memory")
#define CP_WAIT0()  asm volatile("cp.async.wait_group 0;" ::: "memory")

__device__ __forceinline__ void ldsm_x4(uint32_t addr, uint32_t* r) {
    asm volatile("ldmatrix.sync.aligned.m8n8.x4.shared.b16 {%0,%1,%2,%3}, [%4];"
                 : "=r"(r[0]), "=r"(r[1]), "=r"(r[2]), "=r"(r[3]) : "r"(addr));
}
__device__ __forceinline__ void ldsm_x2(uint32_t addr, uint32_t* r) {
    asm volatile("ldmatrix.sync.aligned.m8n8.x2.shared.b16 {%0,%1}, [%2];"
                 : "=r"(r[0]), "=r"(r[1]) : "r"(addr));
}
__device__ __forceinline__ void ldsm_x4_t(uint32_t addr, uint32_t* r) {
    asm volatile("ldmatrix.sync.aligned.m8n8.x4.trans.shared.b16 {%0,%1,%2,%3}, [%4];"
                 : "=r"(r[0]), "=r"(r[1]), "=r"(r[2]), "=r"(r[3]) : "r"(addr));
}
__device__ __forceinline__ void ldsm_x2_t(uint32_t addr, uint32_t* r) {
    asm volatile("ldmatrix.sync.aligned.m8n8.x2.trans.shared.b16 {%0,%1}, [%2];"
                 : "=r"(r[0]), "=r"(r[1]) : "r"(addr));
}
__device__ __forceinline__ void mma_f16(float* d, const uint32_t* a, const uint32_t* b) {
    asm volatile("mma.sync.aligned.m16n8k16.row.col.f32.f16.f16.f32 "
                 "{%0,%1,%2,%3}, {%4,%5,%6,%7}, {%8,%9}, {%0,%1,%2,%3};"
                 : "+f"(d[0]), "+f"(d[1]), "+f"(d[2]), "+f"(d[3])
                 : "r"(a[0]), "r"(a[1]), "r"(a[2]), "r"(a[3]), "r"(b[0]), "r"(b[1]));
}
__device__ __forceinline__ uint32_t pack2h(float x, float y) {
    uint32_t r;
    asm("cvt.rn.f16x2.f32 %0, %1, %2;" : "=r"(r) : "f"(y), "f"(x));
    return r;
}
__device__ __forceinline__ void split2h(float x, float y, uint32_t& hi, uint32_t& lo) {
    hi = pack2h(x, y);
    __half2 hv = *(__half2*)&hi;
    float rx = x - __low2float(hv);
    float ry = y - __high2float(hv);
    lo = pack2h(rx, ry);
}
__device__ __forceinline__ float2 h2f(uint32_t p) {
    return __half22float2(*(__half2*)&p);
}
__device__ __forceinline__ uint32_t hmul2u(uint32_t a, uint32_t s) {
    __half2 r = __hmul2(*(__half2*)&a, *(__half2*)&s);
    return *(uint32_t*)&r;
}

// ---------------- merged conversion kernel ----------------------------------
__global__ __launch_bounds__(256)
void conv_all_k(const float* __restrict__ X,
                const float* __restrict__ Wa, const float* __restrict__ Wb,
                const float* __restrict__ Wc,
                __half* __restrict__ xhi, __half* __restrict__ xlo,
                __half* __restrict__ oa, __half* __restrict__ ob,
                __half* __restrict__ oc)
{
    __shared__ float t[32][33];
    int bid = blockIdx.x;
    if (bid < 4096) {
        int i = bid * 256 + threadIdx.x;
        float4 v = ((const float4*)X)[i];
        uint32_t h01, l01, h23, l23;
        split2h(v.x, v.y, h01, l01);
        split2h(v.z, v.w, h23, l23);
        ((uint2*)xhi)[i] = make_uint2(h01, h23);
        ((uint2*)xlo)[i] = make_uint2(l01, l23);
        return;
    }
    int r0 = bid - 4096;
    int z = r0 >> 10;
    int rr = r0 & 1023;
    const float* W = (z == 0) ? Wa : (z == 1) ? Wb : Wc;
    __half* o = (z == 0) ? oa : (z == 1) ? ob : oc;
    int n0 = (rr & 31) * 32, k0 = (rr >> 5) * 32;
    int tx = threadIdx.x & 31, ty = threadIdx.x >> 5;
#pragma unroll
    for (int r = 0; r < 4; r++)
        t[ty * 4 + r][tx] = W[(size_t)(k0 + ty * 4 + r) * DD + n0 + tx];
    __syncthreads();
#pragma unroll
    for (int r = 0; r < 4; r++) {
        int n = ty * 4 + r;
        o[(size_t)(n0 + n) * DD + k0 + tx] = __float2half_rn(t[tx][n]);
    }
}

// ---------------- mma.sync GEMM, 3-stage cp.async pipeline ------------------
template<int DUAL>
__global__ __launch_bounds__(512)
void gemm_mma(const __half* __restrict__ Ahi_g, const __half* __restrict__ Alo_g,
              const __half* __restrict__ B1_g, const __half* __restrict__ B2_g,
              const float* __restrict__ b1, const float* __restrict__ b2,
              void* __restrict__ O1v, void* __restrict__ O2v)
{
    extern __shared__ char sm[];
    const uint32_t sb = smem_u32(sm);
    const int NT = DUAL ? 4 : 3;
    const uint32_t STAGE = NT * 16384u;
    const int tid = threadIdx.x, wid = tid >> 5, lane = tid & 31;
    const int m0 = blockIdx.y * 128, n0 = blockIdx.x * 128;
    const int wrow = (wid >> 2) * 32, wcol = (wid & 3) * 32;

    const char* srcs[4];
    srcs[0] = (const char*)Ahi_g + (size_t)m0 * 2048;
    srcs[1] = (const char*)Alo_g + (size_t)m0 * 2048;
    srcs[2] = (const char*)B1_g + (size_t)n0 * 2048;
    if (DUAL) srcs[3] = (const char*)B2_g + (size_t)n0 * 2048;

    float acc1[2][4][4];
    float acc2[2][4][4];
#pragma unroll
    for (int mt = 0; mt < 2; mt++)
#pragma unroll
        for (int nt = 0; nt < 4; nt++)
#pragma unroll
            for (int c = 0; c < 4; c++) { acc1[mt][nt][c] = 0.f; acc2[mt][nt][c] = 0.f; }

    const int aq = lane >> 3, ar = lane & 7;
    const int br = lane & 7, bhh = (lane >> 3) & 1;

    auto load_stage = [&](int s, int kc) {
        uint32_t sbase = sb + (uint32_t)s * STAGE;
#pragma unroll
        for (int t = 0; t < NT; t++) {
            const char* gp = srcs[t] + (size_t)kc * 128;
#pragma unroll
            for (int rep = 0; rep < 2; rep++) {
                int i = rep * 512 + tid;
                int row = i >> 3, c16 = (i & 7) * 16;
                uint32_t so = sbase + t * 16384u + SW(row * 128 + c16);
                CP_ASYNC16(so, gp + (size_t)row * 2048 + c16);
            }
        }
        CP_COMMIT();
    };

    load_stage(0, 0);
    load_stage(1, 1);

    for (int kc = 0; kc < 16; kc++) {
        if (kc + 2 < 16) load_stage((kc + 2) % 3, kc + 2);
        else CP_COMMIT();
        CP_WAIT2();
        __syncthreads();

        uint32_t stb = sb + (uint32_t)(kc % 3) * STAGE;
#pragma unroll
        for (int ks = 0; ks < 4; ks++) {
            int k0 = ks * 16;
            uint32_t aHI[2][4], aLO[2][4];
#pragma unroll
            for (int mt = 0; mt < 2; mt++) {
                int m = wrow + mt * 16 + (aq & 1) * 8 + ar;
                int k = k0 + (aq >> 1) * 8;
                uint32_t off = SW(m * 128 + k * 2);
                ldsm_x4(stb + off, aHI[mt]);
                ldsm_x4(stb + 16384u + off, aLO[mt]);
            }
            uint32_t bF1[4][2], bF2[4][2];
#pragma unroll
            for (int nt = 0; nt < 4; nt++) {
                int n = wcol + nt * 8 + br;
                int k = k0 + bhh * 8;
                uint32_t off = SW(n * 128 + k * 2);
                ldsm_x2(stb + 32768u + off, bF1[nt]);
                if (DUAL) ldsm_x2(stb + 49152u + off, bF2[nt]);
            }
#pragma unroll
            for (int mt = 0; mt < 2; mt++)
#pragma unroll
                for (int nt = 0; nt < 4; nt++) {
                    mma_f16(acc1[mt][nt], aHI[mt], bF1[nt]);
                    mma_f16(acc1[mt][nt], aLO[mt], bF1[nt]);
                }
            if (DUAL) {
#pragma unroll
                for (int mt = 0; mt < 2; mt++)
#pragma unroll
                    for (int nt = 0; nt < 4; nt++) {
                        mma_f16(acc2[mt][nt], aHI[mt], bF2[nt]);
                        mma_f16(acc2[mt][nt], aLO[mt], bF2[nt]);
                    }
            }
        }
        __syncthreads();
    }
    CP_WAIT0();

#pragma unroll
    for (int nt = 0; nt < 4; nt++) {
        int n = n0 + wcol + nt * 8 + (lane & 3) * 2;
        float bv0 = __ldg(&b1[n]), bv1 = __ldg(&b1[n + 1]);
        float gv0 = 0.f, gv1 = 0.f;
        if (DUAL) { gv0 = __ldg(&b2[n]); gv1 = __ldg(&b2[n + 1]); }
#pragma unroll
        for (int mt = 0; mt < 2; mt++) {
            int m = m0 + wrow + mt * 16 + (lane >> 2);
            float v00 = acc1[mt][nt][0] + bv0, v01 = acc1[mt][nt][1] + bv1;
            float v10 = acc1[mt][nt][2] + bv0, v11 = acc1[mt][nt][3] + bv1;
            if (DUAL) {
                __half* U = (__half*)O1v;
                __half* A = (__half*)O2v;
                *(uint32_t*)&U[(size_t)m * 1024 + n]       = pack2h(v00, v01);
                *(uint32_t*)&U[(size_t)(m + 8) * 1024 + n] = pack2h(v10, v11);
                float s0 = 1.f / (1.f + expf(-(acc2[mt][nt][0] + gv0)));
                float s1 = 1.f / (1.f + expf(-(acc2[mt][nt][1] + gv1)));
                float s2 = 1.f / (1.f + expf(-(acc2[mt][nt][2] + gv0)));
                float s3 = 1.f / (1.f + expf(-(acc2[mt][nt][3] + gv1)));
                *(uint32_t*)&A[(size_t)m * 1024 + n]       = pack2h(s0, s1);
                *(uint32_t*)&A[(size_t)(m + 8) * 1024 + n] = pack2h(s2, s3);
            } else {
                __half* Ph = (__half*)O1v;
                __half* Pl = (__half*)O2v;
                uint32_t hi, lo;
                split2h(v00, v01, hi, lo);
                *(uint32_t*)&Ph[(size_t)m * 1024 + n] = hi;
                *(uint32_t*)&Pl[(size_t)m * 1024 + n] = lo;
                split2h(v10, v11, hi, lo);
                *(uint32_t*)&Ph[(size_t)(m + 8) * 1024 + n] = hi;
                *(uint32_t*)&Pl[(size_t)(m + 8) * 1024 + n] = lo;
            }
        }
    }
}
#define SMEM_DUAL   (3u * 4u * 16384u)
#define SMEM_SINGLE (3u * 3u * 16384u)

// ---------------- gated scan -------------------------------------------------
__global__ void scan_chunk_k()
{
    int d4 = threadIdx.x;
    int c = blockIdx.x, b = blockIdx.y;
    size_t baseh = ((size_t)b * SS + (size_t)c * SCL) * DD + d4 * 4;
    float4 A = make_float4(1.f, 1.f, 1.f, 1.f);
    float4 U = make_float4(0.f, 0.f, 0.f, 0.f);
#pragma unroll
    for (int j = 0; j < SCL; j++) {
        uint2 ar = *(const uint2*)&g_ah[baseh + (size_t)j * DD];
        uint2 ur = *(const uint2*)&g_uh[baseh + (size_t)j * DD];
        float2 a01 = h2f(ar.x), a23 = h2f(ar.y);
        float2 u01 = h2f(ur.x), u23 = h2f(ur.y);
        U.x = a01.x * U.x + u01.x; U.y = a01.y * U.y + u01.y;
        U.z = a23.x * U.z + u23.x; U.w = a23.y * U.w + u23.y;
        A.x *= a01.x; A.y *= a01.y; A.z *= a23.x; A.w *= a23.y;
    }
    size_t o = ((size_t)b * SNC + c) * 256 + d4;
    ((float4*)g_Ac)[o] = A;
    ((float4*)g_Uc)[o] = U;
}

__global__ __launch_bounds__(256)
void scan_prefix_k()
{
    int wg = blockIdx.x * 8 + (threadIdx.x >> 5);
    int lane = threadIdx.x & 31;
    int b = wg >> 8;
    int d4 = wg & 255;

    size_t o0 = ((size_t)b * SNC + lane * 4) * 256 + d4;
    float4 Ac[4], Uc[4];
#pragma unroll
    for (int r = 0; r < 4; r++) {
        Ac[r] = ((const float4*)g_Ac)[o0 + (size_t)r * 256];
        Uc[r] = ((const float4*)g_Uc)[o0 + (size_t)r * 256];
    }
    float4 A = make_float4(1.f, 1.f, 1.f, 1.f);
    float4 U = make_float4(0.f, 0.f, 0.f, 0.f);
#pragma unroll
    for (int r = 0; r < 4; r++) {
        U.x = Ac[r].x * U.x + Uc[r].x; U.y = Ac[r].y * U.y + Uc[r].y;
        U.z = Ac[r].z * U.z + Uc[r].z; U.w = Ac[r].w * U.w + Uc[r].w;
        A.x *= Ac[r].x; A.y *= Ac[r].y; A.z *= Ac[r].z; A.w *= Ac[r].w;
    }
    float4 sA = A, sU = U;
#pragma unroll
    for (int d = 1; d < 32; d <<= 1) {
        float4 tA, tU;
        tA.x = __shfl_up_sync(0xffffffff, sA.x, d);
        tA.y = __shfl_up_sync(0xffffffff, sA.y, d);
        tA.z = __shfl_up_sync(0xffffffff, sA.z, d);
        tA.w = __shfl_up_sync(0xffffffff, sA.w, d);
        tU.x = __shfl_up_sync(0xffffffff, sU.x, d);
        tU.y = __shfl_up_sync(0xffffffff, sU.y, d);
        tU.z = __shfl_up_sync(0xffffffff, sU.z, d);
        tU.w = __shfl_up_sync(0xffffffff, sU.w, d);
        if (lane >= d) {
            sU.x = sA.x * tU.x + sU.x; sU.y = sA.y * tU.y + sU.y;
            sU.z = sA.z * tU.z + sU.z; sU.w = sA.w * tU.w + sU.w;
            sA.x *= tA.x; sA.y *= tA.y; sA.z *= tA.z; sA.w *= tA.w;
        }
    }
    float4 eU;
    eU.x = __shfl_up_sync(0xffffffff, sU.x, 1);
    eU.y = __shfl_up_sync(0xffffffff, sU.y, 1);
    eU.z = __shfl_up_sync(0xffffffff, sU.z, 1);
    eU.w = __shfl_up_sync(0xffffffff, sU.w, 1);
    if (lane == 0) eU = make_float4(0.f, 0.f, 0.f, 0.f);

    float4 h = eU;
#pragma unroll
    for (int r = 0; r < 4; r++) {
        ((float4*)g_P)[o0 + (size_t)r * 256] = h;
        h.x = Ac[r].x * h.x + Uc[r].x; h.y = Ac[r].y * h.y + Uc[r].y;
        h.z = Ac[r].z * h.z + Uc[r].z; h.w = Ac[r].w * h.w + Uc[r].w;
    }
}

__global__ void scan_apply_k()
{
    int d4 = threadIdx.x;
    int c = blockIdx.x, b = blockIdx.y;
    float4 h = ((const float4*)g_P)[((size_t)b * SNC + c) * 256 + d4];
    size_t baseh = ((size_t)b * SS + (size_t)c * SCL) * DD + d4 * 4;
    uint2* hh = (uint2*)g_Hhi;
    uint2* hl = (uint2*)g_Hlo;
    size_t base4 = (((size_t)b * SS + (size_t)c * SCL) * DD) / 4 + d4;
#pragma unroll
    for (int j = 0; j < SCL; j++) {
        uint2 ar = *(const uint2*)&g_ah[baseh + (size_t)j * DD];
        uint2 ur = *(const uint2*)&g_uh[baseh + (size_t)j * DD];
        float2 a01 = h2f(ar.x), a23 = h2f(ar.y);
        float2 u01 = h2f(ur.x), u23 = h2f(ur.y);
        h.x = a01.x * h.x + u01.x; h.y = a01.y * h.y + u01.y;
        h.z = a23.x * h.z + u23.x; h.w = a23.y * h.w + u23.y;
        uint32_t h01, l01, h23, l23;
        split2h(h.x, h.y, h01, l01);
        split2h(h.z, h.w, h23, l23);
        hh[base4 + (size_t)j * 256] = make_uint2(h01, h23);
        hl[base4 + (size_t)j * 256] = make_uint2(l01, l23);
    }
}

// ---------------- retention KV branch: M = Kw^T V (independent of mamba) ----
__global__ __launch_bounds__(128)
void ret_kv(const float* __restrict__ kin, const float* __restrict__ vin,
            const float* __restrict__ gammas)
{
    __shared__ __align__(128) char sm[16656];
    const uint32_t sb = smem_u32(sm);
    const uint32_t WS = 0, VS = 8192;
    float* gps = (float*)(sm + 16384);

    int c = blockIdx.x, h = blockIdx.y, b = blockIdx.z;
    int tid = threadIdx.x, wid = tid >> 5, lane = tid & 31;

    if (tid < 65) gps[tid] = powf(gammas[h], (float)tid);
    __syncthreads();

    size_t base = ((size_t)b * SS + (size_t)c * RL) * DD + (size_t)h * HDD;
#pragma unroll
    for (int it = 0; it < 8; it++) {
        int i = it * 128 + tid;
        int row = i >> 4, c4 = (i & 15) << 2;
        size_t ga = base + (size_t)row * DD + c4;
        uint32_t off = SW(row * 128 + c4 * 2);
        float4 kv = *(const float4*)&kin[ga];
        float w = gps[63 - row];
        *(uint2*)(sm + WS + off) =
            make_uint2(pack2h(kv.x * w, kv.y * w), pack2h(kv.z * w, kv.w * w));
        float4 vv = *(const float4*)&vin[ga];
        *(uint2*)(sm + VS + off) = make_uint2(pack2h(vv.x, vv.y), pack2h(vv.z, vv.w));
    }
    __syncthreads();

    const int R = wid * 16;
    const int l2 = lane & 15;
    const int lg = lane >> 3, lr = lane & 7;

    float mc[8][4];
#pragma unroll
    for (int nb = 0; nb < 8; nb++)
#pragma unroll
        for (int r = 0; r < 4; r++) mc[nb][r] = 0.f;

#pragma unroll
    for (int kk = 0; kk < 4; kk++) {
        int k0 = kk * 16;
        uint32_t aK[4];
        {
            int jrow = k0 + ((lg & 2) ? 8 : 0) + lr;
            int mcol = R + ((lg & 1) ? 8 : 0);
            uint32_t off = SW(jrow * 128 + mcol * 2);
            ldsm_x4_t(sb + WS + off, aK);
        }
#pragma unroll
        for (int nb = 0; nb < 8; nb++) {
            int n = nb * 8;
            int jrow = k0 + l2;
            uint32_t off = SW(jrow * 128 + n * 2);
            uint32_t bV[2];
            ldsm_x2_t(sb + VS + off, bV);
            mma_f16(mc[nb], aK, bV);
        }
    }

    const int rb = R + (lane >> 2);
    const int cb = (lane & 3) * 2;
    size_t mb = (((size_t)(b * HH + h)) * RNC + c) * 4096;
#pragma unroll
    for (int nb = 0; nb < 8; nb++) {
        int col = nb * 8 + cb;
        *(float2*)&g_M[mb + (size_t)rb * 64 + col]       = make_float2(mc[nb][0], mc[nb][1]);
        *(float2*)&g_M[mb + (size_t)(rb + 8) * 64 + col] = make_float2(mc[nb][2], mc[nb][3]);
    }
}

// ---------------- retention state scan over chunks ---------------------------
__global__ void ret_scan_k(const float* __restrict__ gammas)
{
    int idx = blockIdx.x * 256 + threadIdx.x;
    int e  = idx & 4095;
    int bh2 = idx >> 12;
    int h  = bh2 & (HH - 1);
    float gL = powf(gammas[h], (float)RL);
    float s = 0.f;
#pragma unroll
    for (int c = 0; c < RNC; c++) {
        size_t o = ((size_t)bh2 * RNC + c) * 4096 + e;
        g_Sp[o] = s;
        s = gL * s + g_M[o];
    }
}

// ---------------- fused retention q-path: out = intra(Q,K,V) + γ^{i+1} Q Sp --
#define RQ_QH 0u
#define RQ_QL 8192u
#define RQ_KS 16384u
#define RQ_VS 24576u
#define RQ_SP 32768u
#define RQ_GP 40960u

__global__ __launch_bounds__(128)
void ret_q(const float* __restrict__ kin, const float* __restrict__ vin,
           const float* __restrict__ gammas, float* __restrict__ out)
{
    __shared__ __align__(128) char sm[41232];
    const uint32_t sb = smem_u32(sm);
    float* gps = (float*)(sm + RQ_GP);

    int c = blockIdx.x, h = blockIdx.y, b = blockIdx.z;
    int tid = threadIdx.x, wid = tid >> 5, lane = tid & 31;

    if (tid < 65) gps[tid] = powf(gammas[h], (float)tid);
    __syncthreads();

    const uint32_t eighth = pack2h(0.125f, 0.125f);
    size_t base = ((size_t)b * SS + (size_t)c * RL) * DD + (size_t)h * HDD;
    size_t sbo  = (((size_t)(b * HH + h)) * RNC + c) * 4096;
#pragma unroll
    for (int it = 0; it < 8; it++) {
        int i = it * 128 + tid;
        int row = i >> 4, c4 = (i & 15) << 2;
        size_t ga = base + (size_t)row * DD + c4;
        uint32_t off = SW(row * 128 + c4 * 2);

        uint2 qh = *(const uint2*)&g_QPh[ga];
        uint2 ql = *(const uint2*)&g_QPl[ga];
        *(uint2*)(sm + RQ_QH + off) = make_uint2(hmul2u(qh.x, eighth), hmul2u(qh.y, eighth));
        *(uint2*)(sm + RQ_QL + off) = make_uint2(hmul2u(ql.x, eighth), hmul2u(ql.y, eighth));

        float4 kv = *(const float4*)&kin[ga];
        *(uint2*)(sm + RQ_KS + off) = make_uint2(pack2h(kv.x, kv.y), pack2h(kv.z, kv.w));

        float4 vv = *(const float4*)&vin[ga];
        *(uint2*)(sm + RQ_VS + off) = make_uint2(pack2h(vv.x, vv.y), pack2h(vv.z, vv.w));

        float4 sv = *(const float4*)&g_Sp[sbo + (size_t)row * 64 + c4];
        *(uint2*)(sm + RQ_SP + off) = make_uint2(pack2h(sv.x, sv.y), pack2h(sv.z, sv.w));
    }
    __syncthreads();

    const int R = wid * 16;
    const int aq = lane >> 3, ar = lane & 7;
    const int br = lane & 7, bhh = (lane >> 3) & 1;
    const int l2 = lane & 15;

    // ---- S = (Q/8) K^T  and  o2 = (Q/8) Sp ----
    float c_[8][4], o2[8][4];
#pragma unroll
    for (int nb = 0; nb < 8; nb++)
#pragma unroll
        for (int r = 0; r < 4; r++) { c_[nb][r] = 0.f; o2[nb][r] = 0.f; }

#pragma unroll
    for (int ks = 0; ks < 4; ks++) {
        int k0 = ks * 16;
        uint32_t aH[4], aL[4];
        {
            int m = R + (aq & 1) * 8 + ar;
            int k = k0 + (aq >> 1) * 8;
            uint32_t off = SW(m * 128 + k * 2);
            ldsm_x4(sb + RQ_QH + off, aH);
            ldsm_x4(sb + RQ_QL + off, aL);
        }
#pragma unroll
        for (int nb = 0; nb < 8; nb++) {
            int n = nb * 8 + br;
            int k = k0 + bhh * 8;
            uint32_t off = SW(n * 128 + k * 2);
            uint32_t bK[2];
            ldsm_x2(sb + RQ_KS + off, bK);
            mma_f16(c_[nb], aH, bK);
            mma_f16(c_[nb], aL, bK);
        }
#pragma unroll
        for (int nb = 0; nb < 8; nb++) {
            int n = nb * 8;
            int krow = k0 + l2;
            uint32_t off = SW(krow * 128 + n * 2);
            uint32_t bS[2];
            ldsm_x2_t(sb + RQ_SP + off, bS);
            mma_f16(o2[nb], aH, bS);
            mma_f16(o2[nb], aL, bS);
        }
    }

    // ---- decay mask on intra scores ----
    const int rb = R + (lane >> 2);
    const int cb = (lane & 3) * 2;
#pragma unroll
    for (int nb = 0; nb < 8; nb++) {
        int col0 = nb * 8 + cb;
        c_[nb][0] *= (rb >= col0)         ? gps[rb - col0]         : 0.f;
        c_[nb][1] *= (rb >= col0 + 1)     ? gps[rb - col0 - 1]     : 0.f;
        c_[nb][2] *= (rb + 8 >= col0)     ? gps[rb + 8 - col0]     : 0.f;
        c_[nb][3] *= (rb + 8 >= col0 + 1) ? gps[rb + 8 - col0 - 1] : 0.f;
    }

    // ---- oc = P V ----
    float oc[8][4];
#pragma unroll
    for (int nb = 0; nb < 8; nb++)
#pragma unroll
        for (int r = 0; r < 4; r++) oc[nb][r] = 0.f;

#pragma unroll
    for (int kk = 0; kk < 4; kk++) {
        int k0 = kk * 16;
        uint32_t aPh[4], aPl[4];
        split2h(c_[2 * kk][0],     c_[2 * kk][1],     aPh[0], aPl[0]);
        split2h(c_[2 * kk][2],     c_[2 * kk][3],     aPh[1], aPl[1]);
        split2h(c_[2 * kk + 1][0], c_[2 * kk + 1][1], aPh[2], aPl[2]);
        split2h(c_[2 * kk + 1][2], c_[2 * kk + 1][3], aPh[3], aPl[3]);
#pragma unroll
        for (int nb = 0; nb < 8; nb++) {
            int n = nb * 8;
            int jrow = k0 + l2;
            uint32_t off = SW(jrow * 128 + n * 2);
            uint32_t bV[2];
            ldsm_x2_t(sb + RQ_VS + off, bV);
            mma_f16(oc[nb], aPh, bV);
            mma_f16(oc[nb], aPl, bV);
        }
    }

    // ---- out = oc + gamma^{row+1} * o2 (single write) ----
    float g0 = gps[rb + 1];
    float g1 = gps[rb + 9];
#pragma unroll
    for (int nb = 0; nb < 8; nb++) {
        int col = nb * 8 + cb;
        *(float2*)&out[base + (size_t)rb * DD + col] =
            make_float2(oc[nb][0] + g0 * o2[nb][0], oc[nb][1] + g0 * o2[nb][1]);
        *(float2*)&out[base + (size_t)(rb + 8) * DD + col] =
            make_float2(oc[nb][2] + g1 * o2[nb][2], oc[nb][3] + g1 * o2[nb][3]);
    }
}

// ---------------- launch ---------------------------------------------------
extern "C" void kernel_launch(void* const* d_in, const int* in_sizes, int n_in,
                              void* d_out, int out_size)
{
    const float* q      = (const float*)d_in[0];
    const float* k      = (const float*)d_in[1];
    const float* v      = (const float*)d_in[2];
    const float* W_in   = (const float*)d_in[3];
    const float* b_in   = (const float*)d_in[4];
    const float* W_gate = (const float*)d_in[5];
    const float* b_gate = (const float*)d_in[6];
    const float* W_out  = (const float*)d_in[7];
    const float* b_out  = (const float*)d_in[8];
    const float* gammas = (const float*)d_in[9];
    float* out = (float*)d_out;

    void *puh, *pah;
    void *pxh, *pxl, *phh, *phl, *pqh, *pql, *pw1, *pw2, *pw3;
    cudaGetSymbolAddress(&puh, g_uh);
    cudaGetSymbolAddress(&pah, g_ah);
    cudaGetSymbolAddress(&pxh, g_Xhi);  cudaGetSymbolAddress(&pxl, g_Xlo);
    cudaGetSymbolAddress(&phh, g_Hhi);  cudaGetSymbolAddress(&phl, g_Hlo);
    cudaGetSymbolAddress(&pqh, g_QPh);  cudaGetSymbolAddress(&pql, g_QPl);
    cudaGetSymbolAddress(&pw1, g_W1);
    cudaGetSymbolAddress(&pw2, g_W2);
    cudaGetSymbolAddress(&pw3, g_W3);

    cudaFuncSetAttribute(gemm_mma<1>, cudaFuncAttributeMaxDynamicSharedMemorySize, SMEM_DUAL);
    cudaFuncSetAttribute(gemm_mma<0>, cudaFuncAttributeMaxDynamicSharedMemorySize, SMEM_SINGLE);

    // fork a side stream for the k/v-only retention branch (graph-capture fork)
    cudaStream_t s2;
    cudaStreamCreateWithFlags(&s2, cudaStreamNonBlocking);
    cudaEvent_t evF, evJ;
    cudaEventCreateWithFlags(&evF, cudaEventDisableTiming);
    cudaEventCreateWithFlags(&evJ, cudaEventDisableTiming);

    cudaEventRecord(evF, 0);
    cudaStreamWaitEvent(s2, evF, 0);
    // branch B: M = Kw^T V, then Sp chunk-prefix (needs only k, v, gammas)
    ret_kv<<<dim3(RNC, HH, BB), 128, 0, s2>>>(k, v, gammas);
    ret_scan_k<<<(BB * HH * HDD * HDD) / 256, 256, 0, s2>>>(gammas);
    cudaEventRecord(evJ, s2);

    // branch A: mamba chain
    conv_all_k<<<4096 + 3072, 256>>>(q, W_in, W_gate, W_out,
        (__half*)pxh, (__half*)pxl,
        (__half*)pw1, (__half*)pw2, (__half*)pw3);

    dim3 gg(8, 32);
    gemm_mma<1><<<gg, 512, SMEM_DUAL>>>(
        (const __half*)pxh, (const __half*)pxl,
        (const __half*)pw1, (const __half*)pw2,
        b_in, b_gate, puh, pah);

    scan_chunk_k <<<dim3(SNC, BB), 256>>>();
    scan_prefix_k<<<(BB * 256) / 8, 256>>>();
    scan_apply_k <<<dim3(SNC, BB), 256>>>();

    gemm_mma<0><<<gg, 512, SMEM_SINGLE>>>(
        (const __half*)phh, (const __half*)phl,
        (const __half*)pw3, nullptr,
        b_out, nullptr, pqh, pql);

    // join: fused retention q-path needs q_proj (A) and Sp (B)
    cudaStreamWaitEvent(0, evJ, 0);
    ret_q<<<dim3(RNC, HH, BB), 128>>>(k, v, gammas, out);
    // streams/events intentionally not destroyed: kernel_launch is called only a
    // few times (correctness + capture); destroying a forked stream mid-capture
    // would invalidate the capture sequence.
}

// round 10
// speedup vs baseline: 4.5360x; 1.2134x over previous
#include <cuda_runtime.h>
#include <cuda_fp16.h>
#include <math.h>
#include <stdint.h>

#define BB  2
#define SS  2048
#define DD  1024
#define HH  16
#define HDD 64
#define MM  (BB*SS)
#define SCL 16            // scan chunk length
#define SNC (SS/SCL)      // 128 scan chunks
#define RL  64            // retention chunk length
#define RNC (SS/RL)       // 32 retention chunks

// ---------------- scratch ---------------------------------------------------
__device__ __half g_uh[MM*DD];                  // u (fp16)
__device__ __half g_ah[MM*DD];                  // a (fp16)
__device__ float g_Ac[BB*SNC*DD];
__device__ float g_Uc[BB*SNC*DD];
__device__ float g_P [BB*SNC*DD];
__device__ float g_M [BB*HH*RNC*HDD*HDD];
__device__ float g_Sp[BB*HH*RNC*HDD*HDD];

__device__ __half g_Xhi[MM*DD], g_Xlo[MM*DD];   // q split (fp16)
__device__ __half g_Hhi[MM*DD], g_Hlo[MM*DD];   // h split (fp16)
__device__ __half g_QPh[MM*DD], g_QPl[MM*DD];   // q_proj split (fp16)
__device__ __half g_W1[DD*DD];                  // W_in^T fp16
__device__ __half g_W2[DD*DD];                  // W_gate^T fp16
__device__ __half g_W3[DD*DD];                  // W_out^T fp16

// ---------------- helpers ---------------------------------------------------
__device__ __forceinline__ uint32_t smem_u32(const void* p) {
    uint32_t a;
    asm("{ .reg .u64 t; cvta.to.shared.u64 t, %1; cvt.u32.u64 %0, t; }"
        : "=r"(a) : "l"(p));
    return a;
}
#define SW(o) ((o) ^ ((((uint32_t)(o)) >> 3) & 0x70))

#define CP_ASYNC16(dst, src) \
    asm volatile("cp.async.cg.shared.global [%0], [%1], 16;" :: "r"(dst), "l"(src))
#define CP_COMMIT() asm volatile("cp.async.commit_group;" ::: "memory")
#define CP_WAIT2()  asm volatile("cp.async.wait_group 2;" ::: "memory")
#define CP_WAIT0()  asm volatile("cp.async.wait_group 0;" ::: "memory")

__device__ __forceinline__ void ldsm_x4(uint32_t addr, uint32_t* r) {
    asm volatile("ldmatrix.sync.aligned.m8n8.x4.shared.b16 {%0,%1,%2,%3}, [%4];"
                 : "=r"(r[0]), "=r"(r[1]), "=r"(r[2]), "=r"(r[3]) : "r"(addr));
}
__device__ __forceinline__ void ldsm_x2(uint32_t addr, uint32_t* r) {
    asm volatile("ldmatrix.sync.aligned.m8n8.x2.shared.b16 {%0,%1}, [%2];"
                 : "=r"(r[0]), "=r"(r[1]) : "r"(addr));
}
__device__ __forceinline__ void ldsm_x4_t(uint32_t addr, uint32_t* r) {
    asm volatile("ldmatrix.sync.aligned.m8n8.x4.trans.shared.b16 {%0,%1,%2,%3}, [%4];"
                 : "=r"(r[0]), "=r"(r[1]), "=r"(r[2]), "=r"(r[3]) : "r"(addr));
}
__device__ __forceinline__ void ldsm_x2_t(uint32_t addr, uint32_t* r) {
    asm volatile("ldmatrix.sync.aligned.m8n8.x2.trans.shared.b16 {%0,%1}, [%2];"
                 : "=r"(r[0]), "=r"(r[1]) : "r"(addr));
}
__device__ __forceinline__ void mma_f16(float* d, const uint32_t* a, const uint32_t* b) {
    asm volatile("mma.sync.aligned.m16n8k16.row.col.f32.f16.f16.f32 "
                 "{%0,%1,%2,%3}, {%4,%5,%6,%7}, {%8,%9}, {%0,%1,%2,%3};"
                 : "+f"(d[0]), "+f"(d[1]), "+f"(d[2]), "+f"(d[3])
                 : "r"(a[0]), "r"(a[1]), "r"(a[2]), "r"(a[3]), "r"(b[0]), "r"(b[1]));
}
__device__ __forceinline__ uint32_t pack2h(float x, float y) {
    uint32_t r;
    asm("cvt.rn.f16x2.f32 %0, %1, %2;" : "=r"(r) : "f"(y), "f"(x));
    return r;
}
__device__ __forceinline__ void split2h(float x, float y, uint32_t& hi, uint32_t& lo) {
    hi = pack2h(x, y);
    __half2 hv = *(__half2*)&hi;
    float rx = x - __low2float(hv);
    float ry = y - __high2float(hv);
    lo = pack2h(rx, ry);
}
__device__ __forceinline__ float2 h2f(uint32_t p) {
    return __half22float2(*(__half2*)&p);
}
__device__ __forceinline__ uint32_t hmul2u(uint32_t a, uint32_t s) {
    __half2 r = __hmul2(*(__half2*)&a, *(__half2*)&s);
    return *(uint32_t*)&r;
}

// ---------------- merged conversion kernel ----------------------------------
__global__ __launch_bounds__(256)
void conv_all_k(const float* __restrict__ X,
                const float* __restrict__ Wa, const float* __restrict__ Wb,
                const float* __restrict__ Wc,
                __half* __restrict__ xhi, __half* __restrict__ xlo,
                __half* __restrict__ oa, __half* __restrict__ ob,
                __half* __restrict__ oc)
{
    __shared__ float t[32][33];
    int bid = blockIdx.x;
    if (bid < 4096) {
        int i = bid * 256 + threadIdx.x;
        float4 v = ((const float4*)X)[i];
        uint32_t h01, l01, h23, l23;
        split2h(v.x, v.y, h01, l01);
        split2h(v.z, v.w, h23, l23);
        ((uint2*)xhi)[i] = make_uint2(h01, h23);
        ((uint2*)xlo)[i] = make_uint2(l01, l23);
        return;
    }
    int r0 = bid - 4096;
    int z = r0 >> 10;
    int rr = r0 & 1023;
    const float* W = (z == 0) ? Wa : (z == 1) ? Wb : Wc;
    __half* o = (z == 0) ? oa : (z == 1) ? ob : oc;
    int n0 = (rr & 31) * 32, k0 = (rr >> 5) * 32;
    int tx = threadIdx.x & 31, ty = threadIdx.x >> 5;
#pragma unroll
    for (int r = 0; r < 4; r++)
        t[ty * 4 + r][tx] = W[(size_t)(k0 + ty * 4 + r) * DD + n0 + tx];
    __syncthreads();
#pragma unroll
    for (int r = 0; r < 4; r++) {
        int n = ty * 4 + r;
        o[(size_t)(n0 + n) * DD + k0 + tx] = __float2half_rn(t[tx][n]);
    }
}

// ---------------- mma.sync GEMM, 3-stage cp.async pipeline ------------------
// DUAL=1: u full split-precision; gate hi-only (sigmoid tolerates ~1e-4).
template<int DUAL>
__global__ __launch_bounds__(512)
void gemm_mma(const __half* __restrict__ Ahi_g, const __half* __restrict__ Alo_g,
              const __half* __restrict__ B1_g, const __half* __restrict__ B2_g,
              const float* __restrict__ b1, const float* __restrict__ b2,
              void* __restrict__ O1v, void* __restrict__ O2v, int m_base)
{
    extern __shared__ char sm[];
    const uint32_t sb = smem_u32(sm);
    const int NT = DUAL ? 4 : 3;
    const uint32_t STAGE = NT * 16384u;
    const int tid = threadIdx.x, wid = tid >> 5, lane = tid & 31;
    const int m0 = m_base + blockIdx.y * 128, n0 = blockIdx.x * 128;
    const int wrow = (wid >> 2) * 32, wcol = (wid & 3) * 32;

    const char* srcs[4];
    srcs[0] = (const char*)Ahi_g + (size_t)m0 * 2048;
    srcs[1] = (const char*)Alo_g + (size_t)m0 * 2048;
    srcs[2] = (const char*)B1_g + (size_t)n0 * 2048;
    if (DUAL) srcs[3] = (const char*)B2_g + (size_t)n0 * 2048;

    float acc1[2][4][4];
    float acc2[2][4][4];
#pragma unroll
    for (int mt = 0; mt < 2; mt++)
#pragma unroll
        for (int nt = 0; nt < 4; nt++)
#pragma unroll
            for (int c = 0; c < 4; c++) { acc1[mt][nt][c] = 0.f; acc2[mt][nt][c] = 0.f; }

    const int aq = lane >> 3, ar = lane & 7;
    const int br = lane & 7, bhh = (lane >> 3) & 1;

    auto load_stage = [&](int s, int kc) {
        uint32_t sbase = sb + (uint32_t)s * STAGE;
#pragma unroll
        for (int t = 0; t < NT; t++) {
            const char* gp = srcs[t] + (size_t)kc * 128;
#pragma unroll
            for (int rep = 0; rep < 2; rep++) {
                int i = rep * 512 + tid;
                int row = i >> 3, c16 = (i & 7) * 16;
                uint32_t so = sbase + t * 16384u + SW(row * 128 + c16);
                CP_ASYNC16(so, gp + (size_t)row * 2048 + c16);
            }
        }
        CP_COMMIT();
    };

    load_stage(0, 0);
    load_stage(1, 1);

    for (int kc = 0; kc < 16; kc++) {
        if (kc + 2 < 16) load_stage((kc + 2) % 3, kc + 2);
        else CP_COMMIT();
        CP_WAIT2();
        __syncthreads();

        uint32_t stb = sb + (uint32_t)(kc % 3) * STAGE;
#pragma unroll
        for (int ks = 0; ks < 4; ks++) {
            int k0 = ks * 16;
            uint32_t aHI[2][4], aLO[2][4];
#pragma unroll
            for (int mt = 0; mt < 2; mt++) {
                int m = wrow + mt * 16 + (aq & 1) * 8 + ar;
                int k = k0 + (aq >> 1) * 8;
                uint32_t off = SW(m * 128 + k * 2);
                ldsm_x4(stb + off, aHI[mt]);
                ldsm_x4(stb + 16384u + off, aLO[mt]);
            }
            uint32_t bF1[4][2], bF2[4][2];
#pragma unroll
            for (int nt = 0; nt < 4; nt++) {
                int n = wcol + nt * 8 + br;
                int k = k0 + bhh * 8;
                uint32_t off = SW(n * 128 + k * 2);
                ldsm_x2(stb + 32768u + off, bF1[nt]);
                if (DUAL) ldsm_x2(stb + 49152u + off, bF2[nt]);
            }
#pragma unroll
            for (int mt = 0; mt < 2; mt++)
#pragma unroll
                for (int nt = 0; nt < 4; nt++) {
                    mma_f16(acc1[mt][nt], aHI[mt], bF1[nt]);
                    mma_f16(acc1[mt][nt], aLO[mt], bF1[nt]);
                }
            if (DUAL) {
#pragma unroll
                for (int mt = 0; mt < 2; mt++)
#pragma unroll
                    for (int nt = 0; nt < 4; nt++)
                        mma_f16(acc2[mt][nt], aHI[mt], bF2[nt]);   // gate: hi-only
            }
        }
        __syncthreads();
    }
    CP_WAIT0();

#pragma unroll
    for (int nt = 0; nt < 4; nt++) {
        int n = n0 + wcol + nt * 8 + (lane & 3) * 2;
        float bv0 = __ldg(&b1[n]), bv1 = __ldg(&b1[n + 1]);
        float gv0 = 0.f, gv1 = 0.f;
        if (DUAL) { gv0 = __ldg(&b2[n]); gv1 = __ldg(&b2[n + 1]); }
#pragma unroll
        for (int mt = 0; mt < 2; mt++) {
            int m = m0 + wrow + mt * 16 + (lane >> 2);
            float v00 = acc1[mt][nt][0] + bv0, v01 = acc1[mt][nt][1] + bv1;
            float v10 = acc1[mt][nt][2] + bv0, v11 = acc1[mt][nt][3] + bv1;
            if (DUAL) {
                __half* U = (__half*)O1v;
                __half* A = (__half*)O2v;
                *(uint32_t*)&U[(size_t)m * 1024 + n]       = pack2h(v00, v01);
                *(uint32_t*)&U[(size_t)(m + 8) * 1024 + n] = pack2h(v10, v11);
                float s0 = 1.f / (1.f + expf(-(acc2[mt][nt][0] + gv0)));
                float s1 = 1.f / (1.f + expf(-(acc2[mt][nt][1] + gv1)));
                float s2 = 1.f / (1.f + expf(-(acc2[mt][nt][2] + gv0)));
                float s3 = 1.f / (1.f + expf(-(acc2[mt][nt][3] + gv1)));
                *(uint32_t*)&A[(size_t)m * 1024 + n]       = pack2h(s0, s1);
                *(uint32_t*)&A[(size_t)(m + 8) * 1024 + n] = pack2h(s2, s3);
            } else {
                __half* Ph = (__half*)O1v;
                __half* Pl = (__half*)O2v;
                uint32_t hi, lo;
                split2h(v00, v01, hi, lo);
                *(uint32_t*)&Ph[(size_t)m * 1024 + n] = hi;
                *(uint32_t*)&Pl[(size_t)m * 1024 + n] = lo;
                split2h(v10, v11, hi, lo);
                *(uint32_t*)&Ph[(size_t)(m + 8) * 1024 + n] = hi;
                *(uint32_t*)&Pl[(size_t)(m + 8) * 1024 + n] = lo;
            }
        }
    }
}
#define SMEM_DUAL   (3u * 4u * 16384u)
#define SMEM_SINGLE (3u * 3u * 16384u)

// ---------------- gated scan (per-batch launches) ----------------------------
__global__ void scan_chunk_k(int b)
{
    int d4 = threadIdx.x;
    int c = blockIdx.x;
    size_t baseh = ((size_t)b * SS + (size_t)c * SCL) * DD + d4 * 4;
    float4 A = make_float4(1.f, 1.f, 1.f, 1.f);
    float4 U = make_float4(0.f, 0.f, 0.f, 0.f);
#pragma unroll
    for (int j = 0; j < SCL; j++) {
        uint2 ar = *(const uint2*)&g_ah[baseh + (size_t)j * DD];
        uint2 ur = *(const uint2*)&g_uh[baseh + (size_t)j * DD];
        float2 a01 = h2f(ar.x), a23 = h2f(ar.y);
        float2 u01 = h2f(ur.x), u23 = h2f(ur.y);
        U.x = a01.x * U.x + u01.x; U.y = a01.y * U.y + u01.y;
        U.z = a23.x * U.z + u23.x; U.w = a23.y * U.w + u23.y;
        A.x *= a01.x; A.y *= a01.y; A.z *= a23.x; A.w *= a23.y;
    }
    size_t o = ((size_t)b * SNC + c) * 256 + d4;
    ((float4*)g_Ac)[o] = A;
    ((float4*)g_Uc)[o] = U;
}

__global__ __launch_bounds__(256)
void scan_prefix_k(int b)
{
    int d4 = blockIdx.x * 8 + (threadIdx.x >> 5);   // 0..255
    int lane = threadIdx.x & 31;

    size_t o0 = ((size_t)b * SNC + lane * 4) * 256 + d4;
    float4 Ac[4], Uc[4];
#pragma unroll
    for (int r = 0; r < 4; r++) {
        Ac[r] = ((const float4*)g_Ac)[o0 + (size_t)r * 256];
        Uc[r] = ((const float4*)g_Uc)[o0 + (size_t)r * 256];
    }
    float4 A = make_float4(1.f, 1.f, 1.f, 1.f);
    float4 U = make_float4(0.f, 0.f, 0.f, 0.f);
#pragma unroll
    for (int r = 0; r < 4; r++) {
        U.x = Ac[r].x * U.x + Uc[r].x; U.y = Ac[r].y * U.y + Uc[r].y;
        U.z = Ac[r].z * U.z + Uc[r].z; U.w = Ac[r].w * U.w + Uc[r].w;
        A.x *= Ac[r].x; A.y *= Ac[r].y; A.z *= Ac[r].z; A.w *= Ac[r].w;
    }
    float4 sA = A, sU = U;
#pragma unroll
    for (int d = 1; d < 32; d <<= 1) {
        float4 tA, tU;
        tA.x = __shfl_up_sync(0xffffffff, sA.x, d);
        tA.y = __shfl_up_sync(0xffffffff, sA.y, d);
        tA.z = __shfl_up_sync(0xffffffff, sA.z, d);
        tA.w = __shfl_up_sync(0xffffffff, sA.w, d);
        tU.x = __shfl_up_sync(0xffffffff, sU.x, d);
        tU.y = __shfl_up_sync(0xffffffff, sU.y, d);
        tU.z = __shfl_up_sync(0xffffffff, sU.z, d);
        tU.w = __shfl_up_sync(0xffffffff, sU.w, d);
        if (lane >= d) {
            sU.x = sA.x * tU.x + sU.x; sU.y = sA.y * tU.y + sU.y;
            sU.z = sA.z * tU.z + sU.z; sU.w = sA.w * tU.w + sU.w;
            sA.x *= tA.x; sA.y *= tA.y; sA.z *= tA.z; sA.w *= tA.w;
        }
    }
    float4 eU;
    eU.x = __shfl_up_sync(0xffffffff, sU.x, 1);
    eU.y = __shfl_up_sync(0xffffffff, sU.y, 1);
    eU.z = __shfl_up_sync(0xffffffff, sU.z, 1);
    eU.w = __shfl_up_sync(0xffffffff, sU.w, 1);
    if (lane == 0) eU = make_float4(0.f, 0.f, 0.f, 0.f);

    float4 h = eU;
#pragma unroll
    for (int r = 0; r < 4; r++) {
        ((float4*)g_P)[o0 + (size_t)r * 256] = h;
        h.x = Ac[r].x * h.x + Uc[r].x; h.y = Ac[r].y * h.y + Uc[r].y;
        h.z = Ac[r].z * h.z + Uc[r].z; h.w = Ac[r].w * h.w + Uc[r].w;
    }
}

__global__ void scan_apply_k(int b)
{
    int d4 = threadIdx.x;
    int c = blockIdx.x;
    float4 h = ((const float4*)g_P)[((size_t)b * SNC + c) * 256 + d4];
    size_t baseh = ((size_t)b * SS + (size_t)c * SCL) * DD + d4 * 4;
    uint2* hh = (uint2*)g_Hhi;
    uint2* hl = (uint2*)g_Hlo;
    size_t base4 = (((size_t)b * SS + (size_t)c * SCL) * DD) / 4 + d4;
#pragma unroll
    for (int j = 0; j < SCL; j++) {
        uint2 ar = *(const uint2*)&g_ah[baseh + (size_t)j * DD];
        uint2 ur = *(const uint2*)&g_uh[baseh + (size_t)j * DD];
        float2 a01 = h2f(ar.x), a23 = h2f(ar.y);
        float2 u01 = h2f(ur.x), u23 = h2f(ur.y);
        h.x = a01.x * h.x + u01.x; h.y = a01.y * h.y + u01.y;
        h.z = a23.x * h.z + u23.x; h.w = a23.y * h.w + u23.y;
        uint32_t h01, l01, h23, l23;
        split2h(h.x, h.y, h01, l01);
        split2h(h.z, h.w, h23, l23);
        hh[base4 + (size_t)j * 256] = make_uint2(h01, h23);
        hl[base4 + (size_t)j * 256] = make_uint2(l01, l23);
    }
}

// ---------------- retention KV branch: M = Kw^T V (independent of mamba) ----
__global__ __launch_bounds__(128)
void ret_kv(const float* __restrict__ kin, const float* __restrict__ vin,
            const float* __restrict__ gammas)
{
    __shared__ __align__(128) char sm[16656];
    const uint32_t sb = smem_u32(sm);
    const uint32_t WS = 0, VS = 8192;
    float* gps = (float*)(sm + 16384);

    int c = blockIdx.x, h = blockIdx.y, b = blockIdx.z;
    int tid = threadIdx.x, wid = tid >> 5, lane = tid & 31;

    if (tid < 65) gps[tid] = powf(gammas[h], (float)tid);
    __syncthreads();

    size_t base = ((size_t)b * SS + (size_t)c * RL) * DD + (size_t)h * HDD;
#pragma unroll
    for (int it = 0; it < 8; it++) {
        int i = it * 128 + tid;
        int row = i >> 4, c4 = (i & 15) << 2;
        size_t ga = base + (size_t)row * DD + c4;
        uint32_t off = SW(row * 128 + c4 * 2);
        float4 kv = *(const float4*)&kin[ga];
        float w = gps[63 - row];
        *(uint2*)(sm + WS + off) =
            make_uint2(pack2h(kv.x * w, kv.y * w), pack2h(kv.z * w, kv.w * w));
        float4 vv = *(const float4*)&vin[ga];
        *(uint2*)(sm + VS + off) = make_uint2(pack2h(vv.x, vv.y), pack2h(vv.z, vv.w));
    }
    __syncthreads();

    const int R = wid * 16;
    const int l2 = lane & 15;
    const int lg = lane >> 3, lr = lane & 7;

    float mc[8][4];
#pragma unroll
    for (int nb = 0; nb < 8; nb++)
#pragma unroll
        for (int r = 0; r < 4; r++) mc[nb][r] = 0.f;

#pragma unroll
    for (int kk = 0; kk < 4; kk++) {
        int k0 = kk * 16;
        uint32_t aK[4];
        {
            int jrow = k0 + ((lg & 2) ? 8 : 0) + lr;
            int mcol = R + ((lg & 1) ? 8 : 0);
            uint32_t off = SW(jrow * 128 + mcol * 2);
            ldsm_x4_t(sb + WS + off, aK);
        }
#pragma unroll
        for (int nb = 0; nb < 8; nb++) {
            int n = nb * 8;
            int jrow = k0 + l2;
            uint32_t off = SW(jrow * 128 + n * 2);
            uint32_t bV[2];
            ldsm_x2_t(sb + VS + off, bV);
            mma_f16(mc[nb], aK, bV);
        }
    }

    const int rb = R + (lane >> 2);
    const int cb = (lane & 3) * 2;
    size_t mb = (((size_t)(b * HH + h)) * RNC + c) * 4096;
#pragma unroll
    for (int nb = 0; nb < 8; nb++) {
        int col = nb * 8 + cb;
        *(float2*)&g_M[mb + (size_t)rb * 64 + col]       = make_float2(mc[nb][0], mc[nb][1]);
        *(float2*)&g_M[mb + (size_t)(rb + 8) * 64 + col] = make_float2(mc[nb][2], mc[nb][3]);
    }
}

// ---------------- retention state scan over chunks ---------------------------
__global__ void ret_scan_k(const float* __restrict__ gammas)
{
    int idx = blockIdx.x * 256 + threadIdx.x;
    int e  = idx & 4095;
    int bh2 = idx >> 12;
    int h  = bh2 & (HH - 1);
    float gL = powf(gammas[h], (float)RL);
    float s = 0.f;
#pragma unroll
    for (int c = 0; c < RNC; c++) {
        size_t o = ((size_t)bh2 * RNC + c) * 4096 + e;
        g_Sp[o] = s;
        s = gL * s + g_M[o];
    }
}

// ---------------- fused retention q-path (per-batch) -------------------------
#define RQ_QH 0u
#define RQ_QL 8192u
#define RQ_KS 16384u
#define RQ_VS 24576u
#define RQ_SP 32768u
#define RQ_GP 40960u

__global__ __launch_bounds__(128)
void ret_q(const float* __restrict__ kin, const float* __restrict__ vin,
           const float* __restrict__ gammas, float* __restrict__ out, int bpar)
{
    __shared__ __align__(128) char sm[41232];
    const uint32_t sb = smem_u32(sm);
    float* gps = (float*)(sm + RQ_GP);

    int c = blockIdx.x, h = blockIdx.y, b = bpar;
    int tid = threadIdx.x, wid = tid >> 5, lane = tid & 31;

    if (tid < 65) gps[tid] = powf(gammas[h], (float)tid);
    __syncthreads();

    const uint32_t eighth = pack2h(0.125f, 0.125f);
    size_t base = ((size_t)b * SS + (size_t)c * RL) * DD + (size_t)h * HDD;
    size_t sbo  = (((size_t)(b * HH + h)) * RNC + c) * 4096;
#pragma unroll
    for (int it = 0; it < 8; it++) {
        int i = it * 128 + tid;
        int row = i >> 4, c4 = (i & 15) << 2;
        size_t ga = base + (size_t)row * DD + c4;
        uint32_t off = SW(row * 128 + c4 * 2);

        uint2 qh = *(const uint2*)&g_QPh[ga];
        uint2 ql = *(const uint2*)&g_QPl[ga];
        *(uint2*)(sm + RQ_QH + off) = make_uint2(hmul2u(qh.x, eighth), hmul2u(qh.y, eighth));
        *(uint2*)(sm + RQ_QL + off) = make_uint2(hmul2u(ql.x, eighth), hmul2u(ql.y, eighth));

        float4 kv = *(const float4*)&kin[ga];
        *(uint2*)(sm + RQ_KS + off) = make_uint2(pack2h(kv.x, kv.y), pack2h(kv.z, kv.w));

        float4 vv = *(const float4*)&vin[ga];
        *(uint2*)(sm + RQ_VS + off) = make_uint2(pack2h(vv.x, vv.y), pack2h(vv.z, vv.w));

        float4 sv = *(const float4*)&g_Sp[sbo + (size_t)row * 64 + c4];
        *(uint2*)(sm + RQ_SP + off) = make_uint2(pack2h(sv.x, sv.y), pack2h(sv.z, sv.w));
    }
    __syncthreads();

    const int R = wid * 16;
    const int aq = lane >> 3, ar = lane & 7;
    const int br = lane & 7, bhh = (lane >> 3) & 1;
    const int l2 = lane & 15;

    float c_[8][4], o2[8][4];
#pragma unroll
    for (int nb = 0; nb < 8; nb++)
#pragma unroll
        for (int r = 0; r < 4; r++) { c_[nb][r] = 0.f; o2[nb][r] = 0.f; }

#pragma unroll
    for (int ks = 0; ks < 4; ks++) {
        int k0 = ks * 16;
        uint32_t aH[4], aL[4];
        {
            int m = R + (aq & 1) * 8 + ar;
            int k = k0 + (aq >> 1) * 8;
            uint32_t off = SW(m * 128 + k * 2);
            ldsm_x4(sb + RQ_QH + off, aH);
            ldsm_x4(sb + RQ_QL + off, aL);
        }
#pragma unroll
        for (int nb = 0; nb < 8; nb++) {
            int n = nb * 8 + br;
            int k = k0 + bhh * 8;
            uint32_t off = SW(n * 128 + k * 2);
            uint32_t bK[2];
            ldsm_x2(sb + RQ_KS + off, bK);
            mma_f16(c_[nb], aH, bK);
            mma_f16(c_[nb], aL, bK);
        }
#pragma unroll
        for (int nb = 0; nb < 8; nb++) {
            int n = nb * 8;
            int krow = k0 + l2;
            uint32_t off = SW(krow * 128 + n * 2);
            uint32_t bS[2];
            ldsm_x2_t(sb + RQ_SP + off, bS);
            mma_f16(o2[nb], aH, bS);
            mma_f16(o2[nb], aL, bS);
        }
    }

    const int rb = R + (lane >> 2);
    const int cb = (lane & 3) * 2;
#pragma unroll
    for (int nb = 0; nb < 8; nb++) {
        int col0 = nb * 8 + cb;
        c_[nb][0] *= (rb >= col0)         ? gps[rb - col0]         : 0.f;
        c_[nb][1] *= (rb >= col0 + 1)     ? gps[rb - col0 - 1]     : 0.f;
        c_[nb][2] *= (rb + 8 >= col0)     ? gps[rb + 8 - col0]     : 0.f;
        c_[nb][3] *= (rb + 8 >= col0 + 1) ? gps[rb + 8 - col0 - 1] : 0.f;
    }

    float oc[8][4];
#pragma unroll
    for (int nb = 0; nb < 8; nb++)
#pragma unroll
        for (int r = 0; r < 4; r++) oc[nb][r] = 0.f;

#pragma unroll
    for (int kk = 0; kk < 4; kk++) {
        int k0 = kk * 16;
        uint32_t aPh[4], aPl[4];
        split2h(c_[2 * kk][0],     c_[2 * kk][1],     aPh[0], aPl[0]);
        split2h(c_[2 * kk][2],     c_[2 * kk][3],     aPh[1], aPl[1]);
        split2h(c_[2 * kk + 1][0], c_[2 * kk + 1][1], aPh[2], aPl[2]);
        split2h(c_[2 * kk + 1][2], c_[2 * kk + 1][3], aPh[3], aPl[3]);
#pragma unroll
        for (int nb = 0; nb < 8; nb++) {
            int n = nb * 8;
            int jrow = k0 + l2;
            uint32_t off = SW(jrow * 128 + n * 2);
            uint32_t bV[2];
            ldsm_x2_t(sb + RQ_VS + off, bV);
            mma_f16(oc[nb], aPh, bV);
            mma_f16(oc[nb], aPl, bV);
        }
    }

    float g0 = gps[rb + 1];
    float g1 = gps[rb + 9];
#pragma unroll
    for (int nb = 0; nb < 8; nb++) {
        int col = nb * 8 + cb;
        *(float2*)&out[base + (size_t)rb * DD + col] =
            make_float2(oc[nb][0] + g0 * o2[nb][0], oc[nb][1] + g0 * o2[nb][1]);
        *(float2*)&out[base + (size_t)(rb + 8) * DD + col] =
            make_float2(oc[nb][2] + g1 * o2[nb][2], oc[nb][3] + g1 * o2[nb][3]);
    }
}

// ---------------- launch ---------------------------------------------------
extern "C" void kernel_launch(void* const* d_in, const int* in_sizes, int n_in,
                              void* d_out, int out_size)
{
    const float* q      = (const float*)d_in[0];
    const float* k      = (const float*)d_in[1];
    const float* v      = (const float*)d_in[2];
    const float* W_in   = (const float*)d_in[3];
    const float* b_in   = (const float*)d_in[4];
    const float* W_gate = (const float*)d_in[5];
    const float* b_gate = (const float*)d_in[6];
    const float* W_out  = (const float*)d_in[7];
    const float* b_out  = (const float*)d_in[8];
    const float* gammas = (const float*)d_in[9];
    float* out = (float*)d_out;

    void *puh, *pah;
    void *pxh, *pxl, *phh, *phl, *pqh, *pql, *pw1, *pw2, *pw3;
    cudaGetSymbolAddress(&puh, g_uh);
    cudaGetSymbolAddress(&pah, g_ah);
    cudaGetSymbolAddress(&pxh, g_Xhi);  cudaGetSymbolAddress(&pxl, g_Xlo);
    cudaGetSymbolAddress(&phh, g_Hhi);  cudaGetSymbolAddress(&phl, g_Hlo);
    cudaGetSymbolAddress(&pqh, g_QPh);  cudaGetSymbolAddress(&pql, g_QPl);
    cudaGetSymbolAddress(&pw1, g_W1);
    cudaGetSymbolAddress(&pw2, g_W2);
    cudaGetSymbolAddress(&pw3, g_W3);

    cudaFuncSetAttribute(gemm_mma<1>, cudaFuncAttributeMaxDynamicSharedMemorySize, SMEM_DUAL);
    cudaFuncSetAttribute(gemm_mma<0>, cudaFuncAttributeMaxDynamicSharedMemorySize, SMEM_SINGLE);

    // streams/events: created per call, never destroyed (capture-safe; no device mem)
    cudaStream_t s2;
    cudaStreamCreateWithFlags(&s2, cudaStreamNonBlocking);
    cudaEvent_t evF, evJ, e1, eEnd;
    cudaEventCreateWithFlags(&evF, cudaEventDisableTiming);
    cudaEventCreateWithFlags(&evJ, cudaEventDisableTiming);
    cudaEventCreateWithFlags(&e1,  cudaEventDisableTiming);
    cudaEventCreateWithFlags(&eEnd, cudaEventDisableTiming);

    cudaEventRecord(evF, 0);
    cudaStreamWaitEvent(s2, evF, 0);
    // branch B (s2): KV state path — needs only k, v, gammas
    ret_kv<<<dim3(RNC, HH, BB), 128, 0, s2>>>(k, v, gammas);
    ret_scan_k<<<(BB * HH * HDD * HDD) / 256, 256, 0, s2>>>(gammas);
    cudaEventRecord(evJ, s2);

    // branch A (s0): conversions + gemm1 batch 0
    conv_all_k<<<4096 + 3072, 256>>>(q, W_in, W_gate, W_out,
        (__half*)pxh, (__half*)pxl,
        (__half*)pw1, (__half*)pw2, (__half*)pw3);

    dim3 gh(8, 16);   // half-batch tile grid (128 CTAs)
    gemm_mma<1><<<gh, 512, SMEM_DUAL>>>(
        (const __half*)pxh, (const __half*)pxl,
        (const __half*)pw1, (const __half*)pw2,
        b_in, b_gate, puh, pah, 0);
    cudaEventRecord(e1, 0);

    // s0: gemm1 batch 1 while s2 runs scans for batch 0
    gemm_mma<1><<<gh, 512, SMEM_DUAL>>>(
        (const __half*)pxh, (const __half*)pxl,
        (const __half*)pw1, (const __half*)pw2,
        b_in, b_gate, puh, pah, 2048);

    cudaStreamWaitEvent(s2, e1, 0);
    scan_chunk_k <<<SNC, 256, 0, s2>>>(0);
    scan_prefix_k<<<32, 256, 0, s2>>>(0);
    scan_apply_k <<<SNC, 256, 0, s2>>>(0);
    // s2: gemm2 batch 0, then fused retention q-path batch 0
    gemm_mma<0><<<gh, 512, SMEM_SINGLE, s2>>>(
        (const __half*)phh, (const __half*)phl,
        (const __half*)pw3, nullptr,
        b_out, nullptr, pqh, pql, 0);
    ret_q<<<dim3(RNC, HH), 128, 0, s2>>>(k, v, gammas, out, 0);
    cudaEventRecord(eEnd, s2);

    // s0: scans batch 1, gemm2 batch 1, retention q-path batch 1
    scan_chunk_k <<<SNC, 256>>>(1);
    scan_prefix_k<<<32, 256>>>(1);
    scan_apply_k <<<SNC, 256>>>(1);
    gemm_mma<0><<<gh, 512, SMEM_SINGLE>>>(
        (const __half*)phh, (const __half*)phl,
        (const __half*)pw3, nullptr,
        b_out, nullptr, pqh, pql, 2048);
    cudaStreamWaitEvent(0, evJ, 0);
    ret_q<<<dim3(RNC, HH), 128>>>(k, v, gammas, out, 1);

    // join forked work back into the origin stream (graph sink)
    cudaStreamWaitEvent(0, eEnd, 0);
}

// round 11
// speedup vs baseline: 5.6874x; 1.2538x over previous
#include <cuda_runtime.h>
#include <cuda_fp16.h>
#include <math.h>
#include <stdint.h>

#define BB  2
#define SS  2048
#define DD  1024
#define HH  16
#define HDD 64
#define MM  (BB*SS)
#define SCL 16            // scan chunk length
#define SNC (SS/SCL)      // 128 scan chunks
#define RL  64            // retention chunk length
#define RNC (SS/RL)       // 32 retention chunks

// ---------------- scratch ---------------------------------------------------
__device__ __half g_uh[MM*DD];                  // u (fp16)
__device__ __half g_ah[MM*DD];                  // a (fp16)
__device__ float g_Ac[BB*SNC*DD];
__device__ float g_Uc[BB*SNC*DD];
__device__ float g_P [BB*SNC*DD];
__device__ float g_M [BB*HH*RNC*HDD*HDD];
__device__ float g_Sp[BB*HH*RNC*HDD*HDD];

__device__ __half g_Xhi[MM*DD];                 // q fp16
__device__ __half g_Hhi[MM*DD];                 // h fp16 (from scan)
__device__ __half g_QPh[MM*DD], g_QPl[MM*DD];   // q_proj split (fp16)
__device__ __half g_W1[DD*DD];                  // W_in^T fp16
__device__ __half g_W2[DD*DD];                  // W_gate^T fp16
__device__ __half g_W3[DD*DD];                  // W_out^T fp16

// ---------------- helpers ---------------------------------------------------
__device__ __forceinline__ uint32_t smem_u32(const void* p) {
    uint32_t a;
    asm("{ .reg .u64 t; cvta.to.shared.u64 t, %1; cvt.u32.u64 %0, t; }"
        : "=r"(a) : "l"(p));
    return a;
}
#define SW(o) ((o) ^ ((((uint32_t)(o)) >> 3) & 0x70))

#define CP_ASYNC16(dst, src) \
    asm volatile("cp.async.cg.shared.global [%0], [%1], 16;" :: "r"(dst), "l"(src))
#define CP_COMMIT() asm volatile("cp.async.commit_group;" ::: "memory")
#define CP_WAIT2()  asm volatile("cp.async.wait_group 2;" ::: "memory")
#define CP_WAIT0()  asm volatile("cp.async.wait_group 0;" ::: "memory")

__device__ __forceinline__ void ldsm_x4(uint32_t addr, uint32_t* r) {
    asm volatile("ldmatrix.sync.aligned.m8n8.x4.shared.b16 {%0,%1,%2,%3}, [%4];"
                 : "=r"(r[0]), "=r"(r[1]), "=r"(r[2]), "=r"(r[3]) : "r"(addr));
}
__device__ __forceinline__ void ldsm_x2(uint32_t addr, uint32_t* r) {
    asm volatile("ldmatrix.sync.aligned.m8n8.x2.shared.b16 {%0,%1}, [%2];"
                 : "=r"(r[0]), "=r"(r[1]) : "r"(addr));
}
__device__ __forceinline__ void ldsm_x4_t(uint32_t addr, uint32_t* r) {
    asm volatile("ldmatrix.sync.aligned.m8n8.x4.trans.shared.b16 {%0,%1,%2,%3}, [%4];"
                 : "=r"(r[0]), "=r"(r[1]), "=r"(r[2]), "=r"(r[3]) : "r"(addr));
}
__device__ __forceinline__ void ldsm_x2_t(uint32_t addr, uint32_t* r) {
    asm volatile("ldmatrix.sync.aligned.m8n8.x2.trans.shared.b16 {%0,%1}, [%2];"
                 : "=r"(r[0]), "=r"(r[1]) : "r"(addr));
}
__device__ __forceinline__ void mma_f16(float* d, const uint32_t* a, const uint32_t* b) {
    asm volatile("mma.sync.aligned.m16n8k16.row.col.f32.f16.f16.f32 "
                 "{%0,%1,%2,%3}, {%4,%5,%6,%7}, {%8,%9}, {%0,%1,%2,%3};"
                 : "+f"(d[0]), "+f"(d[1]), "+f"(d[2]), "+f"(d[3])
                 : "r"(a[0]), "r"(a[1]), "r"(a[2]), "r"(a[3]), "r"(b[0]), "r"(b[1]));
}
__device__ __forceinline__ uint32_t pack2h(float x, float y) {
    uint32_t r;
    asm("cvt.rn.f16x2.f32 %0, %1, %2;" : "=r"(r) : "f"(y), "f"(x));
    return r;
}
__device__ __forceinline__ void split2h(float x, float y, uint32_t& hi, uint32_t& lo) {
    hi = pack2h(x, y);
    __half2 hv = *(__half2*)&hi;
    float rx = x - __low2float(hv);
    float ry = y - __high2float(hv);
    lo = pack2h(rx, ry);
}
__device__ __forceinline__ float2 h2f(uint32_t p) {
    return __half22float2(*(__half2*)&p);
}
__device__ __forceinline__ uint32_t hmul2u(uint32_t a, uint32_t s) {
    __half2 r = __hmul2(*(__half2*)&a, *(__half2*)&s);
    return *(uint32_t*)&r;
}

// ---------------- merged conversion kernel ----------------------------------
// blocks [0, 4096): q -> Xhi fp16. blocks [4096, 7168): W transpose+fp16.
__global__ __launch_bounds__(256)
void conv_all_k(const float* __restrict__ X,
                const float* __restrict__ Wa, const float* __restrict__ Wb,
                const float* __restrict__ Wc,
                __half* __restrict__ xhi,
                __half* __restrict__ oa, __half* __restrict__ ob,
                __half* __restrict__ oc)
{
    __shared__ float t[32][33];
    int bid = blockIdx.x;
    if (bid < 4096) {
        int i = bid * 256 + threadIdx.x;
        float4 v = ((const float4*)X)[i];
        ((uint2*)xhi)[i] = make_uint2(pack2h(v.x, v.y), pack2h(v.z, v.w));
        return;
    }
    int r0 = bid - 4096;
    int z = r0 >> 10;
    int rr = r0 & 1023;
    const float* W = (z == 0) ? Wa : (z == 1) ? Wb : Wc;
    __half* o = (z == 0) ? oa : (z == 1) ? ob : oc;
    int n0 = (rr & 31) * 32, k0 = (rr >> 5) * 32;
    int tx = threadIdx.x & 31, ty = threadIdx.x >> 5;
#pragma unroll
    for (int r = 0; r < 4; r++)
        t[ty * 4 + r][tx] = W[(size_t)(k0 + ty * 4 + r) * DD + n0 + tx];
    __syncthreads();
#pragma unroll
    for (int r = 0; r < 4; r++) {
        int n = ty * 4 + r;
        o[(size_t)(n0 + n) * DD + k0 + tx] = __float2half_rn(t[tx][n]);
    }
}

// ---------------- mma.sync GEMM, 3-stage cp.async pipeline ------------------
// Hi-only A (fp16). DUAL=1: u + sigmoid gate (fp16 outputs).
// DUAL=0: q_proj, output split hi/lo fp16 (output split is free).
template<int DUAL>
__global__ __launch_bounds__(512)
void gemm_mma(const __half* __restrict__ Ahi_g,
              const __half* __restrict__ B1_g, const __half* __restrict__ B2_g,
              const float* __restrict__ b1, const float* __restrict__ b2,
              void* __restrict__ O1v, void* __restrict__ O2v, int m_base)
{
    extern __shared__ char sm[];
    const uint32_t sb = smem_u32(sm);
    const int NT = DUAL ? 3 : 2;
    const uint32_t STAGE = NT * 16384u;
    const int tid = threadIdx.x, wid = tid >> 5, lane = tid & 31;
    const int m0 = m_base + blockIdx.y * 128, n0 = blockIdx.x * 128;
    const int wrow = (wid >> 2) * 32, wcol = (wid & 3) * 32;

    const char* srcs[3];
    srcs[0] = (const char*)Ahi_g + (size_t)m0 * 2048;
    srcs[1] = (const char*)B1_g + (size_t)n0 * 2048;
    if (DUAL) srcs[2] = (const char*)B2_g + (size_t)n0 * 2048;

    float acc1[2][4][4];
    float acc2[2][4][4];
#pragma unroll
    for (int mt = 0; mt < 2; mt++)
#pragma unroll
        for (int nt = 0; nt < 4; nt++)
#pragma unroll
            for (int c = 0; c < 4; c++) { acc1[mt][nt][c] = 0.f; acc2[mt][nt][c] = 0.f; }

    const int aq = lane >> 3, ar = lane & 7;
    const int br = lane & 7, bhh = (lane >> 3) & 1;

    auto load_stage = [&](int s, int kc) {
        uint32_t sbase = sb + (uint32_t)s * STAGE;
#pragma unroll
        for (int t = 0; t < NT; t++) {
            const char* gp = srcs[t] + (size_t)kc * 128;
#pragma unroll
            for (int rep = 0; rep < 2; rep++) {
                int i = rep * 512 + tid;
                int row = i >> 3, c16 = (i & 7) * 16;
                uint32_t so = sbase + t * 16384u + SW(row * 128 + c16);
                CP_ASYNC16(so, gp + (size_t)row * 2048 + c16);
            }
        }
        CP_COMMIT();
    };

    load_stage(0, 0);
    load_stage(1, 1);

    for (int kc = 0; kc < 16; kc++) {
        if (kc + 2 < 16) load_stage((kc + 2) % 3, kc + 2);
        else CP_COMMIT();
        CP_WAIT2();
        __syncthreads();

        uint32_t stb = sb + (uint32_t)(kc % 3) * STAGE;
#pragma unroll
        for (int ks = 0; ks < 4; ks++) {
            int k0 = ks * 16;
            uint32_t aHI[2][4];
#pragma unroll
            for (int mt = 0; mt < 2; mt++) {
                int m = wrow + mt * 16 + (aq & 1) * 8 + ar;
                int k = k0 + (aq >> 1) * 8;
                uint32_t off = SW(m * 128 + k * 2);
                ldsm_x4(stb + off, aHI[mt]);
            }
            uint32_t bF1[4][2], bF2[4][2];
#pragma unroll
            for (int nt = 0; nt < 4; nt++) {
                int n = wcol + nt * 8 + br;
                int k = k0 + bhh * 8;
                uint32_t off = SW(n * 128 + k * 2);
                ldsm_x2(stb + 16384u + off, bF1[nt]);
                if (DUAL) ldsm_x2(stb + 32768u + off, bF2[nt]);
            }
#pragma unroll
            for (int mt = 0; mt < 2; mt++)
#pragma unroll
                for (int nt = 0; nt < 4; nt++) {
                    mma_f16(acc1[mt][nt], aHI[mt], bF1[nt]);
                    if (DUAL) mma_f16(acc2[mt][nt], aHI[mt], bF2[nt]);
                }
        }
        __syncthreads();
    }
    CP_WAIT0();

#pragma unroll
    for (int nt = 0; nt < 4; nt++) {
        int n = n0 + wcol + nt * 8 + (lane & 3) * 2;
        float bv0 = __ldg(&b1[n]), bv1 = __ldg(&b1[n + 1]);
        float gv0 = 0.f, gv1 = 0.f;
        if (DUAL) { gv0 = __ldg(&b2[n]); gv1 = __ldg(&b2[n + 1]); }
#pragma unroll
        for (int mt = 0; mt < 2; mt++) {
            int m = m0 + wrow + mt * 16 + (lane >> 2);
            float v00 = acc1[mt][nt][0] + bv0, v01 = acc1[mt][nt][1] + bv1;
            float v10 = acc1[mt][nt][2] + bv0, v11 = acc1[mt][nt][3] + bv1;
            if (DUAL) {
                __half* U = (__half*)O1v;
                __half* A = (__half*)O2v;
                *(uint32_t*)&U[(size_t)m * 1024 + n]       = pack2h(v00, v01);
                *(uint32_t*)&U[(size_t)(m + 8) * 1024 + n] = pack2h(v10, v11);
                float s0 = 1.f / (1.f + expf(-(acc2[mt][nt][0] + gv0)));
                float s1 = 1.f / (1.f + expf(-(acc2[mt][nt][1] + gv1)));
                float s2 = 1.f / (1.f + expf(-(acc2[mt][nt][2] + gv0)));
                float s3 = 1.f / (1.f + expf(-(acc2[mt][nt][3] + gv1)));
                *(uint32_t*)&A[(size_t)m * 1024 + n]       = pack2h(s0, s1);
                *(uint32_t*)&A[(size_t)(m + 8) * 1024 + n] = pack2h(s2, s3);
            } else {
                __half* Ph = (__half*)O1v;
                __half* Pl = (__half*)O2v;
                uint32_t hi, lo;
                split2h(v00, v01, hi, lo);
                *(uint32_t*)&Ph[(size_t)m * 1024 + n] = hi;
                *(uint32_t*)&Pl[(size_t)m * 1024 + n] = lo;
                split2h(v10, v11, hi, lo);
                *(uint32_t*)&Ph[(size_t)(m + 8) * 1024 + n] = hi;
                *(uint32_t*)&Pl[(size_t)(m + 8) * 1024 + n] = lo;
            }
        }
    }
}
#define SMEM_DUAL   (3u * 3u * 16384u)   // 147456
#define SMEM_SINGLE (3u * 2u * 16384u)   // 98304

// ---------------- gated scan (per-batch launches) ----------------------------
__global__ void scan_chunk_k(int b)
{
    int d4 = threadIdx.x;
    int c = blockIdx.x;
    size_t baseh = ((size_t)b * SS + (size_t)c * SCL) * DD + d4 * 4;
    float4 A = make_float4(1.f, 1.f, 1.f, 1.f);
    float4 U = make_float4(0.f, 0.f, 0.f, 0.f);
#pragma unroll
    for (int j = 0; j < SCL; j++) {
        uint2 ar = *(const uint2*)&g_ah[baseh + (size_t)j * DD];
        uint2 ur = *(const uint2*)&g_uh[baseh + (size_t)j * DD];
        float2 a01 = h2f(ar.x), a23 = h2f(ar.y);
        float2 u01 = h2f(ur.x), u23 = h2f(ur.y);
        U.x = a01.x * U.x + u01.x; U.y = a01.y * U.y + u01.y;
        U.z = a23.x * U.z + u23.x; U.w = a23.y * U.w + u23.y;
        A.x *= a01.x; A.y *= a01.y; A.z *= a23.x; A.w *= a23.y;
    }
    size_t o = ((size_t)b * SNC + c) * 256 + d4;
    ((float4*)g_Ac)[o] = A;
    ((float4*)g_Uc)[o] = U;
}

__global__ __launch_bounds__(256)
void scan_prefix_k(int b)
{
    int d4 = blockIdx.x * 8 + (threadIdx.x >> 5);
    int lane = threadIdx.x & 31;

    size_t o0 = ((size_t)b * SNC + lane * 4) * 256 + d4;
    float4 Ac[4], Uc[4];
#pragma unroll
    for (int r = 0; r < 4; r++) {
        Ac[r] = ((const float4*)g_Ac)[o0 + (size_t)r * 256];
        Uc[r] = ((const float4*)g_Uc)[o0 + (size_t)r * 256];
    }
    float4 A = make_float4(1.f, 1.f, 1.f, 1.f);
    float4 U = make_float4(0.f, 0.f, 0.f, 0.f);
#pragma unroll
    for (int r = 0; r < 4; r++) {
        U.x = Ac[r].x * U.x + Uc[r].x; U.y = Ac[r].y * U.y + Uc[r].y;
        U.z = Ac[r].z * U.z + Uc[r].z; U.w = Ac[r].w * U.w + Uc[r].w;
        A.x *= Ac[r].x; A.y *= Ac[r].y; A.z *= Ac[r].z; A.w *= Ac[r].w;
    }
    float4 sA = A, sU = U;
#pragma unroll
    for (int d = 1; d < 32; d <<= 1) {
        float4 tA, tU;
        tA.x = __shfl_up_sync(0xffffffff, sA.x, d);
        tA.y = __shfl_up_sync(0xffffffff, sA.y, d);
        tA.z = __shfl_up_sync(0xffffffff, sA.z, d);
        tA.w = __shfl_up_sync(0xffffffff, sA.w, d);
        tU.x = __shfl_up_sync(0xffffffff, sU.x, d);
        tU.y = __shfl_up_sync(0xffffffff, sU.y, d);
        tU.z = __shfl_up_sync(0xffffffff, sU.z, d);
        tU.w = __shfl_up_sync(0xffffffff, sU.w, d);
        if (lane >= d) {
            sU.x = sA.x * tU.x + sU.x; sU.y = sA.y * tU.y + sU.y;
            sU.z = sA.z * tU.z + sU.z; sU.w = sA.w * tU.w + sU.w;
            sA.x *= tA.x; sA.y *= tA.y; sA.z *= tA.z; sA.w *= tA.w;
        }
    }
    float4 eU;
    eU.x = __shfl_up_sync(0xffffffff, sU.x, 1);
    eU.y = __shfl_up_sync(0xffffffff, sU.y, 1);
    eU.z = __shfl_up_sync(0xffffffff, sU.z, 1);
    eU.w = __shfl_up_sync(0xffffffff, sU.w, 1);
    if (lane == 0) eU = make_float4(0.f, 0.f, 0.f, 0.f);

    float4 h = eU;
#pragma unroll
    for (int r = 0; r < 4; r++) {
        ((float4*)g_P)[o0 + (size_t)r * 256] = h;
        h.x = Ac[r].x * h.x + Uc[r].x; h.y = Ac[r].y * h.y + Uc[r].y;
        h.z = Ac[r].z * h.z + Uc[r].z; h.w = Ac[r].w * h.w + Uc[r].w;
    }
}

__global__ void scan_apply_k(int b)
{
    int d4 = threadIdx.x;
    int c = blockIdx.x;
    float4 h = ((const float4*)g_P)[((size_t)b * SNC + c) * 256 + d4];
    size_t baseh = ((size_t)b * SS + (size_t)c * SCL) * DD + d4 * 4;
    uint2* hh = (uint2*)g_Hhi;
    size_t base4 = (((size_t)b * SS + (size_t)c * SCL) * DD) / 4 + d4;
#pragma unroll
    for (int j = 0; j < SCL; j++) {
        uint2 ar = *(const uint2*)&g_ah[baseh + (size_t)j * DD];
        uint2 ur = *(const uint2*)&g_uh[baseh + (size_t)j * DD];
        float2 a01 = h2f(ar.x), a23 = h2f(ar.y);
        float2 u01 = h2f(ur.x), u23 = h2f(ur.y);
        h.x = a01.x * h.x + u01.x; h.y = a01.y * h.y + u01.y;
        h.z = a23.x * h.z + u23.x; h.w = a23.y * h.w + u23.y;
        hh[base4 + (size_t)j * 256] = make_uint2(pack2h(h.x, h.y), pack2h(h.z, h.w));
    }
}

// ---------------- retention KV branch: M = Kw^T V ----------------------------
__global__ __launch_bounds__(128)
void ret_kv(const float* __restrict__ kin, const float* __restrict__ vin,
            const float* __restrict__ gammas)
{
    __shared__ __align__(128) char sm[16656];
    const uint32_t sb = smem_u32(sm);
    const uint32_t WS = 0, VS = 8192;
    float* gps = (float*)(sm + 16384);

    int c = blockIdx.x, h = blockIdx.y, b = blockIdx.z;
    int tid = threadIdx.x, wid = tid >> 5, lane = tid & 31;

    if (tid < 65) gps[tid] = powf(gammas[h], (float)tid);
    __syncthreads();

    size_t base = ((size_t)b * SS + (size_t)c * RL) * DD + (size_t)h * HDD;
#pragma unroll
    for (int it = 0; it < 8; it++) {
        int i = it * 128 + tid;
        int row = i >> 4, c4 = (i & 15) << 2;
        size_t ga = base + (size_t)row * DD + c4;
        uint32_t off = SW(row * 128 + c4 * 2);
        float4 kv = *(const float4*)&kin[ga];
        float w = gps[63 - row];
        *(uint2*)(sm + WS + off) =
            make_uint2(pack2h(kv.x * w, kv.y * w), pack2h(kv.z * w, kv.w * w));
        float4 vv = *(const float4*)&vin[ga];
        *(uint2*)(sm + VS + off) = make_uint2(pack2h(vv.x, vv.y), pack2h(vv.z, vv.w));
    }
    __syncthreads();

    const int R = wid * 16;
    const int l2 = lane & 15;
    const int lg = lane >> 3, lr = lane & 7;

    float mc[8][4];
#pragma unroll
    for (int nb = 0; nb < 8; nb++)
#pragma unroll
        for (int r = 0; r < 4; r++) mc[nb][r] = 0.f;

#pragma unroll
    for (int kk = 0; kk < 4; kk++) {
        int k0 = kk * 16;
        uint32_t aK[4];
        {
            int jrow = k0 + ((lg & 2) ? 8 : 0) + lr;
            int mcol = R + ((lg & 1) ? 8 : 0);
            uint32_t off = SW(jrow * 128 + mcol * 2);
            ldsm_x4_t(sb + WS + off, aK);
        }
#pragma unroll
        for (int nb = 0; nb < 8; nb++) {
            int n = nb * 8;
            int jrow = k0 + l2;
            uint32_t off = SW(jrow * 128 + n * 2);
            uint32_t bV[2];
            ldsm_x2_t(sb + VS + off, bV);
            mma_f16(mc[nb], aK, bV);
        }
    }

    const int rb = R + (lane >> 2);
    const int cb = (lane & 3) * 2;
    size_t mb = (((size_t)(b * HH + h)) * RNC + c) * 4096;
#pragma unroll
    for (int nb = 0; nb < 8; nb++) {
        int col = nb * 8 + cb;
        *(float2*)&g_M[mb + (size_t)rb * 64 + col]       = make_float2(mc[nb][0], mc[nb][1]);
        *(float2*)&g_M[mb + (size_t)(rb + 8) * 64 + col] = make_float2(mc[nb][2], mc[nb][3]);
    }
}

// ---------------- retention state scan over chunks ---------------------------
__global__ void ret_scan_k(const float* __restrict__ gammas)
{
    int idx = blockIdx.x * 256 + threadIdx.x;
    int e  = idx & 4095;
    int bh2 = idx >> 12;
    int h  = bh2 & (HH - 1);
    float gL = powf(gammas[h], (float)RL);
    float s = 0.f;
#pragma unroll
    for (int c = 0; c < RNC; c++) {
        size_t o = ((size_t)bh2 * RNC + c) * 4096 + e;
        g_Sp[o] = s;
        s = gL * s + g_M[o];
    }
}

// ---------------- fused retention q-path (per-batch) -------------------------
#define RQ_QH 0u
#define RQ_QL 8192u
#define RQ_KS 16384u
#define RQ_VS 24576u
#define RQ_SP 32768u
#define RQ_GP 40960u

__global__ __launch_bounds__(128)
void ret_q(const float* __restrict__ kin, const float* __restrict__ vin,
           const float* __restrict__ gammas, float* __restrict__ out, int bpar)
{
    __shared__ __align__(128) char sm[41232];
    const uint32_t sb = smem_u32(sm);
    float* gps = (float*)(sm + RQ_GP);

    int c = blockIdx.x, h = blockIdx.y, b = bpar;
    int tid = threadIdx.x, wid = tid >> 5, lane = tid & 31;

    if (tid < 65) gps[tid] = powf(gammas[h], (float)tid);
    __syncthreads();

    const uint32_t eighth = pack2h(0.125f, 0.125f);
    size_t base = ((size_t)b * SS + (size_t)c * RL) * DD + (size_t)h * HDD;
    size_t sbo  = (((size_t)(b * HH + h)) * RNC + c) * 4096;
#pragma unroll
    for (int it = 0; it < 8; it++) {
        int i = it * 128 + tid;
        int row = i >> 4, c4 = (i & 15) << 2;
        size_t ga = base + (size_t)row * DD + c4;
        uint32_t off = SW(row * 128 + c4 * 2);

        uint2 qh = *(const uint2*)&g_QPh[ga];
        uint2 ql = *(const uint2*)&g_QPl[ga];
        *(uint2*)(sm + RQ_QH + off) = make_uint2(hmul2u(qh.x, eighth), hmul2u(qh.y, eighth));
        *(uint2*)(sm + RQ_QL + off) = make_uint2(hmul2u(ql.x, eighth), hmul2u(ql.y, eighth));

        float4 kv = *(const float4*)&kin[ga];
        *(uint2*)(sm + RQ_KS + off) = make_uint2(pack2h(kv.x, kv.y), pack2h(kv.z, kv.w));

        float4 vv = *(const float4*)&vin[ga];
        *(uint2*)(sm + RQ_VS + off) = make_uint2(pack2h(vv.x, vv.y), pack2h(vv.z, vv.w));

        float4 sv = *(const float4*)&g_Sp[sbo + (size_t)row * 64 + c4];
        *(uint2*)(sm + RQ_SP + off) = make_uint2(pack2h(sv.x, sv.y), pack2h(sv.z, sv.w));
    }
    __syncthreads();

    const int R = wid * 16;
    const int aq = lane >> 3, ar = lane & 7;
    const int br = lane & 7, bhh = (lane >> 3) & 1;
    const int l2 = lane & 15;

    float c_[8][4], o2[8][4];
#pragma unroll
    for (int nb = 0; nb < 8; nb++)
#pragma unroll
        for (int r = 0; r < 4; r++) { c_[nb][r] = 0.f; o2[nb][r] = 0.f; }

#pragma unroll
    for (int ks = 0; ks < 4; ks++) {
        int k0 = ks * 16;
        uint32_t aH[4], aL[4];
        {
            int m = R + (aq & 1) * 8 + ar;
            int k = k0 + (aq >> 1) * 8;
            uint32_t off = SW(m * 128 + k * 2);
            ldsm_x4(sb + RQ_QH + off, aH);
            ldsm_x4(sb + RQ_QL + off, aL);
        }
#pragma unroll
        for (int nb = 0; nb < 8; nb++) {
            int n = nb * 8 + br;
            int k = k0 + bhh * 8;
            uint32_t off = SW(n * 128 + k * 2);
            uint32_t bK[2];
            ldsm_x2(sb + RQ_KS + off, bK);
            mma_f16(c_[nb], aH, bK);
            mma_f16(c_[nb], aL, bK);
        }
#pragma unroll
        for (int nb = 0; nb < 8; nb++) {
            int n = nb * 8;
            int krow = k0 + l2;
            uint32_t off = SW(krow * 128 + n * 2);
            uint32_t bS[2];
            ldsm_x2_t(sb + RQ_SP + off, bS);
            mma_f16(o2[nb], aH, bS);
            mma_f16(o2[nb], aL, bS);
        }
    }

    const int rb = R + (lane >> 2);
    const int cb = (lane & 3) * 2;
#pragma unroll
    for (int nb = 0; nb < 8; nb++) {
        int col0 = nb * 8 + cb;
        c_[nb][0] *= (rb >= col0)         ? gps[rb - col0]         : 0.f;
        c_[nb][1] *= (rb >= col0 + 1)     ? gps[rb - col0 - 1]     : 0.f;
        c_[nb][2] *= (rb + 8 >= col0)     ? gps[rb + 8 - col0]     : 0.f;
        c_[nb][3] *= (rb + 8 >= col0 + 1) ? gps[rb + 8 - col0 - 1] : 0.f;
    }

    float oc[8][4];
#pragma unroll
    for (int nb = 0; nb < 8; nb++)
#pragma unroll
        for (int r = 0; r < 4; r++) oc[nb][r] = 0.f;

#pragma unroll
    for (int kk = 0; kk < 4; kk++) {
        int k0 = kk * 16;
        uint32_t aPh[4], aPl[4];
        split2h(c_[2 * kk][0],     c_[2 * kk][1],     aPh[0], aPl[0]);
        split2h(c_[2 * kk][2],     c_[2 * kk][3],     aPh[1], aPl[1]);
        split2h(c_[2 * kk + 1][0], c_[2 * kk + 1][1], aPh[2], aPl[2]);
        split2h(c_[2 * kk + 1][2], c_[2 * kk + 1][3], aPh[3], aPl[3]);
#pragma unroll
        for (int nb = 0; nb < 8; nb++) {
            int n = nb * 8;
            int jrow = k0 + l2;
            uint32_t off = SW(jrow * 128 + n * 2);
            uint32_t bV[2];
            ldsm_x2_t(sb + RQ_VS + off, bV);
            mma_f16(oc[nb], aPh, bV);
            mma_f16(oc[nb], aPl, bV);
        }
    }

    float g0 = gps[rb + 1];
    float g1 = gps[rb + 9];
#pragma unroll
    for (int nb = 0; nb < 8; nb++) {
        int col = nb * 8 + cb;
        *(float2*)&out[base + (size_t)rb * DD + col] =
            make_float2(oc[nb][0] + g0 * o2[nb][0], oc[nb][1] + g0 * o2[nb][1]);
        *(float2*)&out[base + (size_t)(rb + 8) * DD + col] =
            make_float2(oc[nb][2] + g1 * o2[nb][2], oc[nb][3] + g1 * o2[nb][3]);
    }
}

// ---------------- launch ---------------------------------------------------
extern "C" void kernel_launch(void* const* d_in, const int* in_sizes, int n_in,
                              void* d_out, int out_size)
{
    const float* q      = (const float*)d_in[0];
    const float* k      = (const float*)d_in[1];
    const float* v      = (const float*)d_in[2];
    const float* W_in   = (const float*)d_in[3];
    const float* b_in   = (const float*)d_in[4];
    const float* W_gate = (const float*)d_in[5];
    const float* b_gate = (const float*)d_in[6];
    const float* W_out  = (const float*)d_in[7];
    const float* b_out  = (const float*)d_in[8];
    const float* gammas = (const float*)d_in[9];
    float* out = (float*)d_out;

    void *puh, *pah;
    void *pxh, *phh, *pqh, *pql, *pw1, *pw2, *pw3;
    cudaGetSymbolAddress(&puh, g_uh);
    cudaGetSymbolAddress(&pah, g_ah);
    cudaGetSymbolAddress(&pxh, g_Xhi);
    cudaGetSymbolAddress(&phh, g_Hhi);
    cudaGetSymbolAddress(&pqh, g_QPh);  cudaGetSymbolAddress(&pql, g_QPl);
    cudaGetSymbolAddress(&pw1, g_W1);
    cudaGetSymbolAddress(&pw2, g_W2);
    cudaGetSymbolAddress(&pw3, g_W3);

    cudaFuncSetAttribute(gemm_mma<1>, cudaFuncAttributeMaxDynamicSharedMemorySize, SMEM_DUAL);
    cudaFuncSetAttribute(gemm_mma<0>, cudaFuncAttributeMaxDynamicSharedMemorySize, SMEM_SINGLE);

    // streams/events: created per call, never destroyed (capture-safe; no device mem)
    cudaStream_t s2;
    cudaStreamCreateWithFlags(&s2, cudaStreamNonBlocking);
    cudaEvent_t evF, evJ, e1, eEnd;
    cudaEventCreateWithFlags(&evF, cudaEventDisableTiming);
    cudaEventCreateWithFlags(&evJ, cudaEventDisableTiming);
    cudaEventCreateWithFlags(&e1,  cudaEventDisableTiming);
    cudaEventCreateWithFlags(&eEnd, cudaEventDisableTiming);

    cudaEventRecord(evF, 0);
    cudaStreamWaitEvent(s2, evF, 0);
    // branch B (s2): KV state path — needs only k, v, gammas
    ret_kv<<<dim3(RNC, HH, BB), 128, 0, s2>>>(k, v, gammas);
    ret_scan_k<<<(BB * HH * HDD * HDD) / 256, 256, 0, s2>>>(gammas);
    cudaEventRecord(evJ, s2);

    // branch A (s0): conversions + gemm1 batch 0
    conv_all_k<<<4096 + 3072, 256>>>(q, W_in, W_gate, W_out,
        (__half*)pxh, (__half*)pw1, (__half*)pw2, (__half*)pw3);

    dim3 gh(8, 16);   // half-batch tile grid (128 CTAs)
    gemm_mma<1><<<gh, 512, SMEM_DUAL>>>(
        (const __half*)pxh, (const __half*)pw1, (const __half*)pw2,
        b_in, b_gate, puh, pah, 0);
    cudaEventRecord(e1, 0);

    // s0: gemm1 batch 1 while s2 runs scans/gemm2/ret_q for batch 0
    gemm_mma<1><<<gh, 512, SMEM_DUAL>>>(
        (const __half*)pxh, (const __half*)pw1, (const __half*)pw2,
        b_in, b_gate, puh, pah, 2048);

    cudaStreamWaitEvent(s2, e1, 0);
    scan_chunk_k <<<SNC, 256, 0, s2>>>(0);
    scan_prefix_k<<<32, 256, 0, s2>>>(0);
    scan_apply_k <<<SNC, 256, 0, s2>>>(0);
    gemm_mma<0><<<gh, 512, SMEM_SINGLE, s2>>>(
        (const __half*)phh, (const __half*)pw3, nullptr,
        b_out, nullptr, pqh, pql, 0);
    ret_q<<<dim3(RNC, HH), 128, 0, s2>>>(k, v, gammas, out, 0);
    cudaEventRecord(eEnd, s2);

    // s0: scans batch 1, gemm2 batch 1, retention q-path batch 1
    scan_chunk_k <<<SNC, 256>>>(1);
    scan_prefix_k<<<32, 256>>>(1);
    scan_apply_k <<<SNC, 256>>>(1);
    gemm_mma<0><<<gh, 512, SMEM_SINGLE>>>(
        (const __half*)phh, (const __half*)pw3, nullptr,
        b_out, nullptr, pqh, pql, 2048);
    cudaStreamWaitEvent(0, evJ, 0);
    ret_q<<<dim3(RNC, HH), 128>>>(k, v, gammas, out, 1);

    // join forked work back into the origin stream (graph sink)
    cudaStreamWaitEvent(0, eEnd, 0);
}